// round 1
// baseline (speedup 1.0000x reference)
#include <cuda_runtime.h>
#include <math.h>

// ---------------- problem constants ----------------
#define B_   4
#define NW_  100
#define NT_  800
#define N_   1000
#define N1_  1001
#define D_   512
#define H_   8
#define HD_  64
#define DFF_ 2048
#define L_   3
#define EPS_ 1e-5f
#define ALPHA_ 0.125f   // 1/sqrt(64)

// ---------------- device scratch (no allocation allowed) ----------------
__device__ float  g_X   [B_*N_*D_];            // 8 MB
__device__ float  g_E   [H_*B_*N_*N_];         // 128 MB  [h][b][n][m]
__device__ float  g_S   [H_*B_*N_*N_];         // 128 MB  scores/probs
__device__ float  g_QKV [B_*N_*3*D_];          // 24.6 MB rows=4000, cols=1536 (Q|K|V)
__device__ float  g_O   [B_*N_*D_];            // 8 MB    concat-head attn out
__device__ float  g_FF  [B_*N_*DFF_];          // 32.8 MB
__device__ float  g_Wpack[L_*D_*3*D_];         // 9.4 MB  packed [l][d][1536]
__device__ float  g_WkvP [D_*2*D_];            // 2 MB    packed [d][1024] (Kd|Vd)
__device__ float  g_KV  [B_*N1_*2*D_];         // 16.4 MB
__device__ double g_esum[B_*5];
__device__ float  g_ec0[32], g_ec1[32], g_ec2[32];  // per (b,h) edge affine coeffs

// ---------------- generic batched SGEMM ----------------
// C[m,n] = alpha * sum_k A[m,k]*Beff[k,n]  (+bias[n]) (+addsrc[m,n]) (relu?)
// Beff[k,n] = transB ? B[n*ldb+k] : B[k*ldb+n]
// batch z: z1 = z/inner, z0 = z%inner, ptr += z1*s1 + z0*s0
#define BM 64
#define BN 64
#define BK 16

__global__ __launch_bounds__(256)
void sgemm(const float* __restrict__ A, int lda, long long sA1, long long sA0,
           const float* __restrict__ Bm, int ldb, long long sB1, long long sB0,
           float* __restrict__ C, int ldc, long long sC1, long long sC0,
           const float* __restrict__ addsrc, int ldadd, long long sD1, long long sD0,
           const float* __restrict__ bias,
           int M, int N, int K, int inner,
           float alpha, int transB, int relu)
{
    int z = blockIdx.z;
    int z1 = z / inner, z0 = z % inner;
    A  += z1*sA1 + z0*sA0;
    Bm += z1*sB1 + z0*sB0;
    C  += z1*sC1 + z0*sC0;
    if (addsrc) addsrc += z1*sD1 + z0*sD0;

    __shared__ float As[BK][BM];
    __shared__ float Bs[BK][BN];

    int tid = threadIdx.x;
    int tx = tid & 15, ty = tid >> 4;
    int row0 = blockIdx.y * BM;
    int col0 = blockIdx.x * BN;

    float acc[4][4] = {};

    int a_m = tid >> 2;          // 0..63
    int a_k = (tid & 3) * 4;     // 0,4,8,12
    int b_n = tid & 63;
    int b_k = tid >> 6;          // 0..3

    for (int kt = 0; kt < K; kt += BK) {
        // A tile  As[k][m]
        {
            int m = row0 + a_m;
            #pragma unroll
            for (int j = 0; j < 4; j++) {
                int k = kt + a_k + j;
                As[a_k + j][a_m] = (m < M && k < K) ? A[(long long)m*lda + k] : 0.f;
            }
        }
        // B tile  Bs[k][n]
        if (!transB) {
            int n = col0 + b_n;
            #pragma unroll
            for (int j = 0; j < 4; j++) {
                int k = kt + b_k + j*4;
                Bs[b_k + j*4][b_n] = (n < N && k < K) ? Bm[(long long)k*ldb + n] : 0.f;
            }
        } else {
            int n = col0 + a_m;
            #pragma unroll
            for (int j = 0; j < 4; j++) {
                int k = kt + a_k + j;
                Bs[a_k + j][a_m] = (n < N && k < K) ? Bm[(long long)n*ldb + k] : 0.f;
            }
        }
        __syncthreads();
        #pragma unroll
        for (int k = 0; k < BK; k++) {
            float4 av = *(const float4*)&As[k][ty*4];
            float4 bv = *(const float4*)&Bs[k][tx*4];
            float a0[4] = {av.x, av.y, av.z, av.w};
            float b0[4] = {bv.x, bv.y, bv.z, bv.w};
            #pragma unroll
            for (int i = 0; i < 4; i++)
                #pragma unroll
                for (int j = 0; j < 4; j++)
                    acc[i][j] += a0[i] * b0[j];
        }
        __syncthreads();
    }
    #pragma unroll
    for (int i = 0; i < 4; i++) {
        int m = row0 + ty*4 + i;
        if (m >= M) continue;
        #pragma unroll
        for (int j = 0; j < 4; j++) {
            int n = col0 + tx*4 + j;
            if (n >= N) continue;
            float v = alpha * acc[i][j];
            if (bias)   v += bias[n];
            if (addsrc) v += addsrc[(long long)m*ldadd + n];
            if (relu)   v = fmaxf(v, 0.f);
            C[(long long)m*ldc + n] = v;
        }
    }
}

// ---------------- row softmax (1000 cols, in place) ----------------
__global__ __launch_bounds__(256)
void softmax_rows(float* __restrict__ S, int ncols)
{
    long long row = blockIdx.x;
    float* p = S + row * (long long)ncols;
    int t = threadIdx.x;
    float vals[4];
    float mx = -1e30f;
    #pragma unroll
    for (int i = 0; i < 4; i++) {
        int c = t + i*256;
        vals[i] = (c < ncols) ? p[c] : -1e30f;
        mx = fmaxf(mx, vals[i]);
    }
    __shared__ float red[256];
    red[t] = mx; __syncthreads();
    for (int s = 128; s > 0; s >>= 1) { if (t < s) red[t] = fmaxf(red[t], red[t+s]); __syncthreads(); }
    mx = red[0]; __syncthreads();
    float sum = 0.f;
    #pragma unroll
    for (int i = 0; i < 4; i++) { vals[i] = __expf(vals[i] - mx); sum += vals[i]; }
    red[t] = sum; __syncthreads();
    for (int s = 128; s > 0; s >>= 1) { if (t < s) red[t] += red[t+s]; __syncthreads(); }
    float inv = 1.f / red[0];
    #pragma unroll
    for (int i = 0; i < 4; i++) {
        int c = t + i*256;
        if (c < ncols) p[c] = vals[i] * inv;
    }
}

// ---------------- InstanceNorm1d over item dim (in place) ----------------
// X [B][Nrows][D], normalize per (b, channel). block(32,8), grid(D/32, B)
__global__ void inorm1d(float* __restrict__ X, const float* __restrict__ g,
                        const float* __restrict__ be, int Nrows)
{
    int b = blockIdx.y;
    int c = blockIdx.x * 32 + threadIdx.x;
    int ty = threadIdx.y;
    float* Xb = X + (long long)b * Nrows * D_;
    float s = 0.f, q = 0.f;
    for (int n = ty; n < Nrows; n += 8) {
        float x = Xb[(long long)n * D_ + c];
        s += x; q += x * x;
    }
    __shared__ float sh_s[8][32], sh_q[8][32];
    sh_s[ty][threadIdx.x] = s; sh_q[ty][threadIdx.x] = q;
    __syncthreads();
    __shared__ float sh_m[32], sh_r[32];
    if (ty == 0) {
        float S = 0.f, Q = 0.f;
        #pragma unroll
        for (int i = 0; i < 8; i++) { S += sh_s[i][threadIdx.x]; Q += sh_q[i][threadIdx.x]; }
        float mean = S / (float)Nrows;
        float var  = Q / (float)Nrows - mean*mean;
        sh_m[threadIdx.x] = mean;
        sh_r[threadIdx.x] = rsqrtf(var + EPS_);
    }
    __syncthreads();
    float mean = sh_m[threadIdx.x], r = sh_r[threadIdx.x];
    float gg = g[c], bb = be[c];
    for (int n = ty; n < Nrows; n += 8) {
        long long idx = (long long)n * D_ + c;
        Xb[idx] = gg * (Xb[idx] - mean) * r + bb;
    }
}

// ---------------- input projections + concat ----------------
__global__ void init_x(const float* __restrict__ wf, const float* __restrict__ tf,
                       const float* __restrict__ Wws, const float* __restrict__ bws,
                       const float* __restrict__ Wwe, const float* __restrict__ bwe,
                       const float* __restrict__ Wt,  const float* __restrict__ bt)
{
    int t = blockIdx.x * blockDim.x + threadIdx.x;
    if (t >= B_*N_*D_) return;
    int d = t & 511;
    int n = (t >> 9) % N_;
    int b = t / (D_*N_);
    float v;
    if (n < NW_) {
        const float* f = wf + (b*NW_ + n)*4;
        v = bws[d];
        #pragma unroll
        for (int k = 0; k < 4; k++) v += f[k] * Wws[k*D_ + d];
    } else if (n < 2*NW_) {
        const float* f = wf + (b*NW_ + (n - NW_))*4;
        v = bwe[d];
        #pragma unroll
        for (int k = 0; k < 4; k++) v += f[k] * Wwe[k*D_ + d];
    } else {
        const float* f = tf + (b*NT_ + (n - 2*NW_))*8;
        v = bt[d];
        #pragma unroll
        for (int k = 0; k < 8; k++) v += f[k] * Wt[k*D_ + d];
    }
    g_X[t] = v;
}

// ---------------- edge bias: analytic InstanceNorm2d ----------------
__global__ void zero_esum() { if (threadIdx.x < B_*5) g_esum[threadIdx.x] = 0.0; }

__global__ __launch_bounds__(256)
void edge_stats(const float* __restrict__ ef)
{
    int b = blockIdx.y;
    const float2* p = (const float2*)ef + (long long)b * (N_*N_);
    int stride = gridDim.x * blockDim.x;
    float s0=0,s1=0,s00=0,s11=0,s01=0;
    for (int i = blockIdx.x*blockDim.x + threadIdx.x; i < N_*N_; i += stride) {
        float2 f = p[i];
        s0 += f.x; s1 += f.y; s00 += f.x*f.x; s11 += f.y*f.y; s01 += f.x*f.y;
    }
    __shared__ double red[256];
    double loc[5] = {(double)s0,(double)s1,(double)s00,(double)s11,(double)s01};
    for (int j = 0; j < 5; j++) {
        red[threadIdx.x] = loc[j];
        __syncthreads();
        for (int s = 128; s > 0; s >>= 1) { if (threadIdx.x < s) red[threadIdx.x] += red[threadIdx.x+s]; __syncthreads(); }
        if (threadIdx.x == 0) atomicAdd(&g_esum[b*5+j], red[0]);
        __syncthreads();
    }
}

// e = f0*w0 + f1*w1 + bias; inorm2d(e) -> E = f0*c0 + f1*c1 + c2 per (b,h)
__global__ void edge_params(const float* __restrict__ We, const float* __restrict__ be,
                            const float* __restrict__ ge, const float* __restrict__ bee)
{
    int t = threadIdx.x;
    if (t >= B_*H_) return;
    int b = t / H_, h = t % H_;
    double cnt = (double)N_ * (double)N_;
    double m0  = g_esum[b*5+0]/cnt, m1 = g_esum[b*5+1]/cnt;
    double v00 = g_esum[b*5+2]/cnt - m0*m0;
    double v11 = g_esum[b*5+3]/cnt - m1*m1;
    double v01 = g_esum[b*5+4]/cnt - m0*m1;
    double w0 = We[0*H_+h], w1 = We[1*H_+h];
    double mean = w0*m0 + w1*m1 + (double)be[h];
    double var  = w0*w0*v00 + 2.0*w0*w1*v01 + w1*w1*v11;
    double grs  = (double)ge[h] / sqrt(var + (double)EPS_);
    g_ec0[t] = (float)(w0*grs);
    g_ec1[t] = (float)(w1*grs);
    g_ec2[t] = (float)(((double)be[h] - mean)*grs + (double)bee[h]);
}

__global__ __launch_bounds__(256)
void edge_write(const float* __restrict__ ef)
{
    int b = blockIdx.y;
    long long i = (long long)blockIdx.x * blockDim.x + threadIdx.x;
    if (i >= (long long)N_*N_) return;
    float2 f = ((const float2*)ef)[(long long)b*(N_*N_) + i];
    #pragma unroll
    for (int h = 0; h < H_; h++) {
        int t = b*H_ + h;
        float v = f.x * g_ec0[t] + f.y * g_ec1[t] + g_ec2[t];
        g_E[((long long)(h*B_ + b))*(N_*N_) + i] = v;
    }
}

// ---------------- weight packing ----------------
__global__ void pack_qkv(const float* __restrict__ Wq, const float* __restrict__ Wk,
                         const float* __restrict__ Wv)
{
    int t = blockIdx.x * blockDim.x + threadIdx.x;
    if (t >= L_*D_*D_) return;           // one (l,d,h,e) triple handles q,k,v
    int e = t & 63;
    int h = (t >> 6) & 7;
    int d = (t >> 9) & 511;
    int l = t >> 18;
    long long src = (((long long)l*H_ + h)*D_ + d)*HD_ + e;
    long long dst = ((long long)l*D_ + d)*(3*D_) + h*HD_ + e;
    g_Wpack[dst]          = Wq[src];
    g_Wpack[dst + D_]     = Wk[src];
    g_Wpack[dst + 2*D_]   = Wv[src];
}

__global__ void pack_kv(const float* __restrict__ Kd, const float* __restrict__ Vd)
{
    int t = blockIdx.x * blockDim.x + threadIdx.x;
    if (t >= D_*D_) return;
    int e = t & 63;
    int h = (t >> 6) & 7;
    int d = t >> 9;
    long long src = ((long long)h*D_ + d)*HD_ + e;
    long long dst = (long long)d*(2*D_) + h*HD_ + e;
    g_WkvP[dst]        = Kd[src];
    g_WkvP[dst + D_]   = Vd[src];
}

// ---------------- finish token append into output X ----------------
__global__ void write_xout(const float* __restrict__ fin, float* __restrict__ out)
{
    int t = blockIdx.x * blockDim.x + threadIdx.x;
    if (t >= B_*N1_*D_) return;
    int d = t & 511;
    int n = (t >> 9) % N1_;
    int b = t / (N1_*D_);
    out[t] = (n < N_) ? g_X[((long long)b*N_ + n)*D_ + d] : fin[d];
}

// ---------------- reorder decode K/V to [H][B][N1][HD] ----------------
__global__ void write_kv(float* __restrict__ outK, float* __restrict__ outV)
{
    int t = blockIdx.x * blockDim.x + threadIdx.x;
    if (t >= H_*B_*N1_*HD_) return;
    int e = t & 63;
    int n = (t >> 6) % N1_;
    int rem = t / (HD_*N1_);
    int b = rem & 3;
    int h = rem >> 2;
    long long src = ((long long)(b*N1_ + n))*(2*D_) + h*HD_ + e;
    outK[t] = g_KV[src];
    outV[t] = g_KV[src + D_];
}

// ---------------- host orchestration ----------------
static inline int cdiv(int a, int b) { return (a + b - 1) / b; }

extern "C" void kernel_launch(void* const* d_in, const int* in_sizes, int n_in,
                              void* d_out, int out_size)
{
    const float* wf   = (const float*)d_in[0];
    const float* tf   = (const float*)d_in[1];
    const float* ef   = (const float*)d_in[2];
    const float* Wws  = (const float*)d_in[3];
    const float* bws  = (const float*)d_in[4];
    const float* Wwe  = (const float*)d_in[5];
    const float* bwe  = (const float*)d_in[6];
    const float* Wt   = (const float*)d_in[7];
    const float* bt   = (const float*)d_in[8];
    const float* g_wt = (const float*)d_in[9];
    const float* be_wt= (const float*)d_in[10];
    const float* W_e  = (const float*)d_in[11];
    const float* b_e  = (const float*)d_in[12];
    const float* g_e  = (const float*)d_in[13];
    const float* be_e = (const float*)d_in[14];
    const float* Wq   = (const float*)d_in[15];
    const float* Wk   = (const float*)d_in[16];
    const float* Wv   = (const float*)d_in[17];
    const float* Wo   = (const float*)d_in[18];
    const float* W1   = (const float*)d_in[19];
    const float* b1   = (const float*)d_in[20];
    const float* W2   = (const float*)d_in[21];
    const float* b2   = (const float*)d_in[22];
    const float* g1   = (const float*)d_in[23];
    const float* be1  = (const float*)d_in[24];
    const float* g2   = (const float*)d_in[25];
    const float* be2  = (const float*)d_in[26];
    const float* fin  = (const float*)d_in[27];
    const float* Kd   = (const float*)d_in[28];
    const float* Vd   = (const float*)d_in[29];

    float* out  = (float*)d_out;
    float* outX = out;
    float* outK = out + (size_t)B_*N1_*D_;
    float* outV = outK + (size_t)H_*B_*N1_*HD_;

    float *pX, *pE, *pS, *pQKV, *pO, *pFF, *pWp, *pWkv, *pKV;
    cudaGetSymbolAddress((void**)&pX,   g_X);
    cudaGetSymbolAddress((void**)&pE,   g_E);
    cudaGetSymbolAddress((void**)&pS,   g_S);
    cudaGetSymbolAddress((void**)&pQKV, g_QKV);
    cudaGetSymbolAddress((void**)&pO,   g_O);
    cudaGetSymbolAddress((void**)&pFF,  g_FF);
    cudaGetSymbolAddress((void**)&pWp,  g_Wpack);
    cudaGetSymbolAddress((void**)&pWkv, g_WkvP);
    cudaGetSymbolAddress((void**)&pKV,  g_KV);

    // ---- setup ----
    zero_esum<<<1, 32>>>();
    edge_stats<<<dim3(32, B_), 256>>>(ef);
    edge_params<<<1, 32>>>(W_e, b_e, g_e, be_e);
    edge_write<<<dim3(cdiv(N_*N_, 256), B_), 256>>>(ef);
    pack_qkv<<<cdiv(L_*D_*D_, 256), 256>>>(Wq, Wk, Wv);
    pack_kv<<<cdiv(D_*D_, 256), 256>>>(Kd, Vd);
    init_x<<<cdiv(B_*N_*D_, 256), 256>>>(wf, tf, Wws, bws, Wwe, bwe, Wt, bt);
    inorm1d<<<dim3(D_/32, B_), dim3(32, 8)>>>(pX, g_wt, be_wt, N_);

    const int Mrows = B_*N_;        // 4000
    const long long sE1 = (long long)B_*N_*N_;   // h-stride in g_E/g_S
    const long long sE0 = (long long)N_*N_;      // b-stride
    const long long sQb = (long long)N_*3*D_;    // b-stride in g_QKV rows

    for (int l = 0; l < L_; l++) {
        const float* Wp_l = pWp + (long long)l*D_*3*D_;
        // QKV: [4000,512] @ [512,1536]
        sgemm<<<dim3(cdiv(3*D_,BN), cdiv(Mrows,BM), 1), 256>>>(
            pX, D_, 0,0,  Wp_l, 3*D_, 0,0,  pQKV, 3*D_, 0,0,
            nullptr, 0, 0,0, nullptr, Mrows, 3*D_, D_, 1, 1.f, 0, 0);
        // S = E + alpha * Q @ K^T   (batched over z=(h,b), inner=B)
        sgemm<<<dim3(cdiv(N_,BN), cdiv(N_,BM), H_*B_), 256>>>(
            pQKV,            3*D_, 64, sQb,
            pQKV + D_,       3*D_, 64, sQb,
            pS,              N_,   sE1, sE0,
            pE,              N_,   sE1, sE0,
            nullptr, N_, N_, HD_, B_, ALPHA_, 1, 0);
        // softmax rows
        softmax_rows<<<H_*B_*N_, 256>>>(pS, N_);
        // O_h = P @ V  (batched)
        sgemm<<<dim3(1, cdiv(N_,BM), H_*B_), 256>>>(
            pS,              N_,   sE1, sE0,
            pQKV + 2*D_,     3*D_, 64, sQb,
            pO,              D_,   64, (long long)N_*D_,
            nullptr, 0, 0,0, nullptr, N_, HD_, N_, B_, 1.f, 0, 0);
        // X = X + O @ Wo
        sgemm<<<dim3(cdiv(D_,BN), cdiv(Mrows,BM), 1), 256>>>(
            pO, D_, 0,0,  Wo + (long long)l*D_*D_, D_, 0,0,  pX, D_, 0,0,
            pX, D_, 0,0, nullptr, Mrows, D_, D_, 1, 1.f, 0, 0);
        inorm1d<<<dim3(D_/32, B_), dim3(32, 8)>>>(pX, g1 + l*D_, be1 + l*D_, N_);
        // FF = relu(X @ W1 + b1)
        sgemm<<<dim3(cdiv(DFF_,BN), cdiv(Mrows,BM), 1), 256>>>(
            pX, D_, 0,0,  W1 + (long long)l*D_*DFF_, DFF_, 0,0,  pFF, DFF_, 0,0,
            nullptr, 0, 0,0, b1 + l*DFF_, Mrows, DFF_, D_, 1, 1.f, 0, 1);
        // X = X + FF @ W2 + b2
        sgemm<<<dim3(cdiv(D_,BN), cdiv(Mrows,BM), 1), 256>>>(
            pFF, DFF_, 0,0,  W2 + (long long)l*DFF_*D_, D_, 0,0,  pX, D_, 0,0,
            pX, D_, 0,0, b2 + l*D_, Mrows, D_, DFF_, 1, 1.f, 0, 0);
        inorm1d<<<dim3(D_/32, B_), dim3(32, 8)>>>(pX, g2 + l*D_, be2 + l*D_, N_);
    }

    // append finish token into output X
    write_xout<<<cdiv(B_*N1_*D_, 256), 256>>>(fin, outX);
    // decode K/V: [4004,512] @ [512,1024]
    sgemm<<<dim3(cdiv(2*D_,BN), cdiv(B_*N1_,BM), 1), 256>>>(
        outX, D_, 0,0,  pWkv, 2*D_, 0,0,  pKV, 2*D_, 0,0,
        nullptr, 0, 0,0, nullptr, B_*N1_, 2*D_, D_, 1, 1.f, 0, 0);
    write_kv<<<cdiv(H_*B_*N1_*HD_, 256), 256>>>(outK, outV);
}

// round 5
// speedup vs baseline: 1.4383x; 1.4383x over previous
#include <cuda_runtime.h>
#include <cuda_fp16.h>
#include <math.h>

// ---------------- problem constants ----------------
#define B_   4
#define NW_  100
#define NT_  800
#define N_   1000
#define N1_  1001
#define D_   512
#define H_   8
#define HD_  64
#define DFF_ 2048
#define L_   3
#define EPS_ 1e-5f
#define ALPHA_ 0.125f   // 1/sqrt(64)

// ---------------- device scratch (no allocation allowed) ----------------
__device__ float  g_X   [B_*N_*D_];
__device__ float  g_S   [H_*B_*N_*N_];
__device__ float  g_QKV [B_*N_*3*D_];
__device__ float  g_O   [B_*N_*D_];
__device__ float  g_FF  [B_*N_*DFF_];
__device__ float  g_Wpack[L_*D_*3*D_];
__device__ float  g_WkvP [D_*2*D_];
__device__ float  g_KV  [B_*N1_*2*D_];
__device__ double g_esum[B_*5];
__device__ float  g_ec0[32], g_ec1[32], g_ec2[32];

// split a pair of floats into fp16 (hi, lo) packed half2 words
__device__ __forceinline__ void split2(float a, float b, unsigned &h, unsigned &l) {
    __half2 hh = __floats2half2_rn(a, b);
    float2 bk = __half22float2(hh);
    __half2 ll = __floats2half2_rn(a - bk.x, b - bk.y);
    h = *(unsigned*)&hh;
    l = *(unsigned*)&ll;
}

// ---------------- split-fp16 (3xFP16) tensor-core batched GEMM ----------------
// C[m,n] = alpha*sum_k A[m,k]*Beff[k,n] (+bias[n]) (+addsrc[m,n] | edge bias) (relu?)
// Beff[k,n] = transB ? B[n*ldb+k] : B[k*ldb+n]
template<int BM, int BN, int WARPS_M, int WARPS_N>
__global__ __launch_bounds__(WARPS_M*WARPS_N*32)
void gemm_h3(const float* __restrict__ A, int lda, long long sA1, long long sA0,
             const float* __restrict__ Bm, int ldb, long long sB1, long long sB0,
             float* __restrict__ C, int ldc, long long sC1, long long sC0,
             const float* __restrict__ addsrc, int ldadd, long long sD1, long long sD0,
             const float* __restrict__ bias,
             int M, int N, int K, int inner, float alpha,
             int transB, int relu, int edge_mode)
{
    constexpr int BK = 16;
    constexpr int THREADS = WARPS_M*WARPS_N*32;
    constexpr int WM = BM/WARPS_M, WN = BN/WARPS_N;
    constexpr int MT = WM/16, NT = WN/8;
    constexpr int LDK = BK + 8;                  // 24 halves: conflict-free frag loads
    constexpr int IA  = (BM*BK/4)/THREADS;       // float4 loads per thread (A tile)
    constexpr int IBT = (BN*BK/4)/THREADS;       // trans-B
    constexpr int IBN = (BK*BN/4)/THREADS;       // non-trans B
    constexpr int IB  = (IBT > IBN ? IBT : IBN);

    __shared__ __align__(16) __half As_hi[2][BM][LDK];
    __shared__ __align__(16) __half As_lo[2][BM][LDK];
    __shared__ __align__(16) __half Bs_hi[2][BN][LDK];
    __shared__ __align__(16) __half Bs_lo[2][BN][LDK];

    int z = blockIdx.z, z1 = z/inner, z0 = z%inner;
    A  += z1*sA1 + z0*sA0;
    Bm += z1*sB1 + z0*sB0;
    C  += z1*sC1 + z0*sC0;

    int tid = threadIdx.x;
    int warp = tid>>5, lane = tid&31, g = lane>>2, tg = lane&3;
    int wm = (warp % WARPS_M)*WM, wn = (warp / WARPS_M)*WN;
    int row0 = blockIdx.y*BM, col0 = blockIdx.x*BN;

    float acc[MT][NT][4] = {};
    float4 ra[IA];
    float4 rb[IB];

    auto ldg_tiles = [&](int kt) {
        #pragma unroll
        for (int i = 0; i < IA; i++) {
            int idx = tid + i*THREADS;
            int m = idx >> 2, kv = (idx & 3)*4;
            ra[i] = make_float4(0.f,0.f,0.f,0.f);
            if (row0+m < M && kt+kv < K)
                ra[i] = *(const float4*)&A[(long long)(row0+m)*lda + kt + kv];
        }
        if (transB) {
            #pragma unroll
            for (int i = 0; i < IBT; i++) {
                int idx = tid + i*THREADS;
                int n = idx >> 2, kv = (idx & 3)*4;
                rb[i] = make_float4(0.f,0.f,0.f,0.f);
                if (col0+n < N && kt+kv < K)
                    rb[i] = *(const float4*)&Bm[(long long)(col0+n)*ldb + kt + kv];
            }
        } else {
            #pragma unroll
            for (int i = 0; i < IBN; i++) {
                int idx = tid + i*THREADS;
                int k = idx / (BN/4);
                int n = (idx % (BN/4))*4;
                rb[i] = make_float4(0.f,0.f,0.f,0.f);
                if (kt+k < K && col0+n < N)
                    rb[i] = *(const float4*)&Bm[(long long)(kt+k)*ldb + col0 + n];
            }
        }
    };

    auto sts_tiles = [&](int buf) {
        #pragma unroll
        for (int i = 0; i < IA; i++) {
            int idx = tid + i*THREADS;
            int m = idx >> 2, kv = (idx & 3)*4;
            unsigned h0,l0,h1,l1;
            split2(ra[i].x, ra[i].y, h0, l0);
            split2(ra[i].z, ra[i].w, h1, l1);
            *(uint2*)&As_hi[buf][m][kv] = make_uint2(h0, h1);
            *(uint2*)&As_lo[buf][m][kv] = make_uint2(l0, l1);
        }
        if (transB) {
            #pragma unroll
            for (int i = 0; i < IBT; i++) {
                int idx = tid + i*THREADS;
                int n = idx >> 2, kv = (idx & 3)*4;
                unsigned h0,l0,h1,l1;
                split2(rb[i].x, rb[i].y, h0, l0);
                split2(rb[i].z, rb[i].w, h1, l1);
                *(uint2*)&Bs_hi[buf][n][kv] = make_uint2(h0, h1);
                *(uint2*)&Bs_lo[buf][n][kv] = make_uint2(l0, l1);
            }
        } else {
            #pragma unroll
            for (int i = 0; i < IBN; i++) {
                int idx = tid + i*THREADS;
                int k = idx / (BN/4);
                int n = (idx % (BN/4))*4;
                float v[4] = {rb[i].x, rb[i].y, rb[i].z, rb[i].w};
                #pragma unroll
                for (int j = 0; j < 4; j++) {
                    __half h = __float2half_rn(v[j]);
                    __half l = __float2half_rn(v[j] - __half2float(h));
                    Bs_hi[buf][n+j][k] = h;
                    Bs_lo[buf][n+j][k] = l;
                }
            }
        }
    };

    auto compute = [&](int buf) {
        unsigned ah[MT][4], al[MT][4];
        #pragma unroll
        for (int mt = 0; mt < MT; mt++) {
            int m0 = wm + mt*16;
            ah[mt][0] = *(unsigned*)&As_hi[buf][m0+g  ][tg*2];
            ah[mt][1] = *(unsigned*)&As_hi[buf][m0+g+8][tg*2];
            ah[mt][2] = *(unsigned*)&As_hi[buf][m0+g  ][tg*2+8];
            ah[mt][3] = *(unsigned*)&As_hi[buf][m0+g+8][tg*2+8];
            al[mt][0] = *(unsigned*)&As_lo[buf][m0+g  ][tg*2];
            al[mt][1] = *(unsigned*)&As_lo[buf][m0+g+8][tg*2];
            al[mt][2] = *(unsigned*)&As_lo[buf][m0+g  ][tg*2+8];
            al[mt][3] = *(unsigned*)&As_lo[buf][m0+g+8][tg*2+8];
        }
        #pragma unroll
        for (int nt = 0; nt < NT; nt++) {
            int n0 = wn + nt*8;
            unsigned bh0 = *(unsigned*)&Bs_hi[buf][n0+g][tg*2];
            unsigned bh1 = *(unsigned*)&Bs_hi[buf][n0+g][tg*2+8];
            unsigned bl0 = *(unsigned*)&Bs_lo[buf][n0+g][tg*2];
            unsigned bl1 = *(unsigned*)&Bs_lo[buf][n0+g][tg*2+8];
            #pragma unroll
            for (int mt = 0; mt < MT; mt++) {
                asm volatile(
                    "mma.sync.aligned.m16n8k16.row.col.f32.f16.f16.f32 "
                    "{%0,%1,%2,%3}, {%4,%5,%6,%7}, {%8,%9}, {%0,%1,%2,%3};"
                    : "+f"(acc[mt][nt][0]), "+f"(acc[mt][nt][1]),
                      "+f"(acc[mt][nt][2]), "+f"(acc[mt][nt][3])
                    : "r"(ah[mt][0]), "r"(ah[mt][1]), "r"(ah[mt][2]), "r"(ah[mt][3]),
                      "r"(bh0), "r"(bh1));
                asm volatile(
                    "mma.sync.aligned.m16n8k16.row.col.f32.f16.f16.f32 "
                    "{%0,%1,%2,%3}, {%4,%5,%6,%7}, {%8,%9}, {%0,%1,%2,%3};"
                    : "+f"(acc[mt][nt][0]), "+f"(acc[mt][nt][1]),
                      "+f"(acc[mt][nt][2]), "+f"(acc[mt][nt][3])
                    : "r"(ah[mt][0]), "r"(ah[mt][1]), "r"(ah[mt][2]), "r"(ah[mt][3]),
                      "r"(bl0), "r"(bl1));
                asm volatile(
                    "mma.sync.aligned.m16n8k16.row.col.f32.f16.f16.f32 "
                    "{%0,%1,%2,%3}, {%4,%5,%6,%7}, {%8,%9}, {%0,%1,%2,%3};"
                    : "+f"(acc[mt][nt][0]), "+f"(acc[mt][nt][1]),
                      "+f"(acc[mt][nt][2]), "+f"(acc[mt][nt][3])
                    : "r"(al[mt][0]), "r"(al[mt][1]), "r"(al[mt][2]), "r"(al[mt][3]),
                      "r"(bh0), "r"(bh1));
            }
        }
    };

    // pipelined mainloop
    ldg_tiles(0);
    sts_tiles(0);
    int buf = 0;
    for (int kt = 0; kt < K; kt += BK) {
        bool has_next = (kt + BK) < K;
        if (has_next) ldg_tiles(kt + BK);
        __syncthreads();
        compute(buf);
        if (has_next) sts_tiles(buf ^ 1);
        buf ^= 1;
    }

    // epilogue
    float ec0 = 0.f, ec1 = 0.f, ec2 = 0.f;
    const float2* e2 = nullptr;
    if (edge_mode) {
        int t = z0*H_ + z1;              // (b,h) coefficient index
        ec0 = g_ec0[t]; ec1 = g_ec1[t]; ec2 = g_ec2[t];
        e2 = (const float2*)addsrc + (long long)z0 * ((long long)N_*N_);
    } else if (addsrc) {
        addsrc += z1*sD1 + z0*sD0;
    }

    #pragma unroll
    for (int mt = 0; mt < MT; mt++) {
        #pragma unroll
        for (int nt = 0; nt < NT; nt++) {
            int nb = col0 + wn + nt*8 + tg*2;
            #pragma unroll
            for (int h = 0; h < 2; h++) {
                int m = row0 + wm + mt*16 + g + h*8;
                if (m >= M) continue;
                #pragma unroll
                for (int j = 0; j < 2; j++) {
                    int n = nb + j;
                    if (n >= N) continue;
                    float v = alpha * acc[mt][nt][h*2+j];
                    if (bias)   v += bias[n];
                    if (edge_mode) {
                        float2 f = e2[(long long)m*ldadd + n];
                        v += f.x*ec0 + f.y*ec1 + ec2;
                    } else if (addsrc) {
                        v += addsrc[(long long)m*ldadd + n];
                    }
                    if (relu) v = fmaxf(v, 0.f);
                    C[(long long)m*ldc + n] = v;
                }
            }
        }
    }
}

// ---------------- row softmax (1000 cols, in place) ----------------
__global__ __launch_bounds__(256)
void softmax_rows(float* __restrict__ S, int ncols)
{
    long long row = blockIdx.x;
    float* p = S + row * (long long)ncols;
    int t = threadIdx.x;
    float vals[4];
    float mx = -1e30f;
    #pragma unroll
    for (int i = 0; i < 4; i++) {
        int c = t + i*256;
        vals[i] = (c < ncols) ? p[c] : -1e30f;
        mx = fmaxf(mx, vals[i]);
    }
    __shared__ float red[256];
    red[t] = mx; __syncthreads();
    for (int s = 128; s > 0; s >>= 1) { if (t < s) red[t] = fmaxf(red[t], red[t+s]); __syncthreads(); }
    mx = red[0]; __syncthreads();
    float sum = 0.f;
    #pragma unroll
    for (int i = 0; i < 4; i++) { vals[i] = __expf(vals[i] - mx); sum += vals[i]; }
    red[t] = sum; __syncthreads();
    for (int s = 128; s > 0; s >>= 1) { if (t < s) red[t] += red[t+s]; __syncthreads(); }
    float inv = 1.f / red[0];
    #pragma unroll
    for (int i = 0; i < 4; i++) {
        int c = t + i*256;
        if (c < ncols) p[c] = vals[i] * inv;
    }
}

// ---------------- InstanceNorm1d over item dim (in place) ----------------
__global__ void inorm1d(float* __restrict__ X, const float* __restrict__ g,
                        const float* __restrict__ be, int Nrows)
{
    int b = blockIdx.y;
    int c = blockIdx.x * 32 + threadIdx.x;
    int ty = threadIdx.y;
    float* Xb = X + (long long)b * Nrows * D_;
    float s = 0.f, q = 0.f;
    for (int n = ty; n < Nrows; n += 8) {
        float x = Xb[(long long)n * D_ + c];
        s += x; q += x * x;
    }
    __shared__ float sh_s[8][32], sh_q[8][32];
    sh_s[ty][threadIdx.x] = s; sh_q[ty][threadIdx.x] = q;
    __syncthreads();
    __shared__ float sh_m[32], sh_r[32];
    if (ty == 0) {
        float S = 0.f, Q = 0.f;
        #pragma unroll
        for (int i = 0; i < 8; i++) { S += sh_s[i][threadIdx.x]; Q += sh_q[i][threadIdx.x]; }
        float mean = S / (float)Nrows;
        float var  = Q / (float)Nrows - mean*mean;
        sh_m[threadIdx.x] = mean;
        sh_r[threadIdx.x] = rsqrtf(var + EPS_);
    }
    __syncthreads();
    float mean = sh_m[threadIdx.x], r = sh_r[threadIdx.x];
    float gg = g[c], bb = be[c];
    for (int n = ty; n < Nrows; n += 8) {
        long long idx = (long long)n * D_ + c;
        Xb[idx] = gg * (Xb[idx] - mean) * r + bb;
    }
}

// ---------------- input projections + concat ----------------
__global__ void init_x(const float* __restrict__ wf, const float* __restrict__ tf,
                       const float* __restrict__ Wws, const float* __restrict__ bws,
                       const float* __restrict__ Wwe, const float* __restrict__ bwe,
                       const float* __restrict__ Wt,  const float* __restrict__ bt)
{
    int t = blockIdx.x * blockDim.x + threadIdx.x;
    if (t >= B_*N_*D_) return;
    int d = t & 511;
    int n = (t >> 9) % N_;
    int b = t / (D_*N_);
    float v;
    if (n < NW_) {
        const float* f = wf + (b*NW_ + n)*4;
        v = bws[d];
        #pragma unroll
        for (int k = 0; k < 4; k++) v += f[k] * Wws[k*D_ + d];
    } else if (n < 2*NW_) {
        const float* f = wf + (b*NW_ + (n - NW_))*4;
        v = bwe[d];
        #pragma unroll
        for (int k = 0; k < 4; k++) v += f[k] * Wwe[k*D_ + d];
    } else {
        const float* f = tf + (b*NT_ + (n - 2*NW_))*8;
        v = bt[d];
        #pragma unroll
        for (int k = 0; k < 8; k++) v += f[k] * Wt[k*D_ + d];
    }
    g_X[t] = v;
}

// ---------------- edge bias: analytic InstanceNorm2d coefficients ----------------
__global__ void zero_esum() { if (threadIdx.x < B_*5) g_esum[threadIdx.x] = 0.0; }

__global__ __launch_bounds__(256)
void edge_stats(const float* __restrict__ ef)
{
    int b = blockIdx.y;
    const float2* p = (const float2*)ef + (long long)b * (N_*N_);
    int stride = gridDim.x * blockDim.x;
    float s0=0,s1=0,s00=0,s11=0,s01=0;
    for (int i = blockIdx.x*blockDim.x + threadIdx.x; i < N_*N_; i += stride) {
        float2 f = p[i];
        s0 += f.x; s1 += f.y; s00 += f.x*f.x; s11 += f.y*f.y; s01 += f.x*f.y;
    }
    __shared__ double red[256];
    double loc[5] = {(double)s0,(double)s1,(double)s00,(double)s11,(double)s01};
    for (int j = 0; j < 5; j++) {
        red[threadIdx.x] = loc[j];
        __syncthreads();
        for (int s = 128; s > 0; s >>= 1) { if (threadIdx.x < s) red[threadIdx.x] += red[threadIdx.x+s]; __syncthreads(); }
        if (threadIdx.x == 0) atomicAdd(&g_esum[b*5+j], red[0]);
        __syncthreads();
    }
}

__global__ void edge_params(const float* __restrict__ We, const float* __restrict__ be,
                            const float* __restrict__ ge, const float* __restrict__ bee)
{
    int t = threadIdx.x;
    if (t >= B_*H_) return;
    int b = t / H_, h = t % H_;
    double cnt = (double)N_ * (double)N_;
    double m0  = g_esum[b*5+0]/cnt, m1 = g_esum[b*5+1]/cnt;
    double v00 = g_esum[b*5+2]/cnt - m0*m0;
    double v11 = g_esum[b*5+3]/cnt - m1*m1;
    double v01 = g_esum[b*5+4]/cnt - m0*m1;
    double w0 = We[0*H_+h], w1 = We[1*H_+h];
    double mean = w0*m0 + w1*m1 + (double)be[h];
    double var  = w0*w0*v00 + 2.0*w0*w1*v01 + w1*w1*v11;
    double grs  = (double)ge[h] / sqrt(var + (double)EPS_);
    g_ec0[t] = (float)(w0*grs);
    g_ec1[t] = (float)(w1*grs);
    g_ec2[t] = (float)(((double)be[h] - mean)*grs + (double)bee[h]);
}

// ---------------- weight packing ----------------
__global__ void pack_qkv(const float* __restrict__ Wq, const float* __restrict__ Wk,
                         const float* __restrict__ Wv)
{
    int t = blockIdx.x * blockDim.x + threadIdx.x;
    if (t >= L_*D_*D_) return;
    int e = t & 63;
    int h = (t >> 6) & 7;
    int d = (t >> 9) & 511;
    int l = t >> 18;
    long long src = (((long long)l*H_ + h)*D_ + d)*HD_ + e;
    long long dst = ((long long)l*D_ + d)*(3*D_) + h*HD_ + e;
    g_Wpack[dst]          = Wq[src];
    g_Wpack[dst + D_]     = Wk[src];
    g_Wpack[dst + 2*D_]   = Wv[src];
}

__global__ void pack_kv(const float* __restrict__ Kd, const float* __restrict__ Vd)
{
    int t = blockIdx.x * blockDim.x + threadIdx.x;
    if (t >= D_*D_) return;
    int e = t & 63;
    int h = (t >> 6) & 7;
    int d = t >> 9;
    long long src = ((long long)h*D_ + d)*HD_ + e;
    long long dst = (long long)d*(2*D_) + h*HD_ + e;
    g_WkvP[dst]        = Kd[src];
    g_WkvP[dst + D_]   = Vd[src];
}

// ---------------- finish token append into output X ----------------
__global__ void write_xout(const float* __restrict__ fin, float* __restrict__ out)
{
    int t = blockIdx.x * blockDim.x + threadIdx.x;
    if (t >= B_*N1_*D_) return;
    int d = t & 511;
    int n = (t >> 9) % N1_;
    int b = t / (N1_*D_);
    out[t] = (n < N_) ? g_X[((long long)b*N_ + n)*D_ + d] : fin[d];
}

// ---------------- reorder decode K/V to [H][B][N1][HD] ----------------
__global__ void write_kv(float* __restrict__ outK, float* __restrict__ outV)
{
    int t = blockIdx.x * blockDim.x + threadIdx.x;
    if (t >= H_*B_*N1_*HD_) return;
    int e = t & 63;
    int n = (t >> 6) % N1_;
    int rem = t / (HD_*N1_);
    int b = rem & 3;
    int h = rem >> 2;
    long long src = ((long long)(b*N1_ + n))*(2*D_) + h*HD_ + e;
    outK[t] = g_KV[src];
    outV[t] = g_KV[src + D_];
}

// ---------------- host orchestration ----------------
static inline int cdiv(int a, int b) { return (a + b - 1) / b; }

extern "C" void kernel_launch(void* const* d_in, const int* in_sizes, int n_in,
                              void* d_out, int out_size)
{
    const float* wf   = (const float*)d_in[0];
    const float* tf   = (const float*)d_in[1];
    const float* ef   = (const float*)d_in[2];
    const float* Wws  = (const float*)d_in[3];
    const float* bws  = (const float*)d_in[4];
    const float* Wwe  = (const float*)d_in[5];
    const float* bwe  = (const float*)d_in[6];
    const float* Wt   = (const float*)d_in[7];
    const float* bt   = (const float*)d_in[8];
    const float* g_wt = (const float*)d_in[9];
    const float* be_wt= (const float*)d_in[10];
    const float* W_e  = (const float*)d_in[11];
    const float* b_e  = (const float*)d_in[12];
    const float* g_e  = (const float*)d_in[13];
    const float* be_e = (const float*)d_in[14];
    const float* Wq   = (const float*)d_in[15];
    const float* Wk   = (const float*)d_in[16];
    const float* Wv   = (const float*)d_in[17];
    const float* Wo   = (const float*)d_in[18];
    const float* W1   = (const float*)d_in[19];
    const float* b1   = (const float*)d_in[20];
    const float* W2   = (const float*)d_in[21];
    const float* b2   = (const float*)d_in[22];
    const float* g1   = (const float*)d_in[23];
    const float* be1  = (const float*)d_in[24];
    const float* g2   = (const float*)d_in[25];
    const float* be2  = (const float*)d_in[26];
    const float* fin  = (const float*)d_in[27];
    const float* Kd   = (const float*)d_in[28];
    const float* Vd   = (const float*)d_in[29];

    float* out  = (float*)d_out;
    float* outX = out;
    float* outK = out + (size_t)B_*N1_*D_;
    float* outV = outK + (size_t)H_*B_*N1_*HD_;

    float *pX, *pS, *pQKV, *pO, *pFF, *pWp, *pWkv, *pKV;
    cudaGetSymbolAddress((void**)&pX,   g_X);
    cudaGetSymbolAddress((void**)&pS,   g_S);
    cudaGetSymbolAddress((void**)&pQKV, g_QKV);
    cudaGetSymbolAddress((void**)&pO,   g_O);
    cudaGetSymbolAddress((void**)&pFF,  g_FF);
    cudaGetSymbolAddress((void**)&pWp,  g_Wpack);
    cudaGetSymbolAddress((void**)&pWkv, g_WkvP);
    cudaGetSymbolAddress((void**)&pKV,  g_KV);

    // ---- setup ----
    zero_esum<<<1, 32>>>();
    edge_stats<<<dim3(32, B_), 256>>>(ef);
    edge_params<<<1, 32>>>(W_e, b_e, g_e, be_e);
    pack_qkv<<<cdiv(L_*D_*D_, 256), 256>>>(Wq, Wk, Wv);
    pack_kv<<<cdiv(D_*D_, 256), 256>>>(Kd, Vd);
    init_x<<<cdiv(B_*N_*D_, 256), 256>>>(wf, tf, Wws, bws, Wwe, bwe, Wt, bt);
    inorm1d<<<dim3(D_/32, B_), dim3(32, 8)>>>(pX, g_wt, be_wt, N_);

    const int Mrows = B_*N_;                     // 4000
    const long long sE1 = (long long)B_*N_*N_;   // h-stride in g_S
    const long long sE0 = (long long)N_*N_;      // b-stride
    const long long sQb = (long long)N_*3*D_;    // b-stride in g_QKV rows

    for (int l = 0; l < L_; l++) {
        const float* Wp_l = pWp + (long long)l*D_*3*D_;
        // QKV: [4000,512] @ [512,1536]
        gemm_h3<128,128,4,2><<<dim3(cdiv(3*D_,128), cdiv(Mrows,128), 1), 256>>>(
            pX, D_, 0,0,  Wp_l, 3*D_, 0,0,  pQKV, 3*D_, 0,0,
            nullptr, 0, 0,0, nullptr, Mrows, 3*D_, D_, 1, 1.f, 0, 0, 0);
        // S = edge_bias + alpha * Q @ K^T  (batched over (h,b), edge bias fused)
        gemm_h3<128,128,4,2><<<dim3(cdiv(N_,128), cdiv(N_,128), H_*B_), 256>>>(
            pQKV,            3*D_, 64, sQb,
            pQKV + D_,       3*D_, 64, sQb,
            pS,              N_,   sE1, sE0,
            ef,              N_,   0, 0,
            nullptr, N_, N_, HD_, B_, ALPHA_, 1, 0, 1);
        // softmax rows
        softmax_rows<<<H_*B_*N_, 256>>>(pS, N_);
        // O_h = P @ V  (batched)
        gemm_h3<128,64,4,2><<<dim3(1, cdiv(N_,128), H_*B_), 256>>>(
            pS,              N_,   sE1, sE0,
            pQKV + 2*D_,     3*D_, 64, sQb,
            pO,              D_,   64, (long long)N_*D_,
            nullptr, 0, 0,0, nullptr, N_, HD_, N_, B_, 1.f, 0, 0, 0);
        // X = X + O @ Wo
        gemm_h3<128,128,4,2><<<dim3(cdiv(D_,128), cdiv(Mrows,128), 1), 256>>>(
            pO, D_, 0,0,  Wo + (long long)l*D_*D_, D_, 0,0,  pX, D_, 0,0,
            pX, D_, 0,0, nullptr, Mrows, D_, D_, 1, 1.f, 0, 0, 0);
        inorm1d<<<dim3(D_/32, B_), dim3(32, 8)>>>(pX, g1 + l*D_, be1 + l*D_, N_);
        // FF = relu(X @ W1 + b1)
        gemm_h3<128,128,4,2><<<dim3(cdiv(DFF_,128), cdiv(Mrows,128), 1), 256>>>(
            pX, D_, 0,0,  W1 + (long long)l*D_*DFF_, DFF_, 0,0,  pFF, DFF_, 0,0,
            nullptr, 0, 0,0, b1 + l*DFF_, Mrows, DFF_, D_, 1, 1.f, 0, 1, 0);
        // X = X + FF @ W2 + b2
        gemm_h3<128,128,4,2><<<dim3(cdiv(D_,128), cdiv(Mrows,128), 1), 256>>>(
            pFF, DFF_, 0,0,  W2 + (long long)l*DFF_*D_, D_, 0,0,  pX, D_, 0,0,
            pX, D_, 0,0, b2 + l*D_, Mrows, D_, DFF_, 1, 1.f, 0, 0, 0);
        inorm1d<<<dim3(D_/32, B_), dim3(32, 8)>>>(pX, g2 + l*D_, be2 + l*D_, N_);
    }

    // append finish token into output X
    write_xout<<<cdiv(B_*N1_*D_, 256), 256>>>(fin, outX);
    // decode K/V: [4004,512] @ [512,1024]
    gemm_h3<128,128,4,2><<<dim3(cdiv(2*D_,128), cdiv(B_*N1_,128), 1), 256>>>(
        outX, D_, 0,0,  pWkv, 2*D_, 0,0,  pKV, 2*D_, 0,0,
        nullptr, 0, 0,0, nullptr, B_*N1_, 2*D_, D_, 1, 1.f, 0, 0, 0);
    write_kv<<<cdiv(H_*B_*N1_*HD_, 256), 256>>>(outK, outV);
}

// round 6
// speedup vs baseline: 1.9513x; 1.3567x over previous
#include <cuda_runtime.h>
#include <cuda_fp16.h>
#include <math.h>

// ---------------- problem constants ----------------
#define B_   4
#define NW_  100
#define NT_  800
#define N_   1000
#define N1_  1001
#define D_   512
#define H_   8
#define HD_  64
#define DFF_ 2048
#define L_   3
#define EPS_ 1e-5f
#define ALPHA_ 0.125f   // 1/sqrt(64)
#define NPAD_ 1024      // padded kv length for AV GEMM k-dim

// ---------------- device scratch (no allocation allowed) ----------------
__device__ float  g_X   [B_*N_*D_];
__device__ float  g_S   [H_*B_*N_*N_];
__device__ float  g_KV  [B_*N1_*2*D_];
__device__ double g_esum[B_*5];
__device__ float  g_ec0[32], g_ec1[32], g_ec2[32];

__device__ __align__(16) __half g_Xh [B_*N_*D_];
__device__ __align__(16) __half g_Xl [B_*N_*D_];
__device__ __align__(16) __half g_QKVh[B_*N_*3*D_];
__device__ __align__(16) __half g_QKVl[B_*N_*3*D_];
__device__ __align__(16) __half g_Vth[B_*D_*NPAD_];
__device__ __align__(16) __half g_Vtl[B_*D_*NPAD_];
__device__ __align__(16) __half g_Ph [H_*B_*N_*NPAD_];
__device__ __align__(16) __half g_Pl [H_*B_*N_*NPAD_];
__device__ __align__(16) __half g_Oh [B_*N_*D_];
__device__ __align__(16) __half g_Ol [B_*N_*D_];
__device__ __align__(16) __half g_FFh[B_*N_*DFF_];
__device__ __align__(16) __half g_FFl[B_*N_*DFF_];
__device__ __align__(16) __half g_Wqkvh[L_*3*D_*D_];
__device__ __align__(16) __half g_Wqkvl[L_*3*D_*D_];
__device__ __align__(16) __half g_Woh[L_*D_*D_];
__device__ __align__(16) __half g_Wol[L_*D_*D_];
__device__ __align__(16) __half g_W1h[L_*DFF_*D_];
__device__ __align__(16) __half g_W1l[L_*DFF_*D_];
__device__ __align__(16) __half g_W2h[L_*D_*DFF_];
__device__ __align__(16) __half g_W2l[L_*D_*DFF_];
__device__ __align__(16) __half g_Wkvh[2*D_*D_];
__device__ __align__(16) __half g_Wkvl[2*D_*D_];
__device__ __align__(16) __half g_Xoh[B_*N1_*D_];
__device__ __align__(16) __half g_Xol[B_*N1_*D_];

__device__ __forceinline__ void splitf(float v, __half &h, __half &l) {
    h = __float2half_rn(v);
    l = __float2half_rn(v - __half2float(h));
}

__device__ __forceinline__ void cp16(unsigned dst, const void* src, bool p) {
    int sz = p ? 16 : 0;
    asm volatile("cp.async.ca.shared.global [%0], [%1], 16, %2;\n"
                 :: "r"(dst), "l"(src), "r"(sz));
}

#define LDSM4(r0,r1,r2,r3,a) \
    asm volatile("ldmatrix.sync.aligned.m8n8.x4.shared.b16 {%0,%1,%2,%3}, [%4];" \
                 : "=r"(r0),"=r"(r1),"=r"(r2),"=r"(r3) : "r"(a))

#define MMA16816(acc,a0,a1,a2,a3,b0,b1) \
    asm volatile("mma.sync.aligned.m16n8k16.row.col.f32.f16.f16.f32 " \
                 "{%0,%1,%2,%3}, {%4,%5,%6,%7}, {%8,%9}, {%0,%1,%2,%3};" \
                 : "+f"((acc)[0]), "+f"((acc)[1]), "+f"((acc)[2]), "+f"((acc)[3]) \
                 : "r"(a0), "r"(a1), "r"(a2), "r"(a3), "r"(b0), "r"(b1))

// ---------------- split-fp16 GEMM: precomputed hi/lo operands ----------------
// C[m,n] = alpha*sum_k A[m,k]*B[n,k]  (+bias[n]) (+addsrc | edge bias) (relu?)
// A,B given as hi/lo half arrays, both k-major. Outputs: fp32 C and/or hi/lo C.
// qkv_mode: also scatter transposed V (cols >= 1024) into g_Vt (padded).
template<int BM, int BN, int WARPS_M, int WARPS_N>
__global__ __launch_bounds__(WARPS_M*WARPS_N*32)
void gemm_hl(const __half* __restrict__ Ah, const __half* __restrict__ Al,
             int lda, long long sA1, long long sA0,
             const __half* __restrict__ Bh, const __half* __restrict__ Bl,
             int ldb, long long sB1, long long sB0,
             float* __restrict__ C, int ldc, long long sC1, long long sC0,
             __half* __restrict__ Ch, __half* __restrict__ Cl,
             int ldch, long long sCh1, long long sCh0,
             const float* __restrict__ addsrc, int ldadd, long long sD1, long long sD0,
             const float* __restrict__ bias,
             int M, int N, int K, int inner, float alpha,
             int relu, int edge_mode, int qkv_mode)
{
    constexpr int BK = 16;
    constexpr int LDK = BK + 8;   // 24 halves (48B): conflict-free ldmatrix
    constexpr int THREADS = WARPS_M*WARPS_N*32;
    constexpr int WM = BM/WARPS_M, WN = BN/WARPS_N;
    constexpr int MT = WM/16, NT = WN/8;

    __shared__ __align__(16) __half As[2][2][BM][LDK];
    __shared__ __align__(16) __half Bs[2][2][BN][LDK];

    int z = blockIdx.z, z1 = z/inner, z0 = z%inner;
    Ah += z1*sA1 + z0*sA0;  Al += z1*sA1 + z0*sA0;
    Bh += z1*sB1 + z0*sB0;  Bl += z1*sB1 + z0*sB0;
    if (C)  C  += z1*sC1  + z0*sC0;
    if (Ch) { Ch += z1*sCh1 + z0*sCh0; Cl += z1*sCh1 + z0*sCh0; }

    int tid = threadIdx.x;
    int warp = tid>>5, lane = tid&31, g = lane>>2, tg = lane&3;
    int wm = (warp % WARPS_M)*WM, wn = (warp / WARPS_M)*WN;
    int row0 = blockIdx.y*BM, col0 = blockIdx.x*BN;

    const unsigned sAb = (unsigned)__cvta_generic_to_shared(&As[0][0][0][0]);
    const unsigned sBb = (unsigned)__cvta_generic_to_shared(&Bs[0][0][0][0]);

    float acc[MT][NT][4] = {};

    // ldmatrix per-lane address components
    int aRow = (lane&7) + ((lane>>3)&1)*8;
    int aCol = ((lane>>4)&1)*8;
    int bRow = (lane&7) + ((lane>>4)&1)*8;
    int bCol = ((lane>>3)&1)*8;

    auto issue = [&](int kt, int buf) {
        {
            int row = tid>>1, ch = (tid&1)*8;
            bool p = (row0+row) < M;
            long long go = (long long)(row0+row)*lda + kt + ch;
            cp16(sAb + (unsigned)((((buf*2+0)*BM + row)*LDK + ch)*2), Ah + go, p);
            cp16(sAb + (unsigned)((((buf*2+1)*BM + row)*LDK + ch)*2), Al + go, p);
        }
        if (tid < BN*2) {
            int row = tid>>1, ch = (tid&1)*8;
            bool p = (col0+row) < N;
            long long go = (long long)(col0+row)*ldb + kt + ch;
            cp16(sBb + (unsigned)((((buf*2+0)*BN + row)*LDK + ch)*2), Bh + go, p);
            cp16(sBb + (unsigned)((((buf*2+1)*BN + row)*LDK + ch)*2), Bl + go, p);
        }
        asm volatile("cp.async.commit_group;");
    };

    auto compute = [&](int buf) {
        unsigned ah[MT][4], al[MT][4];
        #pragma unroll
        for (int mt = 0; mt < MT; mt++) {
            int r = wm + mt*16 + aRow;
            LDSM4(ah[mt][0], ah[mt][1], ah[mt][2], ah[mt][3],
                  sAb + (unsigned)((((buf*2+0)*BM + r)*LDK + aCol)*2));
            LDSM4(al[mt][0], al[mt][1], al[mt][2], al[mt][3],
                  sAb + (unsigned)((((buf*2+1)*BM + r)*LDK + aCol)*2));
        }
        #pragma unroll
        for (int nt2 = 0; nt2 < NT/2; nt2++) {
            int rB = wn + nt2*16 + bRow;
            unsigned bh0,bh1,bh2,bh3, bl0,bl1,bl2,bl3;
            LDSM4(bh0,bh1,bh2,bh3, sBb + (unsigned)((((buf*2+0)*BN + rB)*LDK + bCol)*2));
            LDSM4(bl0,bl1,bl2,bl3, sBb + (unsigned)((((buf*2+1)*BN + rB)*LDK + bCol)*2));
            #pragma unroll
            for (int mt = 0; mt < MT; mt++) {
                MMA16816(acc[mt][nt2*2], ah[mt][0],ah[mt][1],ah[mt][2],ah[mt][3], bh0,bh1);
                MMA16816(acc[mt][nt2*2], ah[mt][0],ah[mt][1],ah[mt][2],ah[mt][3], bl0,bl1);
                MMA16816(acc[mt][nt2*2], al[mt][0],al[mt][1],al[mt][2],al[mt][3], bh0,bh1);
            }
            #pragma unroll
            for (int mt = 0; mt < MT; mt++) {
                MMA16816(acc[mt][nt2*2+1], ah[mt][0],ah[mt][1],ah[mt][2],ah[mt][3], bh2,bh3);
                MMA16816(acc[mt][nt2*2+1], ah[mt][0],ah[mt][1],ah[mt][2],ah[mt][3], bl2,bl3);
                MMA16816(acc[mt][nt2*2+1], al[mt][0],al[mt][1],al[mt][2],al[mt][3], bh2,bh3);
            }
        }
    };

    issue(0, 0);
    int buf = 0;
    for (int kt = 0; kt < K; kt += BK) {
        asm volatile("cp.async.wait_group 0;");
        __syncthreads();
        if (kt + BK < K) issue(kt + BK, buf ^ 1);
        compute(buf);
        buf ^= 1;
        __syncthreads();
    }

    // ---- epilogue ----
    float ec0 = 0.f, ec1 = 0.f, ec2 = 0.f;
    const float2* e2 = nullptr;
    if (edge_mode) {
        int t = z0*H_ + z1;
        ec0 = g_ec0[t]; ec1 = g_ec1[t]; ec2 = g_ec2[t];
        e2 = (const float2*)addsrc + (long long)z0 * ((long long)N_*N_);
    } else if (addsrc) {
        addsrc += z1*sD1 + z0*sD0;
    }

    #pragma unroll
    for (int mt = 0; mt < MT; mt++) {
        #pragma unroll
        for (int nt = 0; nt < NT; nt++) {
            int nb = col0 + wn + nt*8 + tg*2;
            #pragma unroll
            for (int h2 = 0; h2 < 2; h2++) {
                int m = row0 + wm + mt*16 + g + h2*8;
                if (m >= M) continue;
                #pragma unroll
                for (int j = 0; j < 2; j++) {
                    int n = nb + j;
                    if (n >= N) continue;
                    float v = alpha * acc[mt][nt][h2*2+j];
                    if (bias)   v += bias[n];
                    if (edge_mode) {
                        float2 f = e2[(long long)m*ldadd + n];
                        v += f.x*ec0 + f.y*ec1 + ec2;
                    } else if (addsrc) {
                        v += addsrc[(long long)m*ldadd + n];
                    }
                    if (relu) v = fmaxf(v, 0.f);
                    if (C) C[(long long)m*ldc + n] = v;
                    if (Ch) {
                        __half hh, ll; splitf(v, hh, ll);
                        Ch[(long long)m*ldch + n] = hh;
                        Cl[(long long)m*ldch + n] = ll;
                        if (qkv_mode && n >= 1024) {
                            int b = m / N_, mm = m - b*N_;
                            long long vi = ((long long)b*D_ + (n-1024))*NPAD_ + mm;
                            g_Vth[vi] = hh; g_Vtl[vi] = ll;
                        }
                    }
                }
            }
        }
    }
}

// ---------------- row softmax: fp32 S -> hi/lo half P (padded to 1024) ----------------
__global__ __launch_bounds__(256)
void softmax_rows(const float* __restrict__ S, __half* __restrict__ Ph,
                  __half* __restrict__ Pl)
{
    long long row = blockIdx.x;
    const float* p = S + row * (long long)N_;
    int t = threadIdx.x;
    float vals[4];
    float mx = -1e30f;
    #pragma unroll
    for (int i = 0; i < 4; i++) {
        int c = t + i*256;
        vals[i] = (c < N_) ? p[c] : -1e30f;
        mx = fmaxf(mx, vals[i]);
    }
    __shared__ float red[256];
    red[t] = mx; __syncthreads();
    for (int s = 128; s > 0; s >>= 1) { if (t < s) red[t] = fmaxf(red[t], red[t+s]); __syncthreads(); }
    mx = red[0]; __syncthreads();
    float sum = 0.f;
    #pragma unroll
    for (int i = 0; i < 4; i++) { vals[i] = __expf(vals[i] - mx); sum += vals[i]; }
    red[t] = sum; __syncthreads();
    for (int s = 128; s > 0; s >>= 1) { if (t < s) red[t] += red[t+s]; __syncthreads(); }
    float inv = 1.f / red[0];
    __half* oh = Ph + row * (long long)NPAD_;
    __half* ol = Pl + row * (long long)NPAD_;
    #pragma unroll
    for (int i = 0; i < 4; i++) {
        int c = t + i*256;           // covers 0..1023 exactly
        float v = (c < N_) ? vals[i]*inv : 0.f;
        __half hh, ll; splitf(v, hh, ll);
        oh[c] = hh; ol[c] = ll;
    }
}

// ---------------- InstanceNorm1d over item dim (fp32 in place + hi/lo out) ------
__global__ void inorm1d(float* __restrict__ X, const float* __restrict__ g,
                        const float* __restrict__ be,
                        __half* __restrict__ Xh, __half* __restrict__ Xl, int Nrows)
{
    int b = blockIdx.y;
    int c = blockIdx.x * 32 + threadIdx.x;
    int ty = threadIdx.y;
    long long base = (long long)b * Nrows * D_;
    float* Xb = X + base;
    float s = 0.f, q = 0.f;
    for (int n = ty; n < Nrows; n += 8) {
        float x = Xb[(long long)n * D_ + c];
        s += x; q += x * x;
    }
    __shared__ float sh_s[8][32], sh_q[8][32];
    sh_s[ty][threadIdx.x] = s; sh_q[ty][threadIdx.x] = q;
    __syncthreads();
    __shared__ float sh_m[32], sh_r[32];
    if (ty == 0) {
        float S = 0.f, Q = 0.f;
        #pragma unroll
        for (int i = 0; i < 8; i++) { S += sh_s[i][threadIdx.x]; Q += sh_q[i][threadIdx.x]; }
        float mean = S / (float)Nrows;
        float var  = Q / (float)Nrows - mean*mean;
        sh_m[threadIdx.x] = mean;
        sh_r[threadIdx.x] = rsqrtf(var + EPS_);
    }
    __syncthreads();
    float mean = sh_m[threadIdx.x], r = sh_r[threadIdx.x];
    float gg = g[c], bb = be[c];
    for (int n = ty; n < Nrows; n += 8) {
        long long idx = (long long)n * D_ + c;
        float v = gg * (Xb[idx] - mean) * r + bb;
        Xb[idx] = v;
        __half hh, ll; splitf(v, hh, ll);
        Xh[base + idx] = hh; Xl[base + idx] = ll;
    }
}

// ---------------- input projections + concat ----------------
__global__ void init_x(const float* __restrict__ wf, const float* __restrict__ tf,
                       const float* __restrict__ Wws, const float* __restrict__ bws,
                       const float* __restrict__ Wwe, const float* __restrict__ bwe,
                       const float* __restrict__ Wt,  const float* __restrict__ bt)
{
    int t = blockIdx.x * blockDim.x + threadIdx.x;
    if (t >= B_*N_*D_) return;
    int d = t & 511;
    int n = (t >> 9) % N_;
    int b = t / (D_*N_);
    float v;
    if (n < NW_) {
        const float* f = wf + (b*NW_ + n)*4;
        v = bws[d];
        #pragma unroll
        for (int k = 0; k < 4; k++) v += f[k] * Wws[k*D_ + d];
    } else if (n < 2*NW_) {
        const float* f = wf + (b*NW_ + (n - NW_))*4;
        v = bwe[d];
        #pragma unroll
        for (int k = 0; k < 4; k++) v += f[k] * Wwe[k*D_ + d];
    } else {
        const float* f = tf + (b*NT_ + (n - 2*NW_))*8;
        v = bt[d];
        #pragma unroll
        for (int k = 0; k < 8; k++) v += f[k] * Wt[k*D_ + d];
    }
    g_X[t] = v;
}

// ---------------- edge bias: analytic InstanceNorm2d coefficients ----------------
__global__ void zero_esum() { if (threadIdx.x < B_*5) g_esum[threadIdx.x] = 0.0; }

__global__ __launch_bounds__(256)
void edge_stats(const float* __restrict__ ef)
{
    int b = blockIdx.y;
    const float2* p = (const float2*)ef + (long long)b * (N_*N_);
    int stride = gridDim.x * blockDim.x;
    float s0=0,s1=0,s00=0,s11=0,s01=0;
    for (int i = blockIdx.x*blockDim.x + threadIdx.x; i < N_*N_; i += stride) {
        float2 f = p[i];
        s0 += f.x; s1 += f.y; s00 += f.x*f.x; s11 += f.y*f.y; s01 += f.x*f.y;
    }
    __shared__ double red[256];
    double loc[5] = {(double)s0,(double)s1,(double)s00,(double)s11,(double)s01};
    for (int j = 0; j < 5; j++) {
        red[threadIdx.x] = loc[j];
        __syncthreads();
        for (int s = 128; s > 0; s >>= 1) { if (threadIdx.x < s) red[threadIdx.x] += red[threadIdx.x+s]; __syncthreads(); }
        if (threadIdx.x == 0) atomicAdd(&g_esum[b*5+j], red[0]);
        __syncthreads();
    }
}

__global__ void edge_params(const float* __restrict__ We, const float* __restrict__ be,
                            const float* __restrict__ ge, const float* __restrict__ bee)
{
    int t = threadIdx.x;
    if (t >= B_*H_) return;
    int b = t / H_, h = t % H_;
    double cnt = (double)N_ * (double)N_;
    double m0  = g_esum[b*5+0]/cnt, m1 = g_esum[b*5+1]/cnt;
    double v00 = g_esum[b*5+2]/cnt - m0*m0;
    double v11 = g_esum[b*5+3]/cnt - m1*m1;
    double v01 = g_esum[b*5+4]/cnt - m0*m1;
    double w0 = We[0*H_+h], w1 = We[1*H_+h];
    double mean = w0*m0 + w1*m1 + (double)be[h];
    double var  = w0*w0*v00 + 2.0*w0*w1*v01 + w1*w1*v11;
    double grs  = (double)ge[h] / sqrt(var + (double)EPS_);
    g_ec0[t] = (float)(w0*grs);
    g_ec1[t] = (float)(w1*grs);
    g_ec2[t] = (float)(((double)be[h] - mean)*grs + (double)bee[h]);
}

// ---------------- weight packing (k-major hi/lo halves) ----------------
__global__ void pack_qkv(const float* __restrict__ Wq, const float* __restrict__ Wk,
                         const float* __restrict__ Wv)
{
    int t = blockIdx.x * blockDim.x + threadIdx.x;
    if (t >= L_*3*D_*D_) return;
    int k = t & 511;
    int n = (t >> 9) % (3*D_);
    int l = t / (3*D_*D_);
    int sec = n / D_, hn = n - sec*D_, h = hn >> 6, e = hn & 63;
    const float* W = (sec == 0) ? Wq : (sec == 1) ? Wk : Wv;
    float v = W[(((long long)l*H_ + h)*D_ + k)*HD_ + e];
    splitf(v, g_Wqkvh[t], g_Wqkvl[t]);
}

__global__ void pack_wo(const float* __restrict__ Wo)
{
    int t = blockIdx.x * blockDim.x + threadIdx.x;
    if (t >= L_*D_*D_) return;
    int k = t & 511, n = (t >> 9) & 511, l = t >> 18;
    float v = Wo[((long long)l*D_ + k)*D_ + n];
    splitf(v, g_Woh[t], g_Wol[t]);
}

__global__ void pack_w1(const float* __restrict__ W1)
{
    int t = blockIdx.x * blockDim.x + threadIdx.x;
    if (t >= L_*DFF_*D_) return;
    int k = t & 511;
    int n = (t >> 9) % DFF_;
    int l = t / (DFF_*D_);
    float v = W1[((long long)l*D_ + k)*DFF_ + n];
    splitf(v, g_W1h[t], g_W1l[t]);
}

__global__ void pack_w2(const float* __restrict__ W2)
{
    int t = blockIdx.x * blockDim.x + threadIdx.x;
    if (t >= L_*D_*DFF_) return;
    int k = t & 2047;
    int n = (t >> 11) & 511;
    int l = t / (D_*DFF_);
    float v = W2[((long long)l*DFF_ + k)*D_ + n];
    splitf(v, g_W2h[t], g_W2l[t]);
}

__global__ void pack_kvw(const float* __restrict__ Kd, const float* __restrict__ Vd)
{
    int t = blockIdx.x * blockDim.x + threadIdx.x;
    if (t >= 2*D_*D_) return;
    int k = t & 511, n = t >> 9;
    int sec = n >> 9, hn = n & 511, h = hn >> 6, e = hn & 63;
    const float* W = sec ? Vd : Kd;
    float v = W[((long long)h*D_ + k)*HD_ + e];
    splitf(v, g_Wkvh[t], g_Wkvl[t]);
}

__global__ void zero_vt_pad()
{
    int t = blockIdx.x * blockDim.x + threadIdx.x;
    if (t >= B_*D_*(NPAD_-N_)) return;
    int c = N_ + t % (NPAD_-N_);
    int r = t / (NPAD_-N_);
    __half z = __float2half(0.f);
    g_Vth[(long long)r*NPAD_ + c] = z;
    g_Vtl[(long long)r*NPAD_ + c] = z;
}

// ---------------- finish token append into output X (+ hi/lo) ----------------
__global__ void write_xout(const float* __restrict__ fin, float* __restrict__ out)
{
    int t = blockIdx.x * blockDim.x + threadIdx.x;
    if (t >= B_*N1_*D_) return;
    int d = t & 511;
    int n = (t >> 9) % N1_;
    int b = t / (N1_*D_);
    float v = (n < N_) ? g_X[((long long)b*N_ + n)*D_ + d] : fin[d];
    out[t] = v;
    splitf(v, g_Xoh[t], g_Xol[t]);
}

// ---------------- reorder decode K/V to [H][B][N1][HD] ----------------
__global__ void write_kv(float* __restrict__ outK, float* __restrict__ outV)
{
    int t = blockIdx.x * blockDim.x + threadIdx.x;
    if (t >= H_*B_*N1_*HD_) return;
    int e = t & 63;
    int n = (t >> 6) % N1_;
    int rem = t / (HD_*N1_);
    int b = rem & 3;
    int h = rem >> 2;
    long long src = ((long long)(b*N1_ + n))*(2*D_) + h*HD_ + e;
    outK[t] = g_KV[src];
    outV[t] = g_KV[src + D_];
}

// ---------------- host orchestration ----------------
static inline int cdiv(int a, int b) { return (a + b - 1) / b; }

extern "C" void kernel_launch(void* const* d_in, const int* in_sizes, int n_in,
                              void* d_out, int out_size)
{
    const float* wf   = (const float*)d_in[0];
    const float* tf   = (const float*)d_in[1];
    const float* ef   = (const float*)d_in[2];
    const float* Wws  = (const float*)d_in[3];
    const float* bws  = (const float*)d_in[4];
    const float* Wwe  = (const float*)d_in[5];
    const float* bwe  = (const float*)d_in[6];
    const float* Wt   = (const float*)d_in[7];
    const float* bt   = (const float*)d_in[8];
    const float* g_wt = (const float*)d_in[9];
    const float* be_wt= (const float*)d_in[10];
    const float* W_e  = (const float*)d_in[11];
    const float* b_e  = (const float*)d_in[12];
    const float* g_e  = (const float*)d_in[13];
    const float* be_e = (const float*)d_in[14];
    const float* Wq   = (const float*)d_in[15];
    const float* Wk   = (const float*)d_in[16];
    const float* Wv   = (const float*)d_in[17];
    const float* Wo   = (const float*)d_in[18];
    const float* W1   = (const float*)d_in[19];
    const float* b1   = (const float*)d_in[20];
    const float* W2   = (const float*)d_in[21];
    const float* b2   = (const float*)d_in[22];
    const float* g1   = (const float*)d_in[23];
    const float* be1  = (const float*)d_in[24];
    const float* g2   = (const float*)d_in[25];
    const float* be2  = (const float*)d_in[26];
    const float* fin  = (const float*)d_in[27];
    const float* Kd   = (const float*)d_in[28];
    const float* Vd   = (const float*)d_in[29];

    float* out  = (float*)d_out;
    float* outX = out;
    float* outK = out + (size_t)B_*N1_*D_;
    float* outV = outK + (size_t)H_*B_*N1_*HD_;

    float *pX, *pS, *pKV;
    __half *pXh,*pXl,*pQh,*pQl,*pVth,*pVtl,*pPh,*pPl,*pOhh,*pOll,*pFh,*pFl;
    __half *pWqh,*pWql,*pWoh,*pWol,*pW1h,*pW1l,*pW2h,*pW2l,*pWkh,*pWkl,*pXoh,*pXol;
    cudaGetSymbolAddress((void**)&pX,  g_X);
    cudaGetSymbolAddress((void**)&pS,  g_S);
    cudaGetSymbolAddress((void**)&pKV, g_KV);
    cudaGetSymbolAddress((void**)&pXh, g_Xh);   cudaGetSymbolAddress((void**)&pXl, g_Xl);
    cudaGetSymbolAddress((void**)&pQh, g_QKVh); cudaGetSymbolAddress((void**)&pQl, g_QKVl);
    cudaGetSymbolAddress((void**)&pVth,g_Vth);  cudaGetSymbolAddress((void**)&pVtl,g_Vtl);
    cudaGetSymbolAddress((void**)&pPh, g_Ph);   cudaGetSymbolAddress((void**)&pPl, g_Pl);
    cudaGetSymbolAddress((void**)&pOhh,g_Oh);   cudaGetSymbolAddress((void**)&pOll,g_Ol);
    cudaGetSymbolAddress((void**)&pFh, g_FFh);  cudaGetSymbolAddress((void**)&pFl, g_FFl);
    cudaGetSymbolAddress((void**)&pWqh,g_Wqkvh);cudaGetSymbolAddress((void**)&pWql,g_Wqkvl);
    cudaGetSymbolAddress((void**)&pWoh,g_Woh);  cudaGetSymbolAddress((void**)&pWol,g_Wol);
    cudaGetSymbolAddress((void**)&pW1h,g_W1h);  cudaGetSymbolAddress((void**)&pW1l,g_W1l);
    cudaGetSymbolAddress((void**)&pW2h,g_W2h);  cudaGetSymbolAddress((void**)&pW2l,g_W2l);
    cudaGetSymbolAddress((void**)&pWkh,g_Wkvh); cudaGetSymbolAddress((void**)&pWkl,g_Wkvl);
    cudaGetSymbolAddress((void**)&pXoh,g_Xoh);  cudaGetSymbolAddress((void**)&pXol,g_Xol);

    // ---- setup ----
    zero_esum<<<1, 32>>>();
    edge_stats<<<dim3(32, B_), 256>>>(ef);
    edge_params<<<1, 32>>>(W_e, b_e, g_e, be_e);
    pack_qkv<<<cdiv(L_*3*D_*D_, 256), 256>>>(Wq, Wk, Wv);
    pack_wo <<<cdiv(L_*D_*D_, 256), 256>>>(Wo);
    pack_w1 <<<cdiv(L_*DFF_*D_, 256), 256>>>(W1);
    pack_w2 <<<cdiv(L_*D_*DFF_, 256), 256>>>(W2);
    pack_kvw<<<cdiv(2*D_*D_, 256), 256>>>(Kd, Vd);
    zero_vt_pad<<<cdiv(B_*D_*(NPAD_-N_), 256), 256>>>();
    init_x<<<cdiv(B_*N_*D_, 256), 256>>>(wf, tf, Wws, bws, Wwe, bwe, Wt, bt);
    inorm1d<<<dim3(D_/32, B_), dim3(32, 8)>>>(pX, g_wt, be_wt, pXh, pXl, N_);

    const int Mrows = B_*N_;                     // 4000
    const long long sE1 = (long long)B_*N_*N_;   // h-stride in g_S
    const long long sE0 = (long long)N_*N_;      // b-stride

    for (int l = 0; l < L_; l++) {
        long long wq = (long long)l*3*D_*D_;
        // QKV: [4000,512]x[1536,512]^T -> hi/lo halves + Vt scatter
        gemm_hl<128,128,4,2><<<dim3(12, 32, 1), 256>>>(
            pXh, pXl, D_, 0,0,
            pWqh + wq, pWql + wq, D_, 0,0,
            nullptr, 0, 0,0,
            pQh, pQl, 3*D_, 0,0,
            nullptr, 0, 0,0, nullptr,
            Mrows, 3*D_, D_, 1, 1.f, 0, 0, 1);
        // S = edge_bias + alpha * Q@K^T (fp32), batched over (h,b)
        gemm_hl<128,128,4,2><<<dim3(8, 8, H_*B_), 256>>>(
            pQh, pQl,              3*D_, 64, (long long)N_*3*D_,
            pQh + D_, pQl + D_,    3*D_, 64, (long long)N_*3*D_,
            pS, N_, sE1, sE0,
            nullptr, nullptr, 0, 0,0,
            ef, N_, 0,0, nullptr,
            N_, N_, HD_, B_, ALPHA_, 0, 1, 0);
        // softmax -> P hi/lo (k-padded)
        softmax_rows<<<H_*B_*N_, 256>>>(pS, pPh, pPl);
        // O_h = P @ V  (A = P, B = Vt), batched over (h,b)
        gemm_hl<128,64,4,2><<<dim3(1, 8, H_*B_), 256>>>(
            pPh, pPl, NPAD_, (long long)B_*N_*NPAD_, (long long)N_*NPAD_,
            pVth, pVtl, NPAD_, (long long)HD_*NPAD_, (long long)D_*NPAD_,
            nullptr, 0, 0,0,
            pOhh, pOll, D_, HD_, (long long)N_*D_,
            nullptr, 0, 0,0, nullptr,
            N_, HD_, NPAD_, B_, 1.f, 0, 0, 0);
        // X = X + O @ Wo   (fp32)
        long long wo = (long long)l*D_*D_;
        gemm_hl<128,128,4,2><<<dim3(4, 32, 1), 256>>>(
            pOhh, pOll, D_, 0,0,
            pWoh + wo, pWol + wo, D_, 0,0,
            pX, D_, 0,0,
            nullptr, nullptr, 0, 0,0,
            pX, D_, 0,0, nullptr,
            Mrows, D_, D_, 1, 1.f, 0, 0, 0);
        inorm1d<<<dim3(D_/32, B_), dim3(32, 8)>>>(pX, g1 + l*D_, be1 + l*D_, pXh, pXl, N_);
        // FF = relu(X @ W1 + b1) -> hi/lo halves
        long long w1o = (long long)l*DFF_*D_;
        gemm_hl<128,128,4,2><<<dim3(16, 32, 1), 256>>>(
            pXh, pXl, D_, 0,0,
            pW1h + w1o, pW1l + w1o, D_, 0,0,
            nullptr, 0, 0,0,
            pFh, pFl, DFF_, 0,0,
            nullptr, 0, 0,0, b1 + l*DFF_,
            Mrows, DFF_, D_, 1, 1.f, 1, 0, 0);
        // X = X + FF @ W2 + b2  (fp32)
        long long w2o = (long long)l*D_*DFF_;
        gemm_hl<128,128,4,2><<<dim3(4, 32, 1), 256>>>(
            pFh, pFl, DFF_, 0,0,
            pW2h + w2o, pW2l + w2o, DFF_, 0,0,
            pX, D_, 0,0,
            nullptr, nullptr, 0, 0,0,
            pX, D_, 0,0, b2 + l*D_,
            Mrows, D_, DFF_, 1, 1.f, 0, 0, 0);
        inorm1d<<<dim3(D_/32, B_), dim3(32, 8)>>>(pX, g2 + l*D_, be2 + l*D_, pXh, pXl, N_);
    }

    // append finish token into output X (+ hi/lo)
    write_xout<<<cdiv(B_*N1_*D_, 256), 256>>>(fin, outX);
    // decode K/V: [4004,512]x[1024,512]^T -> fp32
    gemm_hl<128,128,4,2><<<dim3(8, 32, 1), 256>>>(
        pXoh, pXol, D_, 0,0,
        pWkh, pWkl, D_, 0,0,
        pKV, 2*D_, 0,0,
        nullptr, nullptr, 0, 0,0,
        nullptr, 0, 0,0, nullptr,
        B_*N1_, 2*D_, D_, 1, 1.f, 0, 0, 0);
    write_kv<<<cdiv(H_*B_*N1_*HD_, 256), 256>>>(outK, outV);
}

// round 8
// speedup vs baseline: 2.3712x; 1.2152x over previous
#include <cuda_runtime.h>
#include <cuda_fp16.h>
#include <math.h>

// ---------------- problem constants ----------------
#define B_   4
#define NW_  100
#define NT_  800
#define N_   1000
#define N1_  1001
#define D_   512
#define H_   8
#define HD_  64
#define DFF_ 2048
#define L_   3
#define EPS_ 1e-5f
#define ALPHA_ 0.125f   // 1/sqrt(64)
#define NPAD_ 1024      // padded kv length for Vt

// ---------------- device scratch (no allocation allowed) ----------------
__device__ float  g_X   [B_*N_*D_];
__device__ float  g_KV  [B_*N1_*2*D_];
__device__ double g_esum[B_*5];
__device__ float  g_ec0[32], g_ec1[32], g_ec2[32];

__device__ __align__(16) __half g_Xh [B_*N_*D_];
__device__ __align__(16) __half g_Xl [B_*N_*D_];
__device__ __align__(16) __half g_QKVh[B_*N_*3*D_];
__device__ __align__(16) __half g_QKVl[B_*N_*3*D_];
__device__ __align__(16) __half g_Vth[B_*D_*NPAD_];
__device__ __align__(16) __half g_Vtl[B_*D_*NPAD_];
__device__ __align__(16) __half g_Oh [B_*N_*D_];
__device__ __align__(16) __half g_Ol [B_*N_*D_];
__device__ __align__(16) __half g_FFh[B_*N_*DFF_];
__device__ __align__(16) __half g_FFl[B_*N_*DFF_];
__device__ __align__(16) __half g_Wqkvh[L_*3*D_*D_];
__device__ __align__(16) __half g_Wqkvl[L_*3*D_*D_];
__device__ __align__(16) __half g_Woh[L_*D_*D_];
__device__ __align__(16) __half g_Wol[L_*D_*D_];
__device__ __align__(16) __half g_W1h[L_*DFF_*D_];
__device__ __align__(16) __half g_W1l[L_*DFF_*D_];
__device__ __align__(16) __half g_W2h[L_*D_*DFF_];
__device__ __align__(16) __half g_W2l[L_*D_*DFF_];
__device__ __align__(16) __half g_Wkvh[2*D_*D_];
__device__ __align__(16) __half g_Wkvl[2*D_*D_];
__device__ __align__(16) __half g_Xoh[B_*N1_*D_];
__device__ __align__(16) __half g_Xol[B_*N1_*D_];

__device__ __forceinline__ void splitf(float v, __half &h, __half &l) {
    h = __float2half_rn(v);
    l = __float2half_rn(v - __half2float(h));
}

__device__ __forceinline__ void cp16(unsigned dst, const void* src, bool p) {
    int sz = p ? 16 : 0;
    asm volatile("cp.async.ca.shared.global [%0], [%1], 16, %2;\n"
                 :: "r"(dst), "l"(src), "r"(sz));
}

#define LDSM4(r0,r1,r2,r3,a) \
    asm volatile("ldmatrix.sync.aligned.m8n8.x4.shared.b16 {%0,%1,%2,%3}, [%4];" \
                 : "=r"(r0),"=r"(r1),"=r"(r2),"=r"(r3) : "r"(a))

#define MMA16816(acc,a0,a1,a2,a3,b0,b1) \
    asm volatile("mma.sync.aligned.m16n8k16.row.col.f32.f16.f16.f32 " \
                 "{%0,%1,%2,%3}, {%4,%5,%6,%7}, {%8,%9}, {%0,%1,%2,%3};" \
                 : "+f"((acc)[0]), "+f"((acc)[1]), "+f"((acc)[2]), "+f"((acc)[3]) \
                 : "r"(a0), "r"(a1), "r"(a2), "r"(a3), "r"(b0), "r"(b1))

// ---------------- split-fp16 GEMM: precomputed hi/lo operands ----------------
template<int BM, int BN, int WARPS_M, int WARPS_N>
__global__ __launch_bounds__(WARPS_M*WARPS_N*32)
void gemm_hl(const __half* __restrict__ Ah, const __half* __restrict__ Al,
             int lda, long long sA1, long long sA0,
             const __half* __restrict__ Bh, const __half* __restrict__ Bl,
             int ldb, long long sB1, long long sB0,
             float* __restrict__ C, int ldc, long long sC1, long long sC0,
             __half* __restrict__ Ch, __half* __restrict__ Cl,
             int ldch, long long sCh1, long long sCh0,
             const float* __restrict__ addsrc, int ldadd, long long sD1, long long sD0,
             const float* __restrict__ bias,
             int M, int N, int K, int inner, float alpha,
             int relu, int qkv_mode)
{
    constexpr int BK = 16;
    constexpr int LDK = BK + 8;
    constexpr int THREADS = WARPS_M*WARPS_N*32;
    constexpr int WM = BM/WARPS_M, WN = BN/WARPS_N;
    constexpr int MT = WM/16, NT = WN/8;

    __shared__ __align__(16) __half As[2][2][BM][LDK];
    __shared__ __align__(16) __half Bs[2][2][BN][LDK];

    int z = blockIdx.z, z1 = z/inner, z0 = z%inner;
    Ah += z1*sA1 + z0*sA0;  Al += z1*sA1 + z0*sA0;
    Bh += z1*sB1 + z0*sB0;  Bl += z1*sB1 + z0*sB0;
    if (C)  C  += z1*sC1  + z0*sC0;
    if (Ch) { Ch += z1*sCh1 + z0*sCh0; Cl += z1*sCh1 + z0*sCh0; }

    int tid = threadIdx.x;
    int warp = tid>>5, lane = tid&31, g = lane>>2, tg = lane&3;
    int wm = (warp % WARPS_M)*WM, wn = (warp / WARPS_M)*WN;
    int row0 = blockIdx.y*BM, col0 = blockIdx.x*BN;

    const unsigned sAb = (unsigned)__cvta_generic_to_shared(&As[0][0][0][0]);
    const unsigned sBb = (unsigned)__cvta_generic_to_shared(&Bs[0][0][0][0]);

    float acc[MT][NT][4] = {};

    int aRow = (lane&7) + ((lane>>3)&1)*8;
    int aCol = ((lane>>4)&1)*8;
    int bRow = (lane&7) + ((lane>>4)&1)*8;
    int bCol = ((lane>>3)&1)*8;

    auto issue = [&](int kt, int buf) {
        {
            int row = tid>>1, ch = (tid&1)*8;
            bool p = (row0+row) < M;
            long long go = (long long)(row0+row)*lda + kt + ch;
            cp16(sAb + (unsigned)((((buf*2+0)*BM + row)*LDK + ch)*2), Ah + go, p);
            cp16(sAb + (unsigned)((((buf*2+1)*BM + row)*LDK + ch)*2), Al + go, p);
        }
        if (tid < BN*2) {
            int row = tid>>1, ch = (tid&1)*8;
            bool p = (col0+row) < N;
            long long go = (long long)(col0+row)*ldb + kt + ch;
            cp16(sBb + (unsigned)((((buf*2+0)*BN + row)*LDK + ch)*2), Bh + go, p);
            cp16(sBb + (unsigned)((((buf*2+1)*BN + row)*LDK + ch)*2), Bl + go, p);
        }
        asm volatile("cp.async.commit_group;");
    };

    auto compute = [&](int buf) {
        unsigned ah[MT][4], al[MT][4];
        #pragma unroll
        for (int mt = 0; mt < MT; mt++) {
            int r = wm + mt*16 + aRow;
            LDSM4(ah[mt][0], ah[mt][1], ah[mt][2], ah[mt][3],
                  sAb + (unsigned)((((buf*2+0)*BM + r)*LDK + aCol)*2));
            LDSM4(al[mt][0], al[mt][1], al[mt][2], al[mt][3],
                  sAb + (unsigned)((((buf*2+1)*BM + r)*LDK + aCol)*2));
        }
        #pragma unroll
        for (int nt2 = 0; nt2 < NT/2; nt2++) {
            int rB = wn + nt2*16 + bRow;
            unsigned bh0,bh1,bh2,bh3, bl0,bl1,bl2,bl3;
            LDSM4(bh0,bh1,bh2,bh3, sBb + (unsigned)((((buf*2+0)*BN + rB)*LDK + bCol)*2));
            LDSM4(bl0,bl1,bl2,bl3, sBb + (unsigned)((((buf*2+1)*BN + rB)*LDK + bCol)*2));
            #pragma unroll
            for (int mt = 0; mt < MT; mt++) {
                MMA16816(acc[mt][nt2*2], ah[mt][0],ah[mt][1],ah[mt][2],ah[mt][3], bh0,bh1);
                MMA16816(acc[mt][nt2*2], ah[mt][0],ah[mt][1],ah[mt][2],ah[mt][3], bl0,bl1);
                MMA16816(acc[mt][nt2*2], al[mt][0],al[mt][1],al[mt][2],al[mt][3], bh0,bh1);
            }
            #pragma unroll
            for (int mt = 0; mt < MT; mt++) {
                MMA16816(acc[mt][nt2*2+1], ah[mt][0],ah[mt][1],ah[mt][2],ah[mt][3], bh2,bh3);
                MMA16816(acc[mt][nt2*2+1], ah[mt][0],ah[mt][1],ah[mt][2],ah[mt][3], bl2,bl3);
                MMA16816(acc[mt][nt2*2+1], al[mt][0],al[mt][1],al[mt][2],al[mt][3], bh2,bh3);
            }
        }
    };

    issue(0, 0);
    int buf = 0;
    for (int kt = 0; kt < K; kt += BK) {
        asm volatile("cp.async.wait_group 0;");
        __syncthreads();
        if (kt + BK < K) issue(kt + BK, buf ^ 1);
        compute(buf);
        buf ^= 1;
        __syncthreads();
    }

    if (addsrc) addsrc += z1*sD1 + z0*sD0;

    #pragma unroll
    for (int mt = 0; mt < MT; mt++) {
        #pragma unroll
        for (int nt = 0; nt < NT; nt++) {
            int nb = col0 + wn + nt*8 + tg*2;
            #pragma unroll
            for (int h2 = 0; h2 < 2; h2++) {
                int m = row0 + wm + mt*16 + g + h2*8;
                if (m >= M) continue;
                #pragma unroll
                for (int j = 0; j < 2; j++) {
                    int n = nb + j;
                    if (n >= N) continue;
                    float v = alpha * acc[mt][nt][h2*2+j];
                    if (bias)   v += bias[n];
                    if (addsrc) v += addsrc[(long long)m*ldadd + n];
                    if (relu) v = fmaxf(v, 0.f);
                    if (C) C[(long long)m*ldc + n] = v;
                    if (Ch) {
                        __half hh, ll; splitf(v, hh, ll);
                        Ch[(long long)m*ldch + n] = hh;
                        Cl[(long long)m*ldch + n] = ll;
                        if (qkv_mode && n >= 1024) {
                            int b = m / N_, mm = m - b*N_;
                            long long vi = ((long long)b*D_ + (n-1024))*NPAD_ + mm;
                            g_Vth[vi] = hh; g_Vtl[vi] = ll;
                        }
                    }
                }
            }
        }
    }
}

// ---------------- flash attention: S=edge+aQK^T, softmax, O=PV fused --------
#define LDKQ 72
#define LDVV 136
#define FLASH_SMEM ((2*128*LDKQ + 2*64*LDVV)*2)

__global__ __launch_bounds__(256,1)
void flash_attn(const float* __restrict__ ef,
                const __half* __restrict__ QKVh, const __half* __restrict__ QKVl,
                const __half* __restrict__ Vth,  const __half* __restrict__ Vtl,
                __half* __restrict__ Oh, __half* __restrict__ Ol)
{
    extern __shared__ __half sm_[];
    __half* Kh = sm_;
    __half* Kl = sm_ + 128*LDKQ;
    __half* Vh = sm_ + 2*128*LDKQ;
    __half* Vl = Vh + 64*LDVV;

    const int qb = blockIdx.x;
    const int z  = blockIdx.y;
    const int h  = z / B_, b = z % B_;
    const int row0 = qb*128;
    const int tid = threadIdx.x, warp = tid>>5, lane = tid&31;
    const int g = lane>>2, tg = lane&3;
    const int aRow = (lane&7) + ((lane>>3)&1)*8;
    const int aCol = ((lane>>4)&1)*8;
    const int bRow = (lane&7) + ((lane>>4)&1)*8;
    const int bCol = ((lane>>3)&1)*8;

    const unsigned sKh = (unsigned)__cvta_generic_to_shared(Kh);
    const unsigned sKl = (unsigned)__cvta_generic_to_shared(Kl);
    const unsigned sVh = (unsigned)__cvta_generic_to_shared(Vh);
    const unsigned sVl = (unsigned)__cvta_generic_to_shared(Vl);

    // ---- stage Q tile through K buffer into registers ----
    #pragma unroll
    for (int i = 0; i < 4; i++) {
        int idx = tid + i*256;
        int r = idx >> 3, ch = (idx & 7)*8;
        int m = row0 + r;
        bool p = m < N_;
        long long go = (long long)(b*N_ + (p ? m : 0))*(3*D_) + h*HD_ + ch;
        cp16(sKh + (unsigned)((r*LDKQ + ch)*2), QKVh + go, p);
        cp16(sKl + (unsigned)((r*LDKQ + ch)*2), QKVl + go, p);
    }
    asm volatile("cp.async.commit_group;");
    asm volatile("cp.async.wait_group 0;");
    __syncthreads();

    unsigned qh[4][4], ql[4][4];
    #pragma unroll
    for (int ks = 0; ks < 4; ks++) {
        LDSM4(qh[ks][0],qh[ks][1],qh[ks][2],qh[ks][3],
              sKh + (unsigned)(((warp*16 + aRow)*LDKQ + ks*16 + aCol)*2));
        LDSM4(ql[ks][0],ql[ks][1],ql[ks][2],ql[ks][3],
              sKl + (unsigned)(((warp*16 + aRow)*LDKQ + ks*16 + aCol)*2));
    }
    __syncthreads();

    float oacc[8][4] = {};
    float rmax0 = -1e30f, rmax1 = -1e30f, rsum0 = 0.f, rsum1 = 0.f;
    const int te = b*H_ + h;
    const float ec0 = g_ec0[te], ec1 = g_ec1[te], ec2 = g_ec2[te];
    const float2* e2 = (const float2*)ef + (long long)b*N_*N_;
    const int r0g = row0 + warp*16 + g;
    const int r1g = r0g + 8;
    const long long er0 = (long long)(r0g < N_ ? r0g : N_-1) * N_;
    const long long er1 = (long long)(r1g < N_ ? r1g : N_-1) * N_;

    for (int kt = 0; kt < 8; kt++) {
        const int kv0 = kt*128;
        #pragma unroll
        for (int i = 0; i < 4; i++) {
            int idx = tid + i*256;
            int r = idx >> 3, ch = (idx & 7)*8;
            int kv = kv0 + r;
            bool p = kv < N_;
            long long go = (long long)(b*N_ + (p ? kv : 0))*(3*D_) + D_ + h*HD_ + ch;
            cp16(sKh + (unsigned)((r*LDKQ + ch)*2), QKVh + go, p);
            cp16(sKl + (unsigned)((r*LDKQ + ch)*2), QKVl + go, p);
        }
        #pragma unroll
        for (int i = 0; i < 4; i++) {
            int idx = tid + i*256;
            int r = idx >> 4, ch = (idx & 15)*8;
            long long go = (long long)(b*D_ + h*HD_ + r)*NPAD_ + kv0 + ch;
            cp16(sVh + (unsigned)((r*LDVV + ch)*2), Vth + go, true);
            cp16(sVl + (unsigned)((r*LDVV + ch)*2), Vtl + go, true);
        }
        asm volatile("cp.async.commit_group;");
        asm volatile("cp.async.wait_group 0;");
        __syncthreads();

        // S = Q @ K^T (split-fp16, fp32 acc)
        float s[16][4];
        #pragma unroll
        for (int i = 0; i < 16; i++) { s[i][0]=s[i][1]=s[i][2]=s[i][3]=0.f; }
        #pragma unroll
        for (int ks = 0; ks < 4; ks++) {
            #pragma unroll
            for (int nt2 = 0; nt2 < 8; nt2++) {
                unsigned bh0,bh1,bh2,bh3, bl0,bl1,bl2,bl3;
                LDSM4(bh0,bh1,bh2,bh3, sKh + (unsigned)(((nt2*16+bRow)*LDKQ + ks*16 + bCol)*2));
                LDSM4(bl0,bl1,bl2,bl3, sKl + (unsigned)(((nt2*16+bRow)*LDKQ + ks*16 + bCol)*2));
                MMA16816(s[nt2*2],   qh[ks][0],qh[ks][1],qh[ks][2],qh[ks][3], bh0,bh1);
                MMA16816(s[nt2*2],   qh[ks][0],qh[ks][1],qh[ks][2],qh[ks][3], bl0,bl1);
                MMA16816(s[nt2*2],   ql[ks][0],ql[ks][1],ql[ks][2],ql[ks][3], bh0,bh1);
                MMA16816(s[nt2*2+1], qh[ks][0],qh[ks][1],qh[ks][2],qh[ks][3], bh2,bh3);
                MMA16816(s[nt2*2+1], qh[ks][0],qh[ks][1],qh[ks][2],qh[ks][3], bl2,bl3);
                MMA16816(s[nt2*2+1], ql[ks][0],ql[ks][1],ql[ks][2],ql[ks][3], bh2,bh3);
            }
        }

        // edge bias + mask + online softmax
        float tm0 = -1e30f, tm1 = -1e30f;
        #pragma unroll
        for (int nt = 0; nt < 16; nt++) {
            int c = nt*8 + 2*tg;
            int n = kv0 + c;
            bool v0 = (n < N_), v1 = (n+1 < N_);
            long long ei0 = v0 ? n : (N_-1);
            long long ei1 = v1 ? (n+1) : (N_-1);
            float2 f00 = e2[er0 + ei0], f01 = e2[er0 + ei1];
            float2 f10 = e2[er1 + ei0], f11 = e2[er1 + ei1];
            s[nt][0] = v0 ? ALPHA_*s[nt][0] + f00.x*ec0 + f00.y*ec1 + ec2 : -1e30f;
            s[nt][1] = v1 ? ALPHA_*s[nt][1] + f01.x*ec0 + f01.y*ec1 + ec2 : -1e30f;
            s[nt][2] = v0 ? ALPHA_*s[nt][2] + f10.x*ec0 + f10.y*ec1 + ec2 : -1e30f;
            s[nt][3] = v1 ? ALPHA_*s[nt][3] + f11.x*ec0 + f11.y*ec1 + ec2 : -1e30f;
            tm0 = fmaxf(tm0, fmaxf(s[nt][0], s[nt][1]));
            tm1 = fmaxf(tm1, fmaxf(s[nt][2], s[nt][3]));
        }
        tm0 = fmaxf(tm0, __shfl_xor_sync(0xffffffffu, tm0, 1));
        tm0 = fmaxf(tm0, __shfl_xor_sync(0xffffffffu, tm0, 2));
        tm1 = fmaxf(tm1, __shfl_xor_sync(0xffffffffu, tm1, 1));
        tm1 = fmaxf(tm1, __shfl_xor_sync(0xffffffffu, tm1, 2));
        float nm0 = fmaxf(rmax0, tm0), nm1 = fmaxf(rmax1, tm1);
        float sc0 = __expf(rmax0 - nm0), sc1 = __expf(rmax1 - nm1);
        rmax0 = nm0; rmax1 = nm1;
        #pragma unroll
        for (int nt = 0; nt < 8; nt++) {
            oacc[nt][0]*=sc0; oacc[nt][1]*=sc0; oacc[nt][2]*=sc1; oacc[nt][3]*=sc1;
        }
        float ps0 = 0.f, ps1 = 0.f;
        #pragma unroll
        for (int nt = 0; nt < 16; nt++) {
            s[nt][0] = __expf(s[nt][0]-nm0); s[nt][1] = __expf(s[nt][1]-nm0);
            s[nt][2] = __expf(s[nt][2]-nm1); s[nt][3] = __expf(s[nt][3]-nm1);
            ps0 += s[nt][0]+s[nt][1]; ps1 += s[nt][2]+s[nt][3];
        }
        ps0 += __shfl_xor_sync(0xffffffffu, ps0, 1);
        ps0 += __shfl_xor_sync(0xffffffffu, ps0, 2);
        ps1 += __shfl_xor_sync(0xffffffffu, ps1, 1);
        ps1 += __shfl_xor_sync(0xffffffffu, ps1, 2);
        rsum0 = rsum0*sc0 + ps0;
        rsum1 = rsum1*sc1 + ps1;

        // O += P @ V  (P converted in-register to hi/lo A fragments)
        #pragma unroll
        for (int s8 = 0; s8 < 8; s8++) {
            unsigned pa[4], pb[4];
            #pragma unroll
            for (int j = 0; j < 2; j++) {
                float x0 = s[2*s8+j][0], x1 = s[2*s8+j][1];
                float x2 = s[2*s8+j][2], x3 = s[2*s8+j][3];
                __half2 h0 = __floats2half2_rn(x0, x1);
                __half2 h1 = __floats2half2_rn(x2, x3);
                float2 k0 = __half22float2(h0);
                float2 k1 = __half22float2(h1);
                __half2 l0 = __floats2half2_rn(x0-k0.x, x1-k0.y);
                __half2 l1 = __floats2half2_rn(x2-k1.x, x3-k1.y);
                pa[j*2+0] = *(unsigned*)&h0; pa[j*2+1] = *(unsigned*)&h1;
                pb[j*2+0] = *(unsigned*)&l0; pb[j*2+1] = *(unsigned*)&l1;
            }
            #pragma unroll
            for (int nt2 = 0; nt2 < 4; nt2++) {
                unsigned vh0,vh1,vh2,vh3, vl0,vl1,vl2,vl3;
                LDSM4(vh0,vh1,vh2,vh3, sVh + (unsigned)(((nt2*16+bRow)*LDVV + s8*16 + bCol)*2));
                LDSM4(vl0,vl1,vl2,vl3, sVl + (unsigned)(((nt2*16+bRow)*LDVV + s8*16 + bCol)*2));
                MMA16816(oacc[nt2*2],   pa[0],pa[1],pa[2],pa[3], vh0,vh1);
                MMA16816(oacc[nt2*2],   pa[0],pa[1],pa[2],pa[3], vl0,vl1);
                MMA16816(oacc[nt2*2],   pb[0],pb[1],pb[2],pb[3], vh0,vh1);
                MMA16816(oacc[nt2*2+1], pa[0],pa[1],pa[2],pa[3], vh2,vh3);
                MMA16816(oacc[nt2*2+1], pa[0],pa[1],pa[2],pa[3], vl2,vl3);
                MMA16816(oacc[nt2*2+1], pb[0],pb[1],pb[2],pb[3], vh2,vh3);
            }
        }
        __syncthreads();
    }

    float i0 = 1.f / rsum0, i1 = 1.f / rsum1;
    #pragma unroll
    for (int nt = 0; nt < 8; nt++) {
        int c = h*HD_ + nt*8 + 2*tg;
        if (r0g < N_) {
            float a = oacc[nt][0]*i0, bb = oacc[nt][1]*i0;
            __half2 hh = __floats2half2_rn(a, bb);
            float2 bk = __half22float2(hh);
            __half2 ll = __floats2half2_rn(a-bk.x, bb-bk.y);
            *(__half2*)&Oh[(long long)(b*N_+r0g)*D_ + c] = hh;
            *(__half2*)&Ol[(long long)(b*N_+r0g)*D_ + c] = ll;
        }
        if (r1g < N_) {
            float a = oacc[nt][2]*i1, bb = oacc[nt][3]*i1;
            __half2 hh = __floats2half2_rn(a, bb);
            float2 bk = __half22float2(hh);
            __half2 ll = __floats2half2_rn(a-bk.x, bb-bk.y);
            *(__half2*)&Oh[(long long)(b*N_+r1g)*D_ + c] = hh;
            *(__half2*)&Ol[(long long)(b*N_+r1g)*D_ + c] = ll;
        }
    }
}

// ---------------- InstanceNorm1d over item dim (fp32 in place + hi/lo out) ------
__global__ void inorm1d(float* __restrict__ X, const float* __restrict__ g,
                        const float* __restrict__ be,
                        __half* __restrict__ Xh, __half* __restrict__ Xl, int Nrows)
{
    int b = blockIdx.y;
    int c = blockIdx.x * 32 + threadIdx.x;
    int ty = threadIdx.y;
    long long base = (long long)b * Nrows * D_;
    float* Xb = X + base;
    float s = 0.f, q = 0.f;
    for (int n = ty; n < Nrows; n += 8) {
        float x = Xb[(long long)n * D_ + c];
        s += x; q += x * x;
    }
    __shared__ float sh_s[8][32], sh_q[8][32];
    sh_s[ty][threadIdx.x] = s; sh_q[ty][threadIdx.x] = q;
    __syncthreads();
    __shared__ float sh_m[32], sh_r[32];
    if (ty == 0) {
        float S = 0.f, Q = 0.f;
        #pragma unroll
        for (int i = 0; i < 8; i++) { S += sh_s[i][threadIdx.x]; Q += sh_q[i][threadIdx.x]; }
        float mean = S / (float)Nrows;
        float var  = Q / (float)Nrows - mean*mean;
        sh_m[threadIdx.x] = mean;
        sh_r[threadIdx.x] = rsqrtf(var + EPS_);
    }
    __syncthreads();
    float mean = sh_m[threadIdx.x], r = sh_r[threadIdx.x];
    float gg = g[c], bb = be[c];
    for (int n = ty; n < Nrows; n += 8) {
        long long idx = (long long)n * D_ + c;
        float v = gg * (Xb[idx] - mean) * r + bb;
        Xb[idx] = v;
        __half hh, ll; splitf(v, hh, ll);
        Xh[base + idx] = hh; Xl[base + idx] = ll;
    }
}

// ---------------- input projections + concat ----------------
__global__ void init_x(const float* __restrict__ wf, const float* __restrict__ tf,
                       const float* __restrict__ Wws, const float* __restrict__ bws,
                       const float* __restrict__ Wwe, const float* __restrict__ bwe,
                       const float* __restrict__ Wt,  const float* __restrict__ bt)
{
    int t = blockIdx.x * blockDim.x + threadIdx.x;
    if (t >= B_*N_*D_) return;
    int d = t & 511;
    int n = (t >> 9) % N_;
    int b = t / (D_*N_);
    float v;
    if (n < NW_) {
        const float* f = wf + (b*NW_ + n)*4;
        v = bws[d];
        #pragma unroll
        for (int k = 0; k < 4; k++) v += f[k] * Wws[k*D_ + d];
    } else if (n < 2*NW_) {
        const float* f = wf + (b*NW_ + (n - NW_))*4;
        v = bwe[d];
        #pragma unroll
        for (int k = 0; k < 4; k++) v += f[k] * Wwe[k*D_ + d];
    } else {
        const float* f = tf + (b*NT_ + (n - 2*NW_))*8;
        v = bt[d];
        #pragma unroll
        for (int k = 0; k < 8; k++) v += f[k] * Wt[k*D_ + d];
    }
    g_X[t] = v;
}

// ---------------- edge bias: analytic InstanceNorm2d coefficients ----------------
__global__ void zero_esum() { if (threadIdx.x < B_*5) g_esum[threadIdx.x] = 0.0; }

__global__ __launch_bounds__(256)
void edge_stats(const float* __restrict__ ef)
{
    int b = blockIdx.y;
    const float2* p = (const float2*)ef + (long long)b * (N_*N_);
    int stride = gridDim.x * blockDim.x;
    float s0=0,s1=0,s00=0,s11=0,s01=0;
    for (int i = blockIdx.x*blockDim.x + threadIdx.x; i < N_*N_; i += stride) {
        float2 f = p[i];
        s0 += f.x; s1 += f.y; s00 += f.x*f.x; s11 += f.y*f.y; s01 += f.x*f.y;
    }
    __shared__ double red[256];
    double loc[5] = {(double)s0,(double)s1,(double)s00,(double)s11,(double)s01};
    for (int j = 0; j < 5; j++) {
        red[threadIdx.x] = loc[j];
        __syncthreads();
        for (int s = 128; s > 0; s >>= 1) { if (threadIdx.x < s) red[threadIdx.x] += red[threadIdx.x+s]; __syncthreads(); }
        if (threadIdx.x == 0) atomicAdd(&g_esum[b*5+j], red[0]);
        __syncthreads();
    }
}

__global__ void edge_params(const float* __restrict__ We, const float* __restrict__ be,
                            const float* __restrict__ ge, const float* __restrict__ bee)
{
    int t = threadIdx.x;
    if (t >= B_*H_) return;
    int b = t / H_, h = t % H_;
    double cnt = (double)N_ * (double)N_;
    double m0  = g_esum[b*5+0]/cnt, m1 = g_esum[b*5+1]/cnt;
    double v00 = g_esum[b*5+2]/cnt - m0*m0;
    double v11 = g_esum[b*5+3]/cnt - m1*m1;
    double v01 = g_esum[b*5+4]/cnt - m0*m1;
    double w0 = We[0*H_+h], w1 = We[1*H_+h];
    double mean = w0*m0 + w1*m1 + (double)be[h];
    double var  = w0*w0*v00 + 2.0*w0*w1*v01 + w1*w1*v11;
    double grs  = (double)ge[h] / sqrt(var + (double)EPS_);
    g_ec0[t] = (float)(w0*grs);
    g_ec1[t] = (float)(w1*grs);
    g_ec2[t] = (float)(((double)be[h] - mean)*grs + (double)bee[h]);
}

// ---------------- weight packing (k-major hi/lo halves) ----------------
__global__ void pack_qkv(const float* __restrict__ Wq, const float* __restrict__ Wk,
                         const float* __restrict__ Wv)
{
    int t = blockIdx.x * blockDim.x + threadIdx.x;
    if (t >= L_*3*D_*D_) return;
    int k = t & 511;
    int n = (t >> 9) % (3*D_);
    int l = t / (3*D_*D_);
    int sec = n / D_, hn = n - sec*D_, h = hn >> 6, e = hn & 63;
    const float* W = (sec == 0) ? Wq : (sec == 1) ? Wk : Wv;
    float v = W[(((long long)l*H_ + h)*D_ + k)*HD_ + e];
    splitf(v, g_Wqkvh[t], g_Wqkvl[t]);
}

__global__ void pack_wo(const float* __restrict__ Wo)
{
    int t = blockIdx.x * blockDim.x + threadIdx.x;
    if (t >= L_*D_*D_) return;
    int k = t & 511, n = (t >> 9) & 511, l = t >> 18;
    float v = Wo[((long long)l*D_ + k)*D_ + n];
    splitf(v, g_Woh[t], g_Wol[t]);
}

__global__ void pack_w1(const float* __restrict__ W1)
{
    int t = blockIdx.x * blockDim.x + threadIdx.x;
    if (t >= L_*DFF_*D_) return;
    int k = t & 511;
    int n = (t >> 9) % DFF_;
    int l = t / (DFF_*D_);
    float v = W1[((long long)l*D_ + k)*DFF_ + n];
    splitf(v, g_W1h[t], g_W1l[t]);
}

__global__ void pack_w2(const float* __restrict__ W2)
{
    int t = blockIdx.x * blockDim.x + threadIdx.x;
    if (t >= L_*D_*DFF_) return;
    int k = t & 2047;
    int n = (t >> 11) & 511;
    int l = t / (D_*DFF_);
    float v = W2[((long long)l*DFF_ + k)*D_ + n];
    splitf(v, g_W2h[t], g_W2l[t]);
}

__global__ void pack_kvw(const float* __restrict__ Kd, const float* __restrict__ Vd)
{
    int t = blockIdx.x * blockDim.x + threadIdx.x;
    if (t >= 2*D_*D_) return;
    int k = t & 511, n = t >> 9;
    int sec = n >> 9, hn = n & 511, h = hn >> 6, e = hn & 63;
    const float* W = sec ? Vd : Kd;
    float v = W[((long long)h*D_ + k)*HD_ + e];
    splitf(v, g_Wkvh[t], g_Wkvl[t]);
}

__global__ void zero_vt_pad()
{
    int t = blockIdx.x * blockDim.x + threadIdx.x;
    if (t >= B_*D_*(NPAD_-N_)) return;
    int c = N_ + t % (NPAD_-N_);
    int r = t / (NPAD_-N_);
    __half z = __float2half(0.f);
    g_Vth[(long long)r*NPAD_ + c] = z;
    g_Vtl[(long long)r*NPAD_ + c] = z;
}

// ---------------- finish token append into output X (+ hi/lo) ----------------
__global__ void write_xout(const float* __restrict__ fin, float* __restrict__ out)
{
    int t = blockIdx.x * blockDim.x + threadIdx.x;
    if (t >= B_*N1_*D_) return;
    int d = t & 511;
    int n = (t >> 9) % N1_;
    int b = t / (N1_*D_);
    float v = (n < N_) ? g_X[((long long)b*N_ + n)*D_ + d] : fin[d];
    out[t] = v;
    splitf(v, g_Xoh[t], g_Xol[t]);
}

// ---------------- reorder decode K/V to [H][B][N1][HD] ----------------
__global__ void write_kv(float* __restrict__ outK, float* __restrict__ outV)
{
    int t = blockIdx.x * blockDim.x + threadIdx.x;
    if (t >= H_*B_*N1_*HD_) return;
    int e = t & 63;
    int n = (t >> 6) % N1_;
    int rem = t / (HD_*N1_);
    int b = rem & 3;
    int h = rem >> 2;
    long long src = ((long long)(b*N1_ + n))*(2*D_) + h*HD_ + e;
    outK[t] = g_KV[src];
    outV[t] = g_KV[src + D_];
}

// ---------------- host orchestration ----------------
static inline int cdiv(int a, int b) { return (a + b - 1) / b; }

extern "C" void kernel_launch(void* const* d_in, const int* in_sizes, int n_in,
                              void* d_out, int out_size)
{
    const float* wf   = (const float*)d_in[0];
    const float* tf   = (const float*)d_in[1];
    const float* ef   = (const float*)d_in[2];
    const float* Wws  = (const float*)d_in[3];
    const float* bws  = (const float*)d_in[4];
    const float* Wwe  = (const float*)d_in[5];
    const float* bwe  = (const float*)d_in[6];
    const float* Wt   = (const float*)d_in[7];
    const float* bt   = (const float*)d_in[8];
    const float* g_wt = (const float*)d_in[9];
    const float* be_wt= (const float*)d_in[10];
    const float* W_e  = (const float*)d_in[11];
    const float* b_e  = (const float*)d_in[12];
    const float* g_e  = (const float*)d_in[13];
    const float* be_e = (const float*)d_in[14];
    const float* Wq   = (const float*)d_in[15];
    const float* Wk   = (const float*)d_in[16];
    const float* Wv   = (const float*)d_in[17];
    const float* Wo   = (const float*)d_in[18];
    const float* W1   = (const float*)d_in[19];
    const float* b1   = (const float*)d_in[20];
    const float* W2   = (const float*)d_in[21];
    const float* b2   = (const float*)d_in[22];
    const float* g1   = (const float*)d_in[23];
    const float* be1  = (const float*)d_in[24];
    const float* g2   = (const float*)d_in[25];
    const float* be2  = (const float*)d_in[26];
    const float* fin  = (const float*)d_in[27];
    const float* Kd   = (const float*)d_in[28];
    const float* Vd   = (const float*)d_in[29];

    float* out  = (float*)d_out;
    float* outX = out;
    float* outK = out + (size_t)B_*N1_*D_;
    float* outV = outK + (size_t)H_*B_*N1_*HD_;

    float *pX, *pKV;
    __half *pXh,*pXl,*pQh,*pQl,*pVth,*pVtl,*pOhh,*pOll,*pFh,*pFl;
    __half *pWqh,*pWql,*pWoh,*pWol,*pW1h,*pW1l,*pW2h,*pW2l,*pWkh,*pWkl,*pXoh,*pXol;
    cudaGetSymbolAddress((void**)&pX,  g_X);
    cudaGetSymbolAddress((void**)&pKV, g_KV);
    cudaGetSymbolAddress((void**)&pXh, g_Xh);   cudaGetSymbolAddress((void**)&pXl, g_Xl);
    cudaGetSymbolAddress((void**)&pQh, g_QKVh); cudaGetSymbolAddress((void**)&pQl, g_QKVl);
    cudaGetSymbolAddress((void**)&pVth,g_Vth);  cudaGetSymbolAddress((void**)&pVtl,g_Vtl);
    cudaGetSymbolAddress((void**)&pOhh,g_Oh);   cudaGetSymbolAddress((void**)&pOll,g_Ol);
    cudaGetSymbolAddress((void**)&pFh, g_FFh);  cudaGetSymbolAddress((void**)&pFl, g_FFl);
    cudaGetSymbolAddress((void**)&pWqh,g_Wqkvh);cudaGetSymbolAddress((void**)&pWql,g_Wqkvl);
    cudaGetSymbolAddress((void**)&pWoh,g_Woh);  cudaGetSymbolAddress((void**)&pWol,g_Wol);
    cudaGetSymbolAddress((void**)&pW1h,g_W1h);  cudaGetSymbolAddress((void**)&pW1l,g_W1l);
    cudaGetSymbolAddress((void**)&pW2h,g_W2h);  cudaGetSymbolAddress((void**)&pW2l,g_W2l);
    cudaGetSymbolAddress((void**)&pWkh,g_Wkvh); cudaGetSymbolAddress((void**)&pWkl,g_Wkvl);
    cudaGetSymbolAddress((void**)&pXoh,g_Xoh);  cudaGetSymbolAddress((void**)&pXol,g_Xol);

    cudaFuncSetAttribute(flash_attn, cudaFuncAttributeMaxDynamicSharedMemorySize, FLASH_SMEM);

    // ---- setup ----
    zero_esum<<<1, 32>>>();
    edge_stats<<<dim3(32, B_), 256>>>(ef);
    edge_params<<<1, 32>>>(W_e, b_e, g_e, be_e);
    pack_qkv<<<cdiv(L_*3*D_*D_, 256), 256>>>(Wq, Wk, Wv);
    pack_wo <<<cdiv(L_*D_*D_, 256), 256>>>(Wo);
    pack_w1 <<<cdiv(L_*DFF_*D_, 256), 256>>>(W1);
    pack_w2 <<<cdiv(L_*D_*DFF_, 256), 256>>>(W2);
    pack_kvw<<<cdiv(2*D_*D_, 256), 256>>>(Kd, Vd);
    zero_vt_pad<<<cdiv(B_*D_*(NPAD_-N_), 256), 256>>>();
    init_x<<<cdiv(B_*N_*D_, 256), 256>>>(wf, tf, Wws, bws, Wwe, bwe, Wt, bt);
    inorm1d<<<dim3(D_/32, B_), dim3(32, 8)>>>(pX, g_wt, be_wt, pXh, pXl, N_);

    const int Mrows = B_*N_;   // 4000

    for (int l = 0; l < L_; l++) {
        long long wq = (long long)l*3*D_*D_;
        // QKV: hi/lo halves + Vt scatter
        gemm_hl<128,128,4,2><<<dim3(12, 32, 1), 256>>>(
            pXh, pXl, D_, 0,0,
            pWqh + wq, pWql + wq, D_, 0,0,
            nullptr, 0, 0,0,
            pQh, pQl, 3*D_, 0,0,
            nullptr, 0, 0,0, nullptr,
            Mrows, 3*D_, D_, 1, 1.f, 0, 1);
        // fused attention: edge bias + softmax + PV
        flash_attn<<<dim3(8, H_*B_), 256, FLASH_SMEM>>>(
            ef, pQh, pQl, pVth, pVtl, pOhh, pOll);
        // X = X + O @ Wo
        long long wo = (long long)l*D_*D_;
        gemm_hl<128,128,4,2><<<dim3(4, 32, 1), 256>>>(
            pOhh, pOll, D_, 0,0,
            pWoh + wo, pWol + wo, D_, 0,0,
            pX, D_, 0,0,
            nullptr, nullptr, 0, 0,0,
            pX, D_, 0,0, nullptr,
            Mrows, D_, D_, 1, 1.f, 0, 0);
        inorm1d<<<dim3(D_/32, B_), dim3(32, 8)>>>(pX, g1 + l*D_, be1 + l*D_, pXh, pXl, N_);
        // FF = relu(X @ W1 + b1)
        long long w1o = (long long)l*DFF_*D_;
        gemm_hl<128,128,4,2><<<dim3(16, 32, 1), 256>>>(
            pXh, pXl, D_, 0,0,
            pW1h + w1o, pW1l + w1o, D_, 0,0,
            nullptr, 0, 0,0,
            pFh, pFl, DFF_, 0,0,
            nullptr, 0, 0,0, b1 + l*DFF_,
            Mrows, DFF_, D_, 1, 1.f, 1, 0);
        // X = X + FF @ W2 + b2
        long long w2o = (long long)l*D_*DFF_;
        gemm_hl<128,128,4,2><<<dim3(4, 32, 1), 256>>>(
            pFh, pFl, DFF_, 0,0,
            pW2h + w2o, pW2l + w2o, DFF_, 0,0,
            pX, D_, 0,0,
            nullptr, nullptr, 0, 0,0,
            pX, D_, 0,0, b2 + l*D_,
            Mrows, D_, DFF_, 1, 1.f, 0, 0);
        inorm1d<<<dim3(D_/32, B_), dim3(32, 8)>>>(pX, g2 + l*D_, be2 + l*D_, pXh, pXl, N_);
    }

    write_xout<<<cdiv(B_*N1_*D_, 256), 256>>>(fin, outX);
    gemm_hl<128,128,4,2><<<dim3(8, 32, 1), 256>>>(
        pXoh, pXol, D_, 0,0,
        pWkh, pWkl, D_, 0,0,
        pKV, 2*D_, 0,0,
        nullptr, nullptr, 0, 0,0,
        nullptr, 0, 0,0, nullptr,
        B_*N1_, 2*D_, D_, 1, 1.f, 0, 0);
    write_kv<<<cdiv(H_*B_*N1_*HD_, 256), 256>>>(outK, outV);
}

// round 10
// speedup vs baseline: 2.4333x; 1.0262x over previous
#include <cuda_runtime.h>
#include <cuda_fp16.h>
#include <math.h>

// ---------------- problem constants ----------------
#define B_   4
#define NW_  100
#define NT_  800
#define N_   1000
#define N1_  1001
#define D_   512
#define H_   8
#define HD_  64
#define DFF_ 2048
#define L_   3
#define EPS_ 1e-5f
#define ALPHA_ 0.125f   // 1/sqrt(64)
#define NPAD_ 1024      // padded kv length for Vt

// ---------------- device scratch (no allocation allowed) ----------------
__device__ float  g_X   [B_*N_*D_];
__device__ float  g_KV  [B_*N1_*2*D_];
__device__ double g_esum[B_*5];
__device__ float  g_ec0[32], g_ec1[32], g_ec2[32];

__device__ __align__(16) __half g_Xh [B_*N_*D_];
__device__ __align__(16) __half g_Xl [B_*N_*D_];
__device__ __align__(16) __half g_QKVh[B_*N_*3*D_];
__device__ __align__(16) __half g_QKVl[B_*N_*3*D_];
__device__ __align__(16) __half g_Vth[B_*D_*NPAD_];
__device__ __align__(16) __half g_Vtl[B_*D_*NPAD_];
__device__ __align__(16) __half g_Oh [B_*N_*D_];
__device__ __align__(16) __half g_Ol [B_*N_*D_];
__device__ __align__(16) __half g_FFh[B_*N_*DFF_];
__device__ __align__(16) __half g_FFl[B_*N_*DFF_];
__device__ __align__(16) __half g_Wqkvh[L_*3*D_*D_];
__device__ __align__(16) __half g_Wqkvl[L_*3*D_*D_];
__device__ __align__(16) __half g_Woh[L_*D_*D_];
__device__ __align__(16) __half g_Wol[L_*D_*D_];
__device__ __align__(16) __half g_W1h[L_*DFF_*D_];
__device__ __align__(16) __half g_W1l[L_*DFF_*D_];
__device__ __align__(16) __half g_W2h[L_*D_*DFF_];
__device__ __align__(16) __half g_W2l[L_*D_*DFF_];
__device__ __align__(16) __half g_Wkvh[2*D_*D_];
__device__ __align__(16) __half g_Wkvl[2*D_*D_];
__device__ __align__(16) __half g_Xoh[B_*N1_*D_];
__device__ __align__(16) __half g_Xol[B_*N1_*D_];

__device__ __forceinline__ void splitf(float v, __half &h, __half &l) {
    h = __float2half_rn(v);
    l = __float2half_rn(v - __half2float(h));
}

__device__ __forceinline__ void cp16(unsigned dst, const void* src, bool p) {
    int sz = p ? 16 : 0;
    asm volatile("cp.async.ca.shared.global [%0], [%1], 16, %2;\n"
                 :: "r"(dst), "l"(src), "r"(sz));
}

#define LDSM4(r0,r1,r2,r3,a) \
    asm volatile("ldmatrix.sync.aligned.m8n8.x4.shared.b16 {%0,%1,%2,%3}, [%4];" \
                 : "=r"(r0),"=r"(r1),"=r"(r2),"=r"(r3) : "r"(a))

#define MMA16816(acc,a0,a1,a2,a3,b0,b1) \
    asm volatile("mma.sync.aligned.m16n8k16.row.col.f32.f16.f16.f32 " \
                 "{%0,%1,%2,%3}, {%4,%5,%6,%7}, {%8,%9}, {%0,%1,%2,%3};" \
                 : "+f"((acc)[0]), "+f"((acc)[1]), "+f"((acc)[2]), "+f"((acc)[3]) \
                 : "r"(a0), "r"(a1), "r"(a2), "r"(a3), "r"(b0), "r"(b1))

// ---------------- split-fp16 GEMM: 3-stage cp.async pipeline ----------------
#define GSTAGES 3
#define GEMM_SMEM (GSTAGES*(2*128*24 + 2*128*24)*2)

template<int BM, int BN, int WARPS_M, int WARPS_N>
__global__ __launch_bounds__(WARPS_M*WARPS_N*32)
void gemm_hl(const __half* __restrict__ Ah, const __half* __restrict__ Al,
             int lda, long long sA1, long long sA0,
             const __half* __restrict__ Bh, const __half* __restrict__ Bl,
             int ldb, long long sB1, long long sB0,
             float* __restrict__ C, int ldc, long long sC1, long long sC0,
             __half* __restrict__ Ch, __half* __restrict__ Cl,
             int ldch, long long sCh1, long long sCh0,
             const float* __restrict__ addsrc, int ldadd, long long sD1, long long sD0,
             const float* __restrict__ bias,
             int M, int N, int K, int inner, float alpha,
             int relu, int qkv_mode)
{
    constexpr int BK = 16;
    constexpr int LDK = BK + 8;
    constexpr int WM = BM/WARPS_M, WN = BN/WARPS_N;
    constexpr int MT = WM/16, NT = WN/8;

    extern __shared__ __half sm_g[];
    __half* As = sm_g;                          // [S][2][BM][LDK]
    __half* Bs = sm_g + GSTAGES*2*BM*LDK;       // [S][2][BN][LDK]

    int z = blockIdx.z, z1 = z/inner, z0 = z%inner;
    Ah += z1*sA1 + z0*sA0;  Al += z1*sA1 + z0*sA0;
    Bh += z1*sB1 + z0*sB0;  Bl += z1*sB1 + z0*sB0;
    if (C)  C  += z1*sC1  + z0*sC0;
    if (Ch) { Ch += z1*sCh1 + z0*sCh0; Cl += z1*sCh1 + z0*sCh0; }

    int tid = threadIdx.x;
    int warp = tid>>5, lane = tid&31, g = lane>>2, tg = lane&3;
    int wm = (warp % WARPS_M)*WM, wn = (warp / WARPS_M)*WN;
    int row0 = blockIdx.y*BM, col0 = blockIdx.x*BN;

    const unsigned sAb = (unsigned)__cvta_generic_to_shared(As);
    const unsigned sBb = (unsigned)__cvta_generic_to_shared(Bs);

    float acc[MT][NT][4] = {};

    int aRow = (lane&7) + ((lane>>3)&1)*8;
    int aCol = ((lane>>4)&1)*8;
    int bRow = (lane&7) + ((lane>>4)&1)*8;
    int bCol = ((lane>>3)&1)*8;

    auto issue = [&](int kt, int s) {
        {
            int row = tid>>1, ch = (tid&1)*8;
            bool p = (row0+row) < M;
            long long go = (long long)(row0+row)*lda + kt + ch;
            cp16(sAb + (unsigned)((((s*2+0)*BM + row)*LDK + ch)*2), Ah + go, p);
            cp16(sAb + (unsigned)((((s*2+1)*BM + row)*LDK + ch)*2), Al + go, p);
        }
        if (tid < BN*2) {
            int row = tid>>1, ch = (tid&1)*8;
            bool p = (col0+row) < N;
            long long go = (long long)(col0+row)*ldb + kt + ch;
            cp16(sBb + (unsigned)((((s*2+0)*BN + row)*LDK + ch)*2), Bh + go, p);
            cp16(sBb + (unsigned)((((s*2+1)*BN + row)*LDK + ch)*2), Bl + go, p);
        }
        asm volatile("cp.async.commit_group;");
    };

    auto compute = [&](int s) {
        unsigned ah[MT][4], al[MT][4];
        #pragma unroll
        for (int mt = 0; mt < MT; mt++) {
            int r = wm + mt*16 + aRow;
            LDSM4(ah[mt][0], ah[mt][1], ah[mt][2], ah[mt][3],
                  sAb + (unsigned)((((s*2+0)*BM + r)*LDK + aCol)*2));
            LDSM4(al[mt][0], al[mt][1], al[mt][2], al[mt][3],
                  sAb + (unsigned)((((s*2+1)*BM + r)*LDK + aCol)*2));
        }
        #pragma unroll
        for (int nt2 = 0; nt2 < NT/2; nt2++) {
            int rB = wn + nt2*16 + bRow;
            unsigned bh0,bh1,bh2,bh3, bl0,bl1,bl2,bl3;
            LDSM4(bh0,bh1,bh2,bh3, sBb + (unsigned)((((s*2+0)*BN + rB)*LDK + bCol)*2));
            LDSM4(bl0,bl1,bl2,bl3, sBb + (unsigned)((((s*2+1)*BN + rB)*LDK + bCol)*2));
            #pragma unroll
            for (int mt = 0; mt < MT; mt++) {
                MMA16816(acc[mt][nt2*2], ah[mt][0],ah[mt][1],ah[mt][2],ah[mt][3], bh0,bh1);
                MMA16816(acc[mt][nt2*2], ah[mt][0],ah[mt][1],ah[mt][2],ah[mt][3], bl0,bl1);
                MMA16816(acc[mt][nt2*2], al[mt][0],al[mt][1],al[mt][2],al[mt][3], bh0,bh1);
            }
            #pragma unroll
            for (int mt = 0; mt < MT; mt++) {
                MMA16816(acc[mt][nt2*2+1], ah[mt][0],ah[mt][1],ah[mt][2],ah[mt][3], bh2,bh3);
                MMA16816(acc[mt][nt2*2+1], ah[mt][0],ah[mt][1],ah[mt][2],ah[mt][3], bl2,bl3);
                MMA16816(acc[mt][nt2*2+1], al[mt][0],al[mt][1],al[mt][2],al[mt][3], bh2,bh3);
            }
        }
    };

    const int T = K / BK;
    issue(0, 0);
    if (T > 1) issue(BK, 1);
    for (int i = 0; i < T; i++) {
        if (i + 1 < T) { asm volatile("cp.async.wait_group 1;"); }
        else           { asm volatile("cp.async.wait_group 0;"); }
        __syncthreads();
        if (i + 2 < T) issue((i+2)*BK, (i+2)%GSTAGES);
        compute(i % GSTAGES);
    }

    if (addsrc) addsrc += z1*sD1 + z0*sD0;

    #pragma unroll
    for (int mt = 0; mt < MT; mt++) {
        #pragma unroll
        for (int nt = 0; nt < NT; nt++) {
            int nb = col0 + wn + nt*8 + tg*2;
            #pragma unroll
            for (int h2 = 0; h2 < 2; h2++) {
                int m = row0 + wm + mt*16 + g + h2*8;
                if (m >= M) continue;
                #pragma unroll
                for (int j = 0; j < 2; j++) {
                    int n = nb + j;
                    if (n >= N) continue;
                    float v = alpha * acc[mt][nt][h2*2+j];
                    if (bias)   v += bias[n];
                    if (addsrc) v += addsrc[(long long)m*ldadd + n];
                    if (relu) v = fmaxf(v, 0.f);
                    if (C) C[(long long)m*ldc + n] = v;
                    if (Ch) {
                        __half hh, ll; splitf(v, hh, ll);
                        Ch[(long long)m*ldch + n] = hh;
                        Cl[(long long)m*ldch + n] = ll;
                        if (qkv_mode && n >= 1024) {
                            int b = m / N_, mm = m - b*N_;
                            long long vi = ((long long)b*D_ + (n-1024))*NPAD_ + mm;
                            g_Vth[vi] = hh; g_Vtl[vi] = ll;
                        }
                    }
                }
            }
        }
    }
}

// ---------------- flash attention (double-buffered KV) ----------------
#define LDKQ 72
#define LDVV 136
#define FBUF (2*128*LDKQ + 2*64*LDVV)            // halves per buffer
#define FLASH_SMEM (2*FBUF*2)                    // bytes, 2 buffers

__global__ __launch_bounds__(256,1)
void flash_attn(const float* __restrict__ ef,
                const __half* __restrict__ QKVh, const __half* __restrict__ QKVl,
                const __half* __restrict__ Vth,  const __half* __restrict__ Vtl,
                __half* __restrict__ Oh, __half* __restrict__ Ol)
{
    extern __shared__ __half sm_[];

    const int qb = blockIdx.x;
    const int z  = blockIdx.y;
    const int h  = z / B_, b = z % B_;
    const int row0 = qb*128;
    const int tid = threadIdx.x, warp = tid>>5, lane = tid&31;
    const int g = lane>>2, tg = lane&3;
    const int aRow = (lane&7) + ((lane>>3)&1)*8;
    const int aCol = ((lane>>4)&1)*8;
    const int bRow = (lane&7) + ((lane>>4)&1)*8;
    const int bCol = ((lane>>3)&1)*8;

    const unsigned sBase = (unsigned)__cvta_generic_to_shared(sm_);
    auto sKh = [&](int bf){ return sBase + (unsigned)(bf*FBUF*2); };
    auto sKl = [&](int bf){ return sBase + (unsigned)((bf*FBUF + 128*LDKQ)*2); };
    auto sVh = [&](int bf){ return sBase + (unsigned)((bf*FBUF + 2*128*LDKQ)*2); };
    auto sVl = [&](int bf){ return sBase + (unsigned)((bf*FBUF + 2*128*LDKQ + 64*LDVV)*2); };

    // ---- stage Q tile through buffer-0 K region into registers ----
    #pragma unroll
    for (int i = 0; i < 4; i++) {
        int idx = tid + i*256;
        int r = idx >> 3, ch = (idx & 7)*8;
        int m = row0 + r;
        bool p = m < N_;
        long long go = (long long)(b*N_ + (p ? m : 0))*(3*D_) + h*HD_ + ch;
        cp16(sKh(0) + (unsigned)((r*LDKQ + ch)*2), QKVh + go, p);
        cp16(sKl(0) + (unsigned)((r*LDKQ + ch)*2), QKVl + go, p);
    }
    asm volatile("cp.async.commit_group;");
    asm volatile("cp.async.wait_group 0;");
    __syncthreads();

    unsigned qh[4][4], ql[4][4];
    #pragma unroll
    for (int ks = 0; ks < 4; ks++) {
        LDSM4(qh[ks][0],qh[ks][1],qh[ks][2],qh[ks][3],
              sKh(0) + (unsigned)(((warp*16 + aRow)*LDKQ + ks*16 + aCol)*2));
        LDSM4(ql[ks][0],ql[ks][1],ql[ks][2],ql[ks][3],
              sKl(0) + (unsigned)(((warp*16 + aRow)*LDKQ + ks*16 + aCol)*2));
    }
    __syncthreads();

    auto issue_kv = [&](int kt, int bf) {
        const int kv0 = kt*128;
        #pragma unroll
        for (int i = 0; i < 4; i++) {
            int idx = tid + i*256;
            int r = idx >> 3, ch = (idx & 7)*8;
            int kv = kv0 + r;
            bool p = kv < N_;
            long long go = (long long)(b*N_ + (p ? kv : 0))*(3*D_) + D_ + h*HD_ + ch;
            cp16(sKh(bf) + (unsigned)((r*LDKQ + ch)*2), QKVh + go, p);
            cp16(sKl(bf) + (unsigned)((r*LDKQ + ch)*2), QKVl + go, p);
        }
        #pragma unroll
        for (int i = 0; i < 4; i++) {
            int idx = tid + i*256;
            int r = idx >> 4, ch = (idx & 15)*8;
            long long go = (long long)(b*D_ + h*HD_ + r)*NPAD_ + kv0 + ch;
            cp16(sVh(bf) + (unsigned)((r*LDVV + ch)*2), Vth + go, true);
            cp16(sVl(bf) + (unsigned)((r*LDVV + ch)*2), Vtl + go, true);
        }
        asm volatile("cp.async.commit_group;");
    };

    float oacc[8][4] = {};
    float rmax0 = -1e30f, rmax1 = -1e30f, rsum0 = 0.f, rsum1 = 0.f;
    const int te = b*H_ + h;
    const float ec0 = g_ec0[te], ec1 = g_ec1[te], ec2 = g_ec2[te];
    const float2* e2 = (const float2*)ef + (long long)b*N_*N_;
    const int r0g = row0 + warp*16 + g;
    const int r1g = r0g + 8;
    const long long er0 = (long long)(r0g < N_ ? r0g : N_-1) * N_;
    const long long er1 = (long long)(r1g < N_ ? r1g : N_-1) * N_;

    issue_kv(0, 0);
    issue_kv(1, 1);

    for (int kt = 0; kt < 8; kt++) {
        const int kv0 = kt*128;
        const int bf = kt & 1;
        if (kt < 7) { asm volatile("cp.async.wait_group 1;"); }
        else        { asm volatile("cp.async.wait_group 0;"); }
        __syncthreads();

        // S = Q @ K^T (split-fp16, fp32 acc)
        float s[16][4];
        #pragma unroll
        for (int i = 0; i < 16; i++) { s[i][0]=s[i][1]=s[i][2]=s[i][3]=0.f; }
        #pragma unroll
        for (int ks = 0; ks < 4; ks++) {
            #pragma unroll
            for (int nt2 = 0; nt2 < 8; nt2++) {
                unsigned bh0,bh1,bh2,bh3, bl0,bl1,bl2,bl3;
                LDSM4(bh0,bh1,bh2,bh3, sKh(bf) + (unsigned)(((nt2*16+bRow)*LDKQ + ks*16 + bCol)*2));
                LDSM4(bl0,bl1,bl2,bl3, sKl(bf) + (unsigned)(((nt2*16+bRow)*LDKQ + ks*16 + bCol)*2));
                MMA16816(s[nt2*2],   qh[ks][0],qh[ks][1],qh[ks][2],qh[ks][3], bh0,bh1);
                MMA16816(s[nt2*2],   qh[ks][0],qh[ks][1],qh[ks][2],qh[ks][3], bl0,bl1);
                MMA16816(s[nt2*2],   ql[ks][0],ql[ks][1],ql[ks][2],ql[ks][3], bh0,bh1);
                MMA16816(s[nt2*2+1], qh[ks][0],qh[ks][1],qh[ks][2],qh[ks][3], bh2,bh3);
                MMA16816(s[nt2*2+1], qh[ks][0],qh[ks][1],qh[ks][2],qh[ks][3], bl2,bl3);
                MMA16816(s[nt2*2+1], ql[ks][0],ql[ks][1],ql[ks][2],ql[ks][3], bh2,bh3);
            }
        }

        // edge bias + mask + online softmax
        float tm0 = -1e30f, tm1 = -1e30f;
        #pragma unroll
        for (int nt = 0; nt < 16; nt++) {
            int c = nt*8 + 2*tg;
            int n = kv0 + c;
            bool v0 = (n < N_), v1 = (n+1 < N_);
            long long ei0 = v0 ? n : (N_-1);
            long long ei1 = v1 ? (n+1) : (N_-1);
            float2 f00 = e2[er0 + ei0], f01 = e2[er0 + ei1];
            float2 f10 = e2[er1 + ei0], f11 = e2[er1 + ei1];
            s[nt][0] = v0 ? ALPHA_*s[nt][0] + f00.x*ec0 + f00.y*ec1 + ec2 : -1e30f;
            s[nt][1] = v1 ? ALPHA_*s[nt][1] + f01.x*ec0 + f01.y*ec1 + ec2 : -1e30f;
            s[nt][2] = v0 ? ALPHA_*s[nt][2] + f10.x*ec0 + f10.y*ec1 + ec2 : -1e30f;
            s[nt][3] = v1 ? ALPHA_*s[nt][3] + f11.x*ec0 + f11.y*ec1 + ec2 : -1e30f;
            tm0 = fmaxf(tm0, fmaxf(s[nt][0], s[nt][1]));
            tm1 = fmaxf(tm1, fmaxf(s[nt][2], s[nt][3]));
        }
        tm0 = fmaxf(tm0, __shfl_xor_sync(0xffffffffu, tm0, 1));
        tm0 = fmaxf(tm0, __shfl_xor_sync(0xffffffffu, tm0, 2));
        tm1 = fmaxf(tm1, __shfl_xor_sync(0xffffffffu, tm1, 1));
        tm1 = fmaxf(tm1, __shfl_xor_sync(0xffffffffu, tm1, 2));
        float nm0 = fmaxf(rmax0, tm0), nm1 = fmaxf(rmax1, tm1);
        float sc0 = __expf(rmax0 - nm0), sc1 = __expf(rmax1 - nm1);
        rmax0 = nm0; rmax1 = nm1;
        #pragma unroll
        for (int nt = 0; nt < 8; nt++) {
            oacc[nt][0]*=sc0; oacc[nt][1]*=sc0; oacc[nt][2]*=sc1; oacc[nt][3]*=sc1;
        }
        float ps0 = 0.f, ps1 = 0.f;
        #pragma unroll
        for (int nt = 0; nt < 16; nt++) {
            s[nt][0] = __expf(s[nt][0]-nm0); s[nt][1] = __expf(s[nt][1]-nm0);
            s[nt][2] = __expf(s[nt][2]-nm1); s[nt][3] = __expf(s[nt][3]-nm1);
            ps0 += s[nt][0]+s[nt][1]; ps1 += s[nt][2]+s[nt][3];
        }
        ps0 += __shfl_xor_sync(0xffffffffu, ps0, 1);
        ps0 += __shfl_xor_sync(0xffffffffu, ps0, 2);
        ps1 += __shfl_xor_sync(0xffffffffu, ps1, 1);
        ps1 += __shfl_xor_sync(0xffffffffu, ps1, 2);
        rsum0 = rsum0*sc0 + ps0;
        rsum1 = rsum1*sc1 + ps1;

        // O += P @ V  (P converted in-register to hi/lo A fragments)
        #pragma unroll
        for (int s8 = 0; s8 < 8; s8++) {
            unsigned pa[4], pb[4];
            #pragma unroll
            for (int j = 0; j < 2; j++) {
                float x0 = s[2*s8+j][0], x1 = s[2*s8+j][1];
                float x2 = s[2*s8+j][2], x3 = s[2*s8+j][3];
                __half2 h0 = __floats2half2_rn(x0, x1);
                __half2 h1 = __floats2half2_rn(x2, x3);
                float2 k0 = __half22float2(h0);
                float2 k1 = __half22float2(h1);
                __half2 l0 = __floats2half2_rn(x0-k0.x, x1-k0.y);
                __half2 l1 = __floats2half2_rn(x2-k1.x, x3-k1.y);
                pa[j*2+0] = *(unsigned*)&h0; pa[j*2+1] = *(unsigned*)&h1;
                pb[j*2+0] = *(unsigned*)&l0; pb[j*2+1] = *(unsigned*)&l1;
            }
            #pragma unroll
            for (int nt2 = 0; nt2 < 4; nt2++) {
                unsigned vh0,vh1,vh2,vh3, vl0,vl1,vl2,vl3;
                LDSM4(vh0,vh1,vh2,vh3, sVh(bf) + (unsigned)(((nt2*16+bRow)*LDVV + s8*16 + bCol)*2));
                LDSM4(vl0,vl1,vl2,vl3, sVl(bf) + (unsigned)(((nt2*16+bRow)*LDVV + s8*16 + bCol)*2));
                MMA16816(oacc[nt2*2],   pa[0],pa[1],pa[2],pa[3], vh0,vh1);
                MMA16816(oacc[nt2*2],   pa[0],pa[1],pa[2],pa[3], vl0,vl1);
                MMA16816(oacc[nt2*2],   pb[0],pb[1],pb[2],pb[3], vh0,vh1);
                MMA16816(oacc[nt2*2+1], pa[0],pa[1],pa[2],pa[3], vh2,vh3);
                MMA16816(oacc[nt2*2+1], pa[0],pa[1],pa[2],pa[3], vl2,vl3);
                MMA16816(oacc[nt2*2+1], pb[0],pb[1],pb[2],pb[3], vh2,vh3);
            }
        }
        __syncthreads();
        if (kt + 2 < 8) issue_kv(kt + 2, bf);
    }

    float i0 = 1.f / rsum0, i1 = 1.f / rsum1;
    #pragma unroll
    for (int nt = 0; nt < 8; nt++) {
        int c = h*HD_ + nt*8 + 2*tg;
        if (r0g < N_) {
            float a = oacc[nt][0]*i0, bb = oacc[nt][1]*i0;
            __half2 hh = __floats2half2_rn(a, bb);
            float2 bk = __half22float2(hh);
            __half2 ll = __floats2half2_rn(a-bk.x, bb-bk.y);
            *(__half2*)&Oh[(long long)(b*N_+r0g)*D_ + c] = hh;
            *(__half2*)&Ol[(long long)(b*N_+r0g)*D_ + c] = ll;
        }
        if (r1g < N_) {
            float a = oacc[nt][2]*i1, bb = oacc[nt][3]*i1;
            __half2 hh = __floats2half2_rn(a, bb);
            float2 bk = __half22float2(hh);
            __half2 ll = __floats2half2_rn(a-bk.x, bb-bk.y);
            *(__half2*)&Oh[(long long)(b*N_+r1g)*D_ + c] = hh;
            *(__half2*)&Ol[(long long)(b*N_+r1g)*D_ + c] = ll;
        }
    }
}

// ---------------- InstanceNorm1d over item dim (fp32 in place + hi/lo out) ------
__global__ void inorm1d(float* __restrict__ X, const float* __restrict__ g,
                        const float* __restrict__ be,
                        __half* __restrict__ Xh, __half* __restrict__ Xl, int Nrows)
{
    int b = blockIdx.y;
    int c = blockIdx.x * 32 + threadIdx.x;
    int ty = threadIdx.y;
    long long base = (long long)b * Nrows * D_;
    float* Xb = X + base;
    float s = 0.f, q = 0.f;
    for (int n = ty; n < Nrows; n += 8) {
        float x = Xb[(long long)n * D_ + c];
        s += x; q += x * x;
    }
    __shared__ float sh_s[8][32], sh_q[8][32];
    sh_s[ty][threadIdx.x] = s; sh_q[ty][threadIdx.x] = q;
    __syncthreads();
    __shared__ float sh_m[32], sh_r[32];
    if (ty == 0) {
        float S = 0.f, Q = 0.f;
        #pragma unroll
        for (int i = 0; i < 8; i++) { S += sh_s[i][threadIdx.x]; Q += sh_q[i][threadIdx.x]; }
        float mean = S / (float)Nrows;
        float var  = Q / (float)Nrows - mean*mean;
        sh_m[threadIdx.x] = mean;
        sh_r[threadIdx.x] = rsqrtf(var + EPS_);
    }
    __syncthreads();
    float mean = sh_m[threadIdx.x], r = sh_r[threadIdx.x];
    float gg = g[c], bb = be[c];
    for (int n = ty; n < Nrows; n += 8) {
        long long idx = (long long)n * D_ + c;
        float v = gg * (Xb[idx] - mean) * r + bb;
        Xb[idx] = v;
        __half hh, ll; splitf(v, hh, ll);
        Xh[base + idx] = hh; Xl[base + idx] = ll;
    }
}

// ---------------- input projections + concat ----------------
__global__ void init_x(const float* __restrict__ wf, const float* __restrict__ tf,
                       const float* __restrict__ Wws, const float* __restrict__ bws,
                       const float* __restrict__ Wwe, const float* __restrict__ bwe,
                       const float* __restrict__ Wt,  const float* __restrict__ bt)
{
    int t = blockIdx.x * blockDim.x + threadIdx.x;
    if (t >= B_*N_*D_) return;
    int d = t & 511;
    int n = (t >> 9) % N_;
    int b = t / (D_*N_);
    float v;
    if (n < NW_) {
        const float* f = wf + (b*NW_ + n)*4;
        v = bws[d];
        #pragma unroll
        for (int k = 0; k < 4; k++) v += f[k] * Wws[k*D_ + d];
    } else if (n < 2*NW_) {
        const float* f = wf + (b*NW_ + (n - NW_))*4;
        v = bwe[d];
        #pragma unroll
        for (int k = 0; k < 4; k++) v += f[k] * Wwe[k*D_ + d];
    } else {
        const float* f = tf + (b*NT_ + (n - 2*NW_))*8;
        v = bt[d];
        #pragma unroll
        for (int k = 0; k < 8; k++) v += f[k] * Wt[k*D_ + d];
    }
    g_X[t] = v;
}

// ---------------- edge bias: analytic InstanceNorm2d coefficients ----------------
__global__ void zero_esum() { if (threadIdx.x < B_*5) g_esum[threadIdx.x] = 0.0; }

__global__ __launch_bounds__(256)
void edge_stats(const float* __restrict__ ef)
{
    int b = blockIdx.y;
    const float2* p = (const float2*)ef + (long long)b * (N_*N_);
    int stride = gridDim.x * blockDim.x;
    float s0=0,s1=0,s00=0,s11=0,s01=0;
    for (int i = blockIdx.x*blockDim.x + threadIdx.x; i < N_*N_; i += stride) {
        float2 f = p[i];
        s0 += f.x; s1 += f.y; s00 += f.x*f.x; s11 += f.y*f.y; s01 += f.x*f.y;
    }
    __shared__ double red[256];
    double loc[5] = {(double)s0,(double)s1,(double)s00,(double)s11,(double)s01};
    for (int j = 0; j < 5; j++) {
        red[threadIdx.x] = loc[j];
        __syncthreads();
        for (int s = 128; s > 0; s >>= 1) { if (threadIdx.x < s) red[threadIdx.x] += red[threadIdx.x+s]; __syncthreads(); }
        if (threadIdx.x == 0) atomicAdd(&g_esum[b*5+j], red[0]);
        __syncthreads();
    }
}

__global__ void edge_params(const float* __restrict__ We, const float* __restrict__ be,
                            const float* __restrict__ ge, const float* __restrict__ bee)
{
    int t = threadIdx.x;
    if (t >= B_*H_) return;
    int b = t / H_, h = t % H_;
    double cnt = (double)N_ * (double)N_;
    double m0  = g_esum[b*5+0]/cnt, m1 = g_esum[b*5+1]/cnt;
    double v00 = g_esum[b*5+2]/cnt - m0*m0;
    double v11 = g_esum[b*5+3]/cnt - m1*m1;
    double v01 = g_esum[b*5+4]/cnt - m0*m1;
    double w0 = We[0*H_+h], w1 = We[1*H_+h];
    double mean = w0*m0 + w1*m1 + (double)be[h];
    double var  = w0*w0*v00 + 2.0*w0*w1*v01 + w1*w1*v11;
    double grs  = (double)ge[h] / sqrt(var + (double)EPS_);
    g_ec0[t] = (float)(w0*grs);
    g_ec1[t] = (float)(w1*grs);
    g_ec2[t] = (float)(((double)be[h] - mean)*grs + (double)bee[h]);
}

// ---------------- weight packing (k-major hi/lo halves) ----------------
__global__ void pack_qkv(const float* __restrict__ Wq, const float* __restrict__ Wk,
                         const float* __restrict__ Wv)
{
    int t = blockIdx.x * blockDim.x + threadIdx.x;
    if (t >= L_*3*D_*D_) return;
    int k = t & 511;
    int n = (t >> 9) % (3*D_);
    int l = t / (3*D_*D_);
    int sec = n / D_, hn = n - sec*D_, h = hn >> 6, e = hn & 63;
    const float* W = (sec == 0) ? Wq : (sec == 1) ? Wk : Wv;
    float v = W[(((long long)l*H_ + h)*D_ + k)*HD_ + e];
    splitf(v, g_Wqkvh[t], g_Wqkvl[t]);
}

__global__ void pack_wo(const float* __restrict__ Wo)
{
    int t = blockIdx.x * blockDim.x + threadIdx.x;
    if (t >= L_*D_*D_) return;
    int k = t & 511, n = (t >> 9) & 511, l = t >> 18;
    float v = Wo[((long long)l*D_ + k)*D_ + n];
    splitf(v, g_Woh[t], g_Wol[t]);
}

__global__ void pack_w1(const float* __restrict__ W1)
{
    int t = blockIdx.x * blockDim.x + threadIdx.x;
    if (t >= L_*DFF_*D_) return;
    int k = t & 511;
    int n = (t >> 9) % DFF_;
    int l = t / (DFF_*D_);
    float v = W1[((long long)l*D_ + k)*DFF_ + n];
    splitf(v, g_W1h[t], g_W1l[t]);
}

__global__ void pack_w2(const float* __restrict__ W2)
{
    int t = blockIdx.x * blockDim.x + threadIdx.x;
    if (t >= L_*D_*DFF_) return;
    int k = t & 2047;
    int n = (t >> 11) & 511;
    int l = t / (D_*DFF_);
    float v = W2[((long long)l*DFF_ + k)*D_ + n];
    splitf(v, g_W2h[t], g_W2l[t]);
}

__global__ void pack_kvw(const float* __restrict__ Kd, const float* __restrict__ Vd)
{
    int t = blockIdx.x * blockDim.x + threadIdx.x;
    if (t >= 2*D_*D_) return;
    int k = t & 511, n = t >> 9;
    int sec = n >> 9, hn = n & 511, h = hn >> 6, e = hn & 63;
    const float* W = sec ? Vd : Kd;
    float v = W[((long long)h*D_ + k)*HD_ + e];
    splitf(v, g_Wkvh[t], g_Wkvl[t]);
}

__global__ void zero_vt_pad()
{
    int t = blockIdx.x * blockDim.x + threadIdx.x;
    if (t >= B_*D_*(NPAD_-N_)) return;
    int c = N_ + t % (NPAD_-N_);
    int r = t / (NPAD_-N_);
    __half z = __float2half(0.f);
    g_Vth[(long long)r*NPAD_ + c] = z;
    g_Vtl[(long long)r*NPAD_ + c] = z;
}

// ---------------- finish token append into output X (+ hi/lo) ----------------
__global__ void write_xout(const float* __restrict__ fin, float* __restrict__ out)
{
    int t = blockIdx.x * blockDim.x + threadIdx.x;
    if (t >= B_*N1_*D_) return;
    int d = t & 511;
    int n = (t >> 9) % N1_;
    int b = t / (N1_*D_);
    float v = (n < N_) ? g_X[((long long)b*N_ + n)*D_ + d] : fin[d];
    out[t] = v;
    splitf(v, g_Xoh[t], g_Xol[t]);
}

// ---------------- reorder decode K/V to [H][B][N1][HD] ----------------
__global__ void write_kv(float* __restrict__ outK, float* __restrict__ outV)
{
    int t = blockIdx.x * blockDim.x + threadIdx.x;
    if (t >= H_*B_*N1_*HD_) return;
    int e = t & 63;
    int n = (t >> 6) % N1_;
    int rem = t / (HD_*N1_);
    int b = rem & 3;
    int h = rem >> 2;
    long long src = ((long long)(b*N1_ + n))*(2*D_) + h*HD_ + e;
    outK[t] = g_KV[src];
    outV[t] = g_KV[src + D_];
}

// ---------------- host orchestration ----------------
static inline int cdiv(int a, int b) { return (a + b - 1) / b; }

extern "C" void kernel_launch(void* const* d_in, const int* in_sizes, int n_in,
                              void* d_out, int out_size)
{
    const float* wf   = (const float*)d_in[0];
    const float* tf   = (const float*)d_in[1];
    const float* ef   = (const float*)d_in[2];
    const float* Wws  = (const float*)d_in[3];
    const float* bws  = (const float*)d_in[4];
    const float* Wwe  = (const float*)d_in[5];
    const float* bwe  = (const float*)d_in[6];
    const float* Wt   = (const float*)d_in[7];
    const float* bt   = (const float*)d_in[8];
    const float* g_wt = (const float*)d_in[9];
    const float* be_wt= (const float*)d_in[10];
    const float* W_e  = (const float*)d_in[11];
    const float* b_e  = (const float*)d_in[12];
    const float* g_e  = (const float*)d_in[13];
    const float* be_e = (const float*)d_in[14];
    const float* Wq   = (const float*)d_in[15];
    const float* Wk   = (const float*)d_in[16];
    const float* Wv   = (const float*)d_in[17];
    const float* Wo   = (const float*)d_in[18];
    const float* W1   = (const float*)d_in[19];
    const float* b1   = (const float*)d_in[20];
    const float* W2   = (const float*)d_in[21];
    const float* b2   = (const float*)d_in[22];
    const float* g1   = (const float*)d_in[23];
    const float* be1  = (const float*)d_in[24];
    const float* g2   = (const float*)d_in[25];
    const float* be2  = (const float*)d_in[26];
    const float* fin  = (const float*)d_in[27];
    const float* Kd   = (const float*)d_in[28];
    const float* Vd   = (const float*)d_in[29];

    float* out  = (float*)d_out;
    float* outX = out;
    float* outK = out + (size_t)B_*N1_*D_;
    float* outV = outK + (size_t)H_*B_*N1_*HD_;

    float *pX, *pKV;
    __half *pXh,*pXl,*pQh,*pQl,*pVth,*pVtl,*pOhh,*pOll,*pFh,*pFl;
    __half *pWqh,*pWql,*pWoh,*pWol,*pW1h,*pW1l,*pW2h,*pW2l,*pWkh,*pWkl,*pXoh,*pXol;
    cudaGetSymbolAddress((void**)&pX,  g_X);
    cudaGetSymbolAddress((void**)&pKV, g_KV);
    cudaGetSymbolAddress((void**)&pXh, g_Xh);   cudaGetSymbolAddress((void**)&pXl, g_Xl);
    cudaGetSymbolAddress((void**)&pQh, g_QKVh); cudaGetSymbolAddress((void**)&pQl, g_QKVl);
    cudaGetSymbolAddress((void**)&pVth,g_Vth);  cudaGetSymbolAddress((void**)&pVtl,g_Vtl);
    cudaGetSymbolAddress((void**)&pOhh,g_Oh);   cudaGetSymbolAddress((void**)&pOll,g_Ol);
    cudaGetSymbolAddress((void**)&pFh, g_FFh);  cudaGetSymbolAddress((void**)&pFl, g_FFl);
    cudaGetSymbolAddress((void**)&pWqh,g_Wqkvh);cudaGetSymbolAddress((void**)&pWql,g_Wqkvl);
    cudaGetSymbolAddress((void**)&pWoh,g_Woh);  cudaGetSymbolAddress((void**)&pWol,g_Wol);
    cudaGetSymbolAddress((void**)&pW1h,g_W1h);  cudaGetSymbolAddress((void**)&pW1l,g_W1l);
    cudaGetSymbolAddress((void**)&pW2h,g_W2h);  cudaGetSymbolAddress((void**)&pW2l,g_W2l);
    cudaGetSymbolAddress((void**)&pWkh,g_Wkvh); cudaGetSymbolAddress((void**)&pWkl,g_Wkvl);
    cudaGetSymbolAddress((void**)&pXoh,g_Xoh);  cudaGetSymbolAddress((void**)&pXol,g_Xol);

    cudaFuncSetAttribute(flash_attn, cudaFuncAttributeMaxDynamicSharedMemorySize, FLASH_SMEM);
    cudaFuncSetAttribute(gemm_hl<128,128,4,2>, cudaFuncAttributeMaxDynamicSharedMemorySize, GEMM_SMEM);

    // ---- setup ----
    zero_esum<<<1, 32>>>();
    edge_stats<<<dim3(32, B_), 256>>>(ef);
    edge_params<<<1, 32>>>(W_e, b_e, g_e, be_e);
    pack_qkv<<<cdiv(L_*3*D_*D_, 256), 256>>>(Wq, Wk, Wv);
    pack_wo <<<cdiv(L_*D_*D_, 256), 256>>>(Wo);
    pack_w1 <<<cdiv(L_*DFF_*D_, 256), 256>>>(W1);
    pack_w2 <<<cdiv(L_*D_*DFF_, 256), 256>>>(W2);
    pack_kvw<<<cdiv(2*D_*D_, 256), 256>>>(Kd, Vd);
    zero_vt_pad<<<cdiv(B_*D_*(NPAD_-N_), 256), 256>>>();
    init_x<<<cdiv(B_*N_*D_, 256), 256>>>(wf, tf, Wws, bws, Wwe, bwe, Wt, bt);
    inorm1d<<<dim3(D_/32, B_), dim3(32, 8)>>>(pX, g_wt, be_wt, pXh, pXl, N_);

    const int Mrows = B_*N_;   // 4000

    for (int l = 0; l < L_; l++) {
        long long wq = (long long)l*3*D_*D_;
        // QKV: hi/lo halves + Vt scatter
        gemm_hl<128,128,4,2><<<dim3(12, 32, 1), 256, GEMM_SMEM>>>(
            pXh, pXl, D_, 0,0,
            pWqh + wq, pWql + wq, D_, 0,0,
            nullptr, 0, 0,0,
            pQh, pQl, 3*D_, 0,0,
            nullptr, 0, 0,0, nullptr,
            Mrows, 3*D_, D_, 1, 1.f, 0, 1);
        // fused attention: edge bias + softmax + PV
        flash_attn<<<dim3(8, H_*B_), 256, FLASH_SMEM>>>(
            ef, pQh, pQl, pVth, pVtl, pOhh, pOll);
        // X = X + O @ Wo
        long long wo = (long long)l*D_*D_;
        gemm_hl<128,128,4,2><<<dim3(4, 32, 1), 256, GEMM_SMEM>>>(
            pOhh, pOll, D_, 0,0,
            pWoh + wo, pWol + wo, D_, 0,0,
            pX, D_, 0,0,
            nullptr, nullptr, 0, 0,0,
            pX, D_, 0,0, nullptr,
            Mrows, D_, D_, 1, 1.f, 0, 0);
        inorm1d<<<dim3(D_/32, B_), dim3(32, 8)>>>(pX, g1 + l*D_, be1 + l*D_, pXh, pXl, N_);
        // FF = relu(X @ W1 + b1)
        long long w1o = (long long)l*DFF_*D_;
        gemm_hl<128,128,4,2><<<dim3(16, 32, 1), 256, GEMM_SMEM>>>(
            pXh, pXl, D_, 0,0,
            pW1h + w1o, pW1l + w1o, D_, 0,0,
            nullptr, 0, 0,0,
            pFh, pFl, DFF_, 0,0,
            nullptr, 0, 0,0, b1 + l*DFF_,
            Mrows, DFF_, D_, 1, 1.f, 1, 0);
        // X = X + FF @ W2 + b2
        long long w2o = (long long)l*D_*DFF_;
        gemm_hl<128,128,4,2><<<dim3(4, 32, 1), 256, GEMM_SMEM>>>(
            pFh, pFl, DFF_, 0,0,
            pW2h + w2o, pW2l + w2o, DFF_, 0,0,
            pX, D_, 0,0,
            nullptr, nullptr, 0, 0,0,
            pX, D_, 0,0, b2 + l*D_,
            Mrows, D_, DFF_, 1, 1.f, 0, 0);
        inorm1d<<<dim3(D_/32, B_), dim3(32, 8)>>>(pX, g2 + l*D_, be2 + l*D_, pXh, pXl, N_);
    }

    write_xout<<<cdiv(B_*N1_*D_, 256), 256>>>(fin, outX);
    gemm_hl<128,128,4,2><<<dim3(8, 32, 1), 256, GEMM_SMEM>>>(
        pXoh, pXol, D_, 0,0,
        pWkh, pWkl, D_, 0,0,
        pKV, 2*D_, 0,0,
        nullptr, nullptr, 0, 0,0,
        nullptr, 0, 0,0, nullptr,
        B_*N1_, 2*D_, D_, 1, 1.f, 0, 0);
    write_kv<<<cdiv(H_*B_*N1_*HD_, 256), 256>>>(outK, outV);
}

// round 13
// speedup vs baseline: 2.5988x; 1.0680x over previous
#include <cuda_runtime.h>
#include <cuda_fp16.h>
#include <math.h>

// ---------------- problem constants ----------------
#define B_   4
#define NW_  100
#define NT_  800
#define N_   1000
#define N1_  1001
#define D_   512
#define H_   8
#define HD_  64
#define DFF_ 2048
#define L_   3
#define EPS_ 1e-5f
#define ALPHA_ 0.125f   // 1/sqrt(64)
#define NPAD_ 1024      // padded kv length for Vt

// ---------------- device scratch (no allocation allowed) ----------------
__device__ float  g_X   [B_*N_*D_];
__device__ float  g_KV  [B_*N1_*2*D_];
__device__ double g_part[B_*32*5];
__device__ float  g_ec0[32], g_ec1[32], g_ec2[32];

__device__ __align__(16) __half g_Xh [B_*N_*D_];
__device__ __align__(16) __half g_Xl [B_*N_*D_];
__device__ __align__(16) __half g_QKVh[B_*N_*3*D_];
__device__ __align__(16) __half g_QKVl[B_*N_*3*D_];
__device__ __align__(16) __half g_Vth[B_*D_*NPAD_];
__device__ __align__(16) __half g_Vtl[B_*D_*NPAD_];
__device__ __align__(16) __half g_Oh [B_*N_*D_];
__device__ __align__(16) __half g_Ol [B_*N_*D_];
__device__ __align__(16) __half g_FFh[B_*N_*DFF_];
__device__ __align__(16) __half g_FFl[B_*N_*DFF_];
__device__ __align__(16) __half g_Wqkvh[L_*3*D_*D_];
__device__ __align__(16) __half g_Wqkvl[L_*3*D_*D_];
__device__ __align__(16) __half g_Woh[L_*D_*D_];
__device__ __align__(16) __half g_Wol[L_*D_*D_];
__device__ __align__(16) __half g_W1h[L_*DFF_*D_];
__device__ __align__(16) __half g_W1l[L_*DFF_*D_];
__device__ __align__(16) __half g_W2h[L_*D_*DFF_];
__device__ __align__(16) __half g_W2l[L_*D_*DFF_];
__device__ __align__(16) __half g_Wkvh[2*D_*D_];
__device__ __align__(16) __half g_Wkvl[2*D_*D_];
__device__ __align__(16) __half g_Xoh[B_*N1_*D_];
__device__ __align__(16) __half g_Xol[B_*N1_*D_];

__device__ __forceinline__ void splitf(float v, __half &h, __half &l) {
    h = __float2half_rn(v);
    l = __float2half_rn(v - __half2float(h));
}

__device__ __forceinline__ void cp16(unsigned dst, const void* src, bool p) {
    int sz = p ? 16 : 0;
    asm volatile("cp.async.ca.shared.global [%0], [%1], 16, %2;\n"
                 :: "r"(dst), "l"(src), "r"(sz));
}

#define LDSM4(r0,r1,r2,r3,a) \
    asm volatile("ldmatrix.sync.aligned.m8n8.x4.shared.b16 {%0,%1,%2,%3}, [%4];" \
                 : "=r"(r0),"=r"(r1),"=r"(r2),"=r"(r3) : "r"(a))

#define MMA16816(acc,a0,a1,a2,a3,b0,b1) \
    asm volatile("mma.sync.aligned.m16n8k16.row.col.f32.f16.f16.f32 " \
                 "{%0,%1,%2,%3}, {%4,%5,%6,%7}, {%8,%9}, {%0,%1,%2,%3};" \
                 : "+f"((acc)[0]), "+f"((acc)[1]), "+f"((acc)[2]), "+f"((acc)[3]) \
                 : "r"(a0), "r"(a1), "r"(a2), "r"(a3), "r"(b0), "r"(b1))

// ---------------- split-fp16 GEMM: 3-stage cp.async pipeline ----------------
#define GSTAGES 3
constexpr int gemm_smem(int BM, int BN) { return GSTAGES*2*(BM+BN)*24*2; }

template<int BM, int BN, int WARPS_M, int WARPS_N>
__global__ __launch_bounds__(WARPS_M*WARPS_N*32)
void gemm_hl(const __half* __restrict__ Ah, const __half* __restrict__ Al,
             int lda, long long sA1, long long sA0,
             const __half* __restrict__ Bh, const __half* __restrict__ Bl,
             int ldb, long long sB1, long long sB0,
             float* __restrict__ C, int ldc, long long sC1, long long sC0,
             __half* __restrict__ Ch, __half* __restrict__ Cl,
             int ldch, long long sCh1, long long sCh0,
             const float* __restrict__ addsrc, int ldadd, long long sD1, long long sD0,
             const float* __restrict__ bias,
             int M, int N, int K, int inner, float alpha,
             int relu, int qkv_mode)
{
    constexpr int BK = 16;
    constexpr int LDK = BK + 8;
    constexpr int WM = BM/WARPS_M, WN = BN/WARPS_N;
    constexpr int MT = WM/16, NT = WN/8;
    constexpr int THREADS = WARPS_M*WARPS_N*32;

    extern __shared__ __half sm_g[];
    __half* As = sm_g;                          // [S][2][BM][LDK]
    __half* Bs = sm_g + GSTAGES*2*BM*LDK;       // [S][2][BN][LDK]

    int z = blockIdx.z, z1 = z/inner, z0 = z%inner;
    Ah += z1*sA1 + z0*sA0;  Al += z1*sA1 + z0*sA0;
    Bh += z1*sB1 + z0*sB0;  Bl += z1*sB1 + z0*sB0;
    if (C)  C  += z1*sC1  + z0*sC0;
    if (Ch) { Ch += z1*sCh1 + z0*sCh0; Cl += z1*sCh1 + z0*sCh0; }

    int tid = threadIdx.x;
    int warp = tid>>5, lane = tid&31, g = lane>>2, tg = lane&3;
    int wm = (warp % WARPS_M)*WM, wn = (warp / WARPS_M)*WN;
    int row0 = blockIdx.y*BM, col0 = blockIdx.x*BN;

    const unsigned sAb = (unsigned)__cvta_generic_to_shared(As);
    const unsigned sBb = (unsigned)__cvta_generic_to_shared(Bs);

    float acc[MT][NT][4] = {};

    int aRow = (lane&7) + ((lane>>3)&1)*8;
    int aCol = ((lane>>4)&1)*8;
    int bRow = (lane&7) + ((lane>>4)&1)*8;
    int bCol = ((lane>>3)&1)*8;

    auto issue = [&](int kt, int s) {
        if (tid < BM*2) {
            int row = tid>>1, ch = (tid&1)*8;
            bool p = (row0+row) < M;
            long long go = (long long)(row0+row)*lda + kt + ch;
            cp16(sAb + (unsigned)((((s*2+0)*BM + row)*LDK + ch)*2), Ah + go, p);
            cp16(sAb + (unsigned)((((s*2+1)*BM + row)*LDK + ch)*2), Al + go, p);
        }
        if (tid < BN*2) {
            int row = tid>>1, ch = (tid&1)*8;
            bool p = (col0+row) < N;
            long long go = (long long)(col0+row)*ldb + kt + ch;
            cp16(sBb + (unsigned)((((s*2+0)*BN + row)*LDK + ch)*2), Bh + go, p);
            cp16(sBb + (unsigned)((((s*2+1)*BN + row)*LDK + ch)*2), Bl + go, p);
        }
        asm volatile("cp.async.commit_group;");
    };

    auto compute = [&](int s) {
        unsigned ah[MT][4], al[MT][4];
        #pragma unroll
        for (int mt = 0; mt < MT; mt++) {
            int r = wm + mt*16 + aRow;
            LDSM4(ah[mt][0], ah[mt][1], ah[mt][2], ah[mt][3],
                  sAb + (unsigned)((((s*2+0)*BM + r)*LDK + aCol)*2));
            LDSM4(al[mt][0], al[mt][1], al[mt][2], al[mt][3],
                  sAb + (unsigned)((((s*2+1)*BM + r)*LDK + aCol)*2));
        }
        #pragma unroll
        for (int nt2 = 0; nt2 < NT/2; nt2++) {
            int rB = wn + nt2*16 + bRow;
            unsigned bh0,bh1,bh2,bh3, bl0,bl1,bl2,bl3;
            LDSM4(bh0,bh1,bh2,bh3, sBb + (unsigned)((((s*2+0)*BN + rB)*LDK + bCol)*2));
            LDSM4(bl0,bl1,bl2,bl3, sBb + (unsigned)((((s*2+1)*BN + rB)*LDK + bCol)*2));
            #pragma unroll
            for (int mt = 0; mt < MT; mt++) {
                MMA16816(acc[mt][nt2*2], ah[mt][0],ah[mt][1],ah[mt][2],ah[mt][3], bh0,bh1);
                MMA16816(acc[mt][nt2*2], ah[mt][0],ah[mt][1],ah[mt][2],ah[mt][3], bl0,bl1);
                MMA16816(acc[mt][nt2*2], al[mt][0],al[mt][1],al[mt][2],al[mt][3], bh0,bh1);
            }
            #pragma unroll
            for (int mt = 0; mt < MT; mt++) {
                MMA16816(acc[mt][nt2*2+1], ah[mt][0],ah[mt][1],ah[mt][2],ah[mt][3], bh2,bh3);
                MMA16816(acc[mt][nt2*2+1], ah[mt][0],ah[mt][1],ah[mt][2],ah[mt][3], bl2,bl3);
                MMA16816(acc[mt][nt2*2+1], al[mt][0],al[mt][1],al[mt][2],al[mt][3], bh2,bh3);
            }
        }
    };

    const int T = K / BK;
    issue(0, 0);
    if (T > 1) issue(BK, 1);
    for (int i = 0; i < T; i++) {
        if (i + 1 < T) { asm volatile("cp.async.wait_group 1;"); }
        else           { asm volatile("cp.async.wait_group 0;"); }
        __syncthreads();
        if (i + 2 < T) issue((i+2)*BK, (i+2)%GSTAGES);
        compute(i % GSTAGES);
    }

    if (addsrc) addsrc += z1*sD1 + z0*sD0;

    #pragma unroll
    for (int mt = 0; mt < MT; mt++) {
        #pragma unroll
        for (int nt = 0; nt < NT; nt++) {
            int nb = col0 + wn + nt*8 + tg*2;
            #pragma unroll
            for (int h2 = 0; h2 < 2; h2++) {
                int m = row0 + wm + mt*16 + g + h2*8;
                if (m >= M) continue;
                #pragma unroll
                for (int j = 0; j < 2; j++) {
                    int n = nb + j;
                    if (n >= N) continue;
                    float v = alpha * acc[mt][nt][h2*2+j];
                    if (bias)   v += bias[n];
                    if (addsrc) v += addsrc[(long long)m*ldadd + n];
                    if (relu) v = fmaxf(v, 0.f);
                    if (C) C[(long long)m*ldc + n] = v;
                    if (Ch) {
                        __half hh, ll; splitf(v, hh, ll);
                        Ch[(long long)m*ldch + n] = hh;
                        Cl[(long long)m*ldch + n] = ll;
                        if (qkv_mode && n >= 1024) {
                            int b = m / N_, mm = m - b*N_;
                            long long vi = ((long long)b*D_ + (n-1024))*NPAD_ + mm;
                            g_Vth[vi] = hh; g_Vtl[vi] = ll;
                        }
                    }
                }
            }
        }
    }
}

// ---------------- flash attention (double-buffered KV) ----------------
#define LDKQ 72
#define LDVV 136
#define FBUF (2*128*LDKQ + 2*64*LDVV)            // halves per buffer
#define FLASH_SMEM (2*FBUF*2)                    // bytes, 2 buffers

__global__ __launch_bounds__(256,1)
void flash_attn(const float* __restrict__ ef,
                const __half* __restrict__ QKVh, const __half* __restrict__ QKVl,
                const __half* __restrict__ Vth,  const __half* __restrict__ Vtl,
                __half* __restrict__ Oh, __half* __restrict__ Ol)
{
    extern __shared__ __half sm_[];

    const int qb = blockIdx.x;
    const int z  = blockIdx.y;
    const int h  = z / B_, b = z % B_;
    const int row0 = qb*128;
    const int tid = threadIdx.x, warp = tid>>5, lane = tid&31;
    const int g = lane>>2, tg = lane&3;
    const int aRow = (lane&7) + ((lane>>3)&1)*8;
    const int aCol = ((lane>>4)&1)*8;
    const int bRow = (lane&7) + ((lane>>4)&1)*8;
    const int bCol = ((lane>>3)&1)*8;

    const unsigned sBase = (unsigned)__cvta_generic_to_shared(sm_);
    auto sKh = [&](int bf){ return sBase + (unsigned)(bf*FBUF*2); };
    auto sKl = [&](int bf){ return sBase + (unsigned)((bf*FBUF + 128*LDKQ)*2); };
    auto sVh = [&](int bf){ return sBase + (unsigned)((bf*FBUF + 2*128*LDKQ)*2); };
    auto sVl = [&](int bf){ return sBase + (unsigned)((bf*FBUF + 2*128*LDKQ + 64*LDVV)*2); };

    // ---- stage Q tile through buffer-0 K region into registers ----
    #pragma unroll
    for (int i = 0; i < 4; i++) {
        int idx = tid + i*256;
        int r = idx >> 3, ch = (idx & 7)*8;
        int m = row0 + r;
        bool p = m < N_;
        long long go = (long long)(b*N_ + (p ? m : 0))*(3*D_) + h*HD_ + ch;
        cp16(sKh(0) + (unsigned)((r*LDKQ + ch)*2), QKVh + go, p);
        cp16(sKl(0) + (unsigned)((r*LDKQ + ch)*2), QKVl + go, p);
    }
    asm volatile("cp.async.commit_group;");
    asm volatile("cp.async.wait_group 0;");
    __syncthreads();

    unsigned qh[4][4], ql[4][4];
    #pragma unroll
    for (int ks = 0; ks < 4; ks++) {
        LDSM4(qh[ks][0],qh[ks][1],qh[ks][2],qh[ks][3],
              sKh(0) + (unsigned)(((warp*16 + aRow)*LDKQ + ks*16 + aCol)*2));
        LDSM4(ql[ks][0],ql[ks][1],ql[ks][2],ql[ks][3],
              sKl(0) + (unsigned)(((warp*16 + aRow)*LDKQ + ks*16 + aCol)*2));
    }
    __syncthreads();

    auto issue_kv = [&](int kt, int bf) {
        const int kv0 = kt*128;
        #pragma unroll
        for (int i = 0; i < 4; i++) {
            int idx = tid + i*256;
            int r = idx >> 3, ch = (idx & 7)*8;
            int kv = kv0 + r;
            bool p = kv < N_;
            long long go = (long long)(b*N_ + (p ? kv : 0))*(3*D_) + D_ + h*HD_ + ch;
            cp16(sKh(bf) + (unsigned)((r*LDKQ + ch)*2), QKVh + go, p);
            cp16(sKl(bf) + (unsigned)((r*LDKQ + ch)*2), QKVl + go, p);
        }
        #pragma unroll
        for (int i = 0; i < 4; i++) {
            int idx = tid + i*256;
            int r = idx >> 4, ch = (idx & 15)*8;
            long long go = (long long)(b*D_ + h*HD_ + r)*NPAD_ + kv0 + ch;
            cp16(sVh(bf) + (unsigned)((r*LDVV + ch)*2), Vth + go, true);
            cp16(sVl(bf) + (unsigned)((r*LDVV + ch)*2), Vtl + go, true);
        }
        asm volatile("cp.async.commit_group;");
    };

    float oacc[8][4] = {};
    float rmax0 = -1e30f, rmax1 = -1e30f, rsum0 = 0.f, rsum1 = 0.f;
    const int te = b*H_ + h;
    const float ec0 = g_ec0[te], ec1 = g_ec1[te], ec2 = g_ec2[te];
    const float2* e2 = (const float2*)ef + (long long)b*N_*N_;
    const int r0g = row0 + warp*16 + g;
    const int r1g = r0g + 8;
    const long long er0 = (long long)(r0g < N_ ? r0g : N_-1) * N_;
    const long long er1 = (long long)(r1g < N_ ? r1g : N_-1) * N_;

    issue_kv(0, 0);
    issue_kv(1, 1);

    for (int kt = 0; kt < 8; kt++) {
        const int kv0 = kt*128;
        const int bf = kt & 1;
        if (kt < 7) { asm volatile("cp.async.wait_group 1;"); }
        else        { asm volatile("cp.async.wait_group 0;"); }
        __syncthreads();

        // S = Q @ K^T (split-fp16, fp32 acc)
        float s[16][4];
        #pragma unroll
        for (int i = 0; i < 16; i++) { s[i][0]=s[i][1]=s[i][2]=s[i][3]=0.f; }
        #pragma unroll
        for (int ks = 0; ks < 4; ks++) {
            #pragma unroll
            for (int nt2 = 0; nt2 < 8; nt2++) {
                unsigned bh0,bh1,bh2,bh3, bl0,bl1,bl2,bl3;
                LDSM4(bh0,bh1,bh2,bh3, sKh(bf) + (unsigned)(((nt2*16+bRow)*LDKQ + ks*16 + bCol)*2));
                LDSM4(bl0,bl1,bl2,bl3, sKl(bf) + (unsigned)(((nt2*16+bRow)*LDKQ + ks*16 + bCol)*2));
                MMA16816(s[nt2*2],   qh[ks][0],qh[ks][1],qh[ks][2],qh[ks][3], bh0,bh1);
                MMA16816(s[nt2*2],   qh[ks][0],qh[ks][1],qh[ks][2],qh[ks][3], bl0,bl1);
                MMA16816(s[nt2*2],   ql[ks][0],ql[ks][1],ql[ks][2],ql[ks][3], bh0,bh1);
                MMA16816(s[nt2*2+1], qh[ks][0],qh[ks][1],qh[ks][2],qh[ks][3], bh2,bh3);
                MMA16816(s[nt2*2+1], qh[ks][0],qh[ks][1],qh[ks][2],qh[ks][3], bl2,bl3);
                MMA16816(s[nt2*2+1], ql[ks][0],ql[ks][1],ql[ks][2],ql[ks][3], bh2,bh3);
            }
        }

        // edge bias + mask + online softmax
        float tm0 = -1e30f, tm1 = -1e30f;
        #pragma unroll
        for (int nt = 0; nt < 16; nt++) {
            int c = nt*8 + 2*tg;
            int n = kv0 + c;
            bool v0 = (n < N_), v1 = (n+1 < N_);
            long long ei0 = v0 ? n : (N_-1);
            long long ei1 = v1 ? (n+1) : (N_-1);
            float2 f00 = e2[er0 + ei0], f01 = e2[er0 + ei1];
            float2 f10 = e2[er1 + ei0], f11 = e2[er1 + ei1];
            s[nt][0] = v0 ? ALPHA_*s[nt][0] + f00.x*ec0 + f00.y*ec1 + ec2 : -1e30f;
            s[nt][1] = v1 ? ALPHA_*s[nt][1] + f01.x*ec0 + f01.y*ec1 + ec2 : -1e30f;
            s[nt][2] = v0 ? ALPHA_*s[nt][2] + f10.x*ec0 + f10.y*ec1 + ec2 : -1e30f;
            s[nt][3] = v1 ? ALPHA_*s[nt][3] + f11.x*ec0 + f11.y*ec1 + ec2 : -1e30f;
            tm0 = fmaxf(tm0, fmaxf(s[nt][0], s[nt][1]));
            tm1 = fmaxf(tm1, fmaxf(s[nt][2], s[nt][3]));
        }
        tm0 = fmaxf(tm0, __shfl_xor_sync(0xffffffffu, tm0, 1));
        tm0 = fmaxf(tm0, __shfl_xor_sync(0xffffffffu, tm0, 2));
        tm1 = fmaxf(tm1, __shfl_xor_sync(0xffffffffu, tm1, 1));
        tm1 = fmaxf(tm1, __shfl_xor_sync(0xffffffffu, tm1, 2));
        float nm0 = fmaxf(rmax0, tm0), nm1 = fmaxf(rmax1, tm1);
        float sc0 = __expf(rmax0 - nm0), sc1 = __expf(rmax1 - nm1);
        rmax0 = nm0; rmax1 = nm1;
        #pragma unroll
        for (int nt = 0; nt < 8; nt++) {
            oacc[nt][0]*=sc0; oacc[nt][1]*=sc0; oacc[nt][2]*=sc1; oacc[nt][3]*=sc1;
        }
        float ps0 = 0.f, ps1 = 0.f;
        #pragma unroll
        for (int nt = 0; nt < 16; nt++) {
            s[nt][0] = __expf(s[nt][0]-nm0); s[nt][1] = __expf(s[nt][1]-nm0);
            s[nt][2] = __expf(s[nt][2]-nm1); s[nt][3] = __expf(s[nt][3]-nm1);
            ps0 += s[nt][0]+s[nt][1]; ps1 += s[nt][2]+s[nt][3];
        }
        ps0 += __shfl_xor_sync(0xffffffffu, ps0, 1);
        ps0 += __shfl_xor_sync(0xffffffffu, ps0, 2);
        ps1 += __shfl_xor_sync(0xffffffffu, ps1, 1);
        ps1 += __shfl_xor_sync(0xffffffffu, ps1, 2);
        rsum0 = rsum0*sc0 + ps0;
        rsum1 = rsum1*sc1 + ps1;

        // O += P @ V  (P converted in-register to hi/lo A fragments)
        #pragma unroll
        for (int s8 = 0; s8 < 8; s8++) {
            unsigned pa[4], pb[4];
            #pragma unroll
            for (int j = 0; j < 2; j++) {
                float x0 = s[2*s8+j][0], x1 = s[2*s8+j][1];
                float x2 = s[2*s8+j][2], x3 = s[2*s8+j][3];
                __half2 h0 = __floats2half2_rn(x0, x1);
                __half2 h1 = __floats2half2_rn(x2, x3);
                float2 k0 = __half22float2(h0);
                float2 k1 = __half22float2(h1);
                __half2 l0 = __floats2half2_rn(x0-k0.x, x1-k0.y);
                __half2 l1 = __floats2half2_rn(x2-k1.x, x3-k1.y);
                pa[j*2+0] = *(unsigned*)&h0; pa[j*2+1] = *(unsigned*)&h1;
                pb[j*2+0] = *(unsigned*)&l0; pb[j*2+1] = *(unsigned*)&l1;
            }
            #pragma unroll
            for (int nt2 = 0; nt2 < 4; nt2++) {
                unsigned vh0,vh1,vh2,vh3, vl0,vl1,vl2,vl3;
                LDSM4(vh0,vh1,vh2,vh3, sVh(bf) + (unsigned)(((nt2*16+bRow)*LDVV + s8*16 + bCol)*2));
                LDSM4(vl0,vl1,vl2,vl3, sVl(bf) + (unsigned)(((nt2*16+bRow)*LDVV + s8*16 + bCol)*2));
                MMA16816(oacc[nt2*2],   pa[0],pa[1],pa[2],pa[3], vh0,vh1);
                MMA16816(oacc[nt2*2],   pa[0],pa[1],pa[2],pa[3], vl0,vl1);
                MMA16816(oacc[nt2*2],   pb[0],pb[1],pb[2],pb[3], vh0,vh1);
                MMA16816(oacc[nt2*2+1], pa[0],pa[1],pa[2],pa[3], vh2,vh3);
                MMA16816(oacc[nt2*2+1], pa[0],pa[1],pa[2],pa[3], vl2,vl3);
                MMA16816(oacc[nt2*2+1], pb[0],pb[1],pb[2],pb[3], vh2,vh3);
            }
        }
        __syncthreads();
        if (kt + 2 < 8) issue_kv(kt + 2, bf);
    }

    float i0 = 1.f / rsum0, i1 = 1.f / rsum1;
    #pragma unroll
    for (int nt = 0; nt < 8; nt++) {
        int c = h*HD_ + nt*8 + 2*tg;
        if (r0g < N_) {
            float a = oacc[nt][0]*i0, bb = oacc[nt][1]*i0;
            __half2 hh = __floats2half2_rn(a, bb);
            float2 bk = __half22float2(hh);
            __half2 ll = __floats2half2_rn(a-bk.x, bb-bk.y);
            *(__half2*)&Oh[(long long)(b*N_+r0g)*D_ + c] = hh;
            *(__half2*)&Ol[(long long)(b*N_+r0g)*D_ + c] = ll;
        }
        if (r1g < N_) {
            float a = oacc[nt][2]*i1, bb = oacc[nt][3]*i1;
            __half2 hh = __floats2half2_rn(a, bb);
            float2 bk = __half22float2(hh);
            __half2 ll = __floats2half2_rn(a-bk.x, bb-bk.y);
            *(__half2*)&Oh[(long long)(b*N_+r1g)*D_ + c] = hh;
            *(__half2*)&Ol[(long long)(b*N_+r1g)*D_ + c] = ll;
        }
    }
}

// ---------------- InstanceNorm1d: redundant stats, sliced normalize ----------
// grid (D/32, B, 8), block (32,8)
__global__ void inorm_r(float* __restrict__ X, const float* __restrict__ g,
                        const float* __restrict__ be,
                        __half* __restrict__ Xh, __half* __restrict__ Xl, int Nrows)
{
    int b = blockIdx.y;
    int zz = blockIdx.z;
    int c = blockIdx.x * 32 + threadIdx.x;
    int ty = threadIdx.y;
    long long base = (long long)b * Nrows * D_;
    float* Xb = X + base;
    float s = 0.f, q = 0.f;
    for (int n = ty; n < Nrows; n += 8) {
        float x = Xb[(long long)n * D_ + c];
        s += x; q += x * x;
    }
    __shared__ float sh_s[8][32], sh_q[8][32];
    sh_s[ty][threadIdx.x] = s; sh_q[ty][threadIdx.x] = q;
    __syncthreads();
    __shared__ float sh_m[32], sh_r[32];
    if (ty == 0) {
        float S = 0.f, Q = 0.f;
        #pragma unroll
        for (int i = 0; i < 8; i++) { S += sh_s[i][threadIdx.x]; Q += sh_q[i][threadIdx.x]; }
        float mean = S / (float)Nrows;
        float var  = Q / (float)Nrows - mean*mean;
        sh_m[threadIdx.x] = mean;
        sh_r[threadIdx.x] = rsqrtf(var + EPS_);
    }
    __syncthreads();
    float mean = sh_m[threadIdx.x], r = sh_r[threadIdx.x];
    float gg = g[c], bb = be[c];
    int chunk = (Nrows + 7) / 8;
    int n0 = zz * chunk;
    int n1 = min(n0 + chunk, Nrows);
    for (int n = n0 + ty; n < n1; n += 8) {
        long long idx = (long long)n * D_ + c;
        float v = gg * (Xb[idx] - mean) * r + bb;
        Xb[idx] = v;
        __half hh, ll; splitf(v, hh, ll);
        Xh[base + idx] = hh; Xl[base + idx] = ll;
    }
}

// ---------------- input projections + concat ----------------
__global__ void init_x(const float* __restrict__ wf, const float* __restrict__ tf,
                       const float* __restrict__ Wws, const float* __restrict__ bws,
                       const float* __restrict__ Wwe, const float* __restrict__ bwe,
                       const float* __restrict__ Wt,  const float* __restrict__ bt)
{
    int t = blockIdx.x * blockDim.x + threadIdx.x;
    if (t >= B_*N_*D_) return;
    int d = t & 511;
    int n = (t >> 9) % N_;
    int b = t / (D_*N_);
    float v;
    if (n < NW_) {
        const float* f = wf + (b*NW_ + n)*4;
        v = bws[d];
        #pragma unroll
        for (int k = 0; k < 4; k++) v += f[k] * Wws[k*D_ + d];
    } else if (n < 2*NW_) {
        const float* f = wf + (b*NW_ + (n - NW_))*4;
        v = bwe[d];
        #pragma unroll
        for (int k = 0; k < 4; k++) v += f[k] * Wwe[k*D_ + d];
    } else {
        const float* f = tf + (b*NT_ + (n - 2*NW_))*8;
        v = bt[d];
        #pragma unroll
        for (int k = 0; k < 8; k++) v += f[k] * Wt[k*D_ + d];
    }
    g_X[t] = v;
}

// ---------------- edge bias: per-block partial moments (no atomics) -----------
__global__ __launch_bounds__(256)
void edge_stats(const float* __restrict__ ef)
{
    int b = blockIdx.y;
    int blk = blockIdx.x;            // 0..31
    const float2* p = (const float2*)ef + (long long)b * (N_*N_);
    int stride = gridDim.x * blockDim.x;
    float s0=0,s1=0,s00=0,s11=0,s01=0;
    for (int i = blk*blockDim.x + threadIdx.x; i < N_*N_; i += stride) {
        float2 f = p[i];
        s0 += f.x; s1 += f.y; s00 += f.x*f.x; s11 += f.y*f.y; s01 += f.x*f.y;
    }
    __shared__ double red[256];
    double loc[5] = {(double)s0,(double)s1,(double)s00,(double)s11,(double)s01};
    for (int j = 0; j < 5; j++) {
        red[threadIdx.x] = loc[j];
        __syncthreads();
        for (int s = 128; s > 0; s >>= 1) { if (threadIdx.x < s) red[threadIdx.x] += red[threadIdx.x+s]; __syncthreads(); }
        if (threadIdx.x == 0) g_part[(b*32 + blk)*5 + j] = red[0];
        __syncthreads();
    }
}

__global__ void edge_params(const float* __restrict__ We, const float* __restrict__ be,
                            const float* __restrict__ ge, const float* __restrict__ bee)
{
    int t = threadIdx.x;
    if (t >= B_*H_) return;
    int b = t / H_, h = t % H_;
    double mm[5];
    for (int j = 0; j < 5; j++) {
        double acc = 0.0;
        for (int blk = 0; blk < 32; blk++) acc += g_part[(b*32 + blk)*5 + j];
        mm[j] = acc;
    }
    double cnt = (double)N_ * (double)N_;
    double m0  = mm[0]/cnt, m1 = mm[1]/cnt;
    double v00 = mm[2]/cnt - m0*m0;
    double v11 = mm[3]/cnt - m1*m1;
    double v01 = mm[4]/cnt - m0*m1;
    double w0 = We[0*H_+h], w1 = We[1*H_+h];
    double mean = w0*m0 + w1*m1 + (double)be[h];
    double var  = w0*w0*v00 + 2.0*w0*w1*v01 + w1*w1*v11;
    double grs  = (double)ge[h] / sqrt(var + (double)EPS_);
    g_ec0[t] = (float)(w0*grs);
    g_ec1[t] = (float)(w1*grs);
    g_ec2[t] = (float)(((double)be[h] - mean)*grs + (double)bee[h]);
}

// ---------------- unified weight pack: tiled transpose + split ----------------
// Sections (tile id ranges):
//  A [0,2304)    : QKV  (l,sec,h) 512x64
//  B [2304,3072) : Wo   (l)       512x512
//  C [3072,6144) : W1   (l)       512x2048
//  D [6144,9216) : W2   (l)       2048x512
//  E [9216,9728) : KV   (sec,h)   512x64
//  F [9728,9920) : Vt pad zero
__global__ __launch_bounds__(256)
void pack_all(const float* __restrict__ Wq, const float* __restrict__ Wk,
              const float* __restrict__ Wv, const float* __restrict__ Wo,
              const float* __restrict__ W1, const float* __restrict__ W2,
              const float* __restrict__ Kd, const float* __restrict__ Vd)
{
    int t = blockIdx.x;
    int tx = threadIdx.x & 31, ty = threadIdx.x >> 5;

    if (t >= 9728) {          // Section F: zero Vt pad
        int idx = (t - 9728) * 256 + threadIdx.x;     // 0..49151
        int r = idx / (NPAD_ - N_);
        int c = N_ + idx % (NPAD_ - N_);
        __half zz = __float2half(0.f);
        g_Vth[(long long)r*NPAD_ + c] = zz;
        g_Vtl[(long long)r*NPAD_ + c] = zz;
        return;
    }

    const float* src; __half *dh, *dl;
    int C, dstStride; long long srcOff = 0, dstOff = 0;
    int tr, tc;

    if (t < 2304) {           // A: QKV
        int batch = t >> 5, w = t & 31;
        tr = w & 15; tc = w >> 4;
        int l = batch / 24, r24 = batch % 24, sec = r24 >> 3, h = r24 & 7;
        src = (sec == 0) ? Wq : (sec == 1) ? Wk : Wv;
        srcOff = (long long)(l*8 + h) * 32768;
        C = 64; dstStride = 512;
        dh = g_Wqkvh; dl = g_Wqkvl;
        dstOff = (long long)l*786432 + (long long)(sec*512 + h*64)*512;
    } else if (t < 3072) {    // B: Wo
        int t2 = t - 2304;
        int l = t2 >> 8, w = t2 & 255;
        tr = w & 15; tc = w >> 4;
        src = Wo; srcOff = (long long)l*262144;
        C = 512; dstStride = 512;
        dh = g_Woh; dl = g_Wol; dstOff = (long long)l*262144;
    } else if (t < 6144) {    // C: W1 512x2048
        int t2 = t - 3072;
        int l = t2 >> 10, w = t2 & 1023;
        tr = w & 15; tc = w >> 4;       // tc 0..63
        src = W1; srcOff = (long long)l*1048576;
        C = 2048; dstStride = 512;
        dh = g_W1h; dl = g_W1l; dstOff = (long long)l*1048576;
    } else if (t < 9216) {    // D: W2 2048x512
        int t2 = t - 6144;
        int l = t2 >> 10, w = t2 & 1023;
        tr = w & 63; tc = w >> 6;       // tr 0..63, tc 0..15
        src = W2; srcOff = (long long)l*1048576;
        C = 512; dstStride = 2048;
        dh = g_W2h; dl = g_W2l; dstOff = (long long)l*1048576;
    } else {                  // E: KV
        int t2 = t - 9216;
        int batch = t2 >> 5, w = t2 & 31;
        tr = w & 15; tc = w >> 4;
        int sec = batch >> 3, h = batch & 7;
        src = sec ? Vd : Kd;
        srcOff = (long long)h * 32768;
        C = 64; dstStride = 512;
        dh = g_Wkvh; dl = g_Wkvl;
        dstOff = (long long)(sec*512 + h*64)*512;
    }

    __shared__ float tile[32][33];
    #pragma unroll
    for (int i = 0; i < 4; i++) {
        int r = tr*32 + ty + i*8;
        int c = tc*32 + tx;
        tile[ty + i*8][tx] = src[srcOff + (long long)r*C + c];
    }
    __syncthreads();
    #pragma unroll
    for (int i = 0; i < 4; i++) {
        int n = tc*32 + ty + i*8;       // dst row (col of src)
        int k = tr*32 + tx;             // dst col (row of src)
        float v = tile[tx][ty + i*8];
        __half hh, ll; splitf(v, hh, ll);
        long long di = dstOff + (long long)n*dstStride + k;
        dh[di] = hh; dl[di] = ll;
    }
}

// ---------------- finish token append into output X (+ hi/lo) ----------------
__global__ void write_xout(const float* __restrict__ fin, float* __restrict__ out)
{
    int t = blockIdx.x * blockDim.x + threadIdx.x;
    if (t >= B_*N1_*D_) return;
    int d = t & 511;
    int n = (t >> 9) % N1_;
    int b = t / (N1_*D_);
    float v = (n < N_) ? g_X[((long long)b*N_ + n)*D_ + d] : fin[d];
    out[t] = v;
    splitf(v, g_Xoh[t], g_Xol[t]);
}

// ---------------- reorder decode K/V to [H][B][N1][HD] ----------------
__global__ void write_kv(float* __restrict__ outK, float* __restrict__ outV)
{
    int t = blockIdx.x * blockDim.x + threadIdx.x;
    if (t >= H_*B_*N1_*HD_) return;
    int e = t & 63;
    int n = (t >> 6) % N1_;
    int rem = t / (HD_*N1_);
    int b = rem & 3;
    int h = rem >> 2;
    long long src = ((long long)(b*N1_ + n))*(2*D_) + h*HD_ + e;
    outK[t] = g_KV[src];
    outV[t] = g_KV[src + D_];
}

// ---------------- host orchestration ----------------
static inline int cdiv(int a, int b) { return (a + b - 1) / b; }

extern "C" void kernel_launch(void* const* d_in, const int* in_sizes, int n_in,
                              void* d_out, int out_size)
{
    const float* wf   = (const float*)d_in[0];
    const float* tf   = (const float*)d_in[1];
    const float* ef   = (const float*)d_in[2];
    const float* Wws  = (const float*)d_in[3];
    const float* bws  = (const float*)d_in[4];
    const float* Wwe  = (const float*)d_in[5];
    const float* bwe  = (const float*)d_in[6];
    const float* Wt   = (const float*)d_in[7];
    const float* bt   = (const float*)d_in[8];
    const float* g_wt = (const float*)d_in[9];
    const float* be_wt= (const float*)d_in[10];
    const float* W_e  = (const float*)d_in[11];
    const float* b_e  = (const float*)d_in[12];
    const float* g_e  = (const float*)d_in[13];
    const float* be_e = (const float*)d_in[14];
    const float* Wq   = (const float*)d_in[15];
    const float* Wk   = (const float*)d_in[16];
    const float* Wv   = (const float*)d_in[17];
    const float* Wo   = (const float*)d_in[18];
    const float* W1   = (const float*)d_in[19];
    const float* b1   = (const float*)d_in[20];
    const float* W2   = (const float*)d_in[21];
    const float* b2   = (const float*)d_in[22];
    const float* g1   = (const float*)d_in[23];
    const float* be1  = (const float*)d_in[24];
    const float* g2   = (const float*)d_in[25];
    const float* be2  = (const float*)d_in[26];
    const float* fin  = (const float*)d_in[27];
    const float* Kd   = (const float*)d_in[28];
    const float* Vd   = (const float*)d_in[29];

    float* out  = (float*)d_out;
    float* outX = out;
    float* outK = out + (size_t)B_*N1_*D_;
    float* outV = outK + (size_t)H_*B_*N1_*HD_;

    float *pX, *pKV;
    __half *pXh,*pXl,*pQh,*pQl,*pVth,*pVtl,*pOhh,*pOll,*pFh,*pFl;
    __half *pWqh,*pWql,*pWoh,*pWol,*pW1h,*pW1l,*pW2h,*pW2l,*pWkh,*pWkl,*pXoh,*pXol;
    cudaGetSymbolAddress((void**)&pX,  g_X);
    cudaGetSymbolAddress((void**)&pKV, g_KV);
    cudaGetSymbolAddress((void**)&pXh, g_Xh);   cudaGetSymbolAddress((void**)&pXl, g_Xl);
    cudaGetSymbolAddress((void**)&pQh, g_QKVh); cudaGetSymbolAddress((void**)&pQl, g_QKVl);
    cudaGetSymbolAddress((void**)&pVth,g_Vth);  cudaGetSymbolAddress((void**)&pVtl,g_Vtl);
    cudaGetSymbolAddress((void**)&pOhh,g_Oh);   cudaGetSymbolAddress((void**)&pOll,g_Ol);
    cudaGetSymbolAddress((void**)&pFh, g_FFh);  cudaGetSymbolAddress((void**)&pFl, g_FFl);
    cudaGetSymbolAddress((void**)&pWqh,g_Wqkvh);cudaGetSymbolAddress((void**)&pWql,g_Wqkvl);
    cudaGetSymbolAddress((void**)&pWoh,g_Woh);  cudaGetSymbolAddress((void**)&pWol,g_Wol);
    cudaGetSymbolAddress((void**)&pW1h,g_W1h);  cudaGetSymbolAddress((void**)&pW1l,g_W1l);
    cudaGetSymbolAddress((void**)&pW2h,g_W2h);  cudaGetSymbolAddress((void**)&pW2l,g_W2l);
    cudaGetSymbolAddress((void**)&pWkh,g_Wkvh); cudaGetSymbolAddress((void**)&pWkl,g_Wkvl);
    cudaGetSymbolAddress((void**)&pXoh,g_Xoh);  cudaGetSymbolAddress((void**)&pXol,g_Xol);

    cudaFuncSetAttribute(flash_attn, cudaFuncAttributeMaxDynamicSharedMemorySize, FLASH_SMEM);
    cudaFuncSetAttribute(gemm_hl<128,128,4,2>, cudaFuncAttributeMaxDynamicSharedMemorySize, gemm_smem(128,128));
    cudaFuncSetAttribute(gemm_hl<64,128,2,4>,  cudaFuncAttributeMaxDynamicSharedMemorySize, gemm_smem(64,128));

    // ---- setup (ordered so ncu -s 5 profiles the QKV GEMM) ----
    edge_stats<<<dim3(32, B_), 256>>>(ef);                               // 0
    edge_params<<<1, 32>>>(W_e, b_e, g_e, be_e);                         // 1
    pack_all<<<9920, 256>>>(Wq, Wk, Wv, Wo, W1, W2, Kd, Vd);             // 2
    init_x<<<cdiv(B_*N_*D_, 256), 256>>>(wf, tf, Wws, bws, Wwe, bwe, Wt, bt); // 3
    inorm_r<<<dim3(D_/32, B_, 8), dim3(32, 8)>>>(pX, g_wt, be_wt, pXh, pXl, N_); // 4

    const int Mrows = B_*N_;   // 4000

    for (int l = 0; l < L_; l++) {
        long long wq = (long long)l*3*D_*D_;
        // QKV: hi/lo halves + Vt scatter                                // 5 (ncu)
        gemm_hl<128,128,4,2><<<dim3(12, 32, 1), 256, gemm_smem(128,128)>>>(
            pXh, pXl, D_, 0,0,
            pWqh + wq, pWql + wq, D_, 0,0,
            nullptr, 0, 0,0,
            pQh, pQl, 3*D_, 0,0,
            nullptr, 0, 0,0, nullptr,
            Mrows, 3*D_, D_, 1, 1.f, 0, 1);
        // fused attention: edge bias + softmax + PV
        flash_attn<<<dim3(8, H_*B_), 256, FLASH_SMEM>>>(
            ef, pQh, pQl, pVth, pVtl, pOhh, pOll);
        // X = X + O @ Wo   (64x128 tiles: 252 CTAs)
        long long wo = (long long)l*D_*D_;
        gemm_hl<64,128,2,4><<<dim3(4, cdiv(Mrows,64), 1), 256, gemm_smem(64,128)>>>(
            pOhh, pOll, D_, 0,0,
            pWoh + wo, pWol + wo, D_, 0,0,
            pX, D_, 0,0,
            nullptr, nullptr, 0, 0,0,
            pX, D_, 0,0, nullptr,
            Mrows, D_, D_, 1, 1.f, 0, 0);
        inorm_r<<<dim3(D_/32, B_, 8), dim3(32, 8)>>>(pX, g1 + l*D_, be1 + l*D_, pXh, pXl, N_);
        // FF = relu(X @ W1 + b1)
        long long w1o = (long long)l*DFF_*D_;
        gemm_hl<128,128,4,2><<<dim3(16, 32, 1), 256, gemm_smem(128,128)>>>(
            pXh, pXl, D_, 0,0,
            pW1h + w1o, pW1l + w1o, D_, 0,0,
            nullptr, 0, 0,0,
            pFh, pFl, DFF_, 0,0,
            nullptr, 0, 0,0, b1 + l*DFF_,
            Mrows, DFF_, D_, 1, 1.f, 1, 0);
        // X = X + FF @ W2 + b2   (64x128 tiles: 252 CTAs)
        long long w2o = (long long)l*D_*DFF_;
        gemm_hl<64,128,2,4><<<dim3(4, cdiv(Mrows,64), 1), 256, gemm_smem(64,128)>>>(
            pFh, pFl, DFF_, 0,0,
            pW2h + w2o, pW2l + w2o, DFF_, 0,0,
            pX, D_, 0,0,
            nullptr, nullptr, 0, 0,0,
            pX, D_, 0,0, b2 + l*D_,
            Mrows, D_, DFF_, 1, 1.f, 0, 0);
        inorm_r<<<dim3(D_/32, B_, 8), dim3(32, 8)>>>(pX, g2 + l*D_, be2 + l*D_, pXh, pXl, N_);
    }

    write_xout<<<cdiv(B_*N1_*D_, 256), 256>>>(fin, outX);
    gemm_hl<128,128,4,2><<<dim3(8, 32, 1), 256, gemm_smem(128,128)>>>(
        pXoh, pXol, D_, 0,0,
        pWkh, pWkl, D_, 0,0,
        pKV, 2*D_, 0,0,
        nullptr, nullptr, 0, 0,0,
        nullptr, 0, 0,0, nullptr,
        B_*N1_, 2*D_, D_, 1, 1.f, 0, 0);
    write_kv<<<cdiv(H_*B_*N1_*HD_, 256), 256>>>(outK, outV);
}

// round 14
// speedup vs baseline: 2.6553x; 1.0217x over previous
#include <cuda_runtime.h>
#include <cuda_fp16.h>
#include <math.h>

// ---------------- problem constants ----------------
#define B_   4
#define NW_  100
#define NT_  800
#define N_   1000
#define N1_  1001
#define D_   512
#define H_   8
#define HD_  64
#define DFF_ 2048
#define L_   3
#define EPS_ 1e-5f
#define ALPHA_ 0.125f   // 1/sqrt(64)
#define NPAD_ 1024      // padded kv length for Vt

// ---------------- device scratch (no allocation allowed) ----------------
__device__ float  g_X   [B_*N_*D_];
__device__ float  g_KV  [B_*N1_*2*D_];
__device__ double g_part[B_*32*5];
__device__ float  g_ec0[32], g_ec1[32], g_ec2[32];

__device__ __align__(16) __half g_Xh [B_*N_*D_];
__device__ __align__(16) __half g_Xl [B_*N_*D_];
__device__ __align__(16) __half g_QKVh[B_*N_*3*D_];
__device__ __align__(16) __half g_QKVl[B_*N_*3*D_];
__device__ __align__(16) __half g_Vth[B_*D_*NPAD_];
__device__ __align__(16) __half g_Vtl[B_*D_*NPAD_];
__device__ __align__(16) __half g_Oh [B_*N_*D_];
__device__ __align__(16) __half g_Ol [B_*N_*D_];
__device__ __align__(16) __half g_FFh[B_*N_*DFF_];
__device__ __align__(16) __half g_FFl[B_*N_*DFF_];
__device__ __align__(16) __half g_Wqkvh[L_*3*D_*D_];
__device__ __align__(16) __half g_Wqkvl[L_*3*D_*D_];
__device__ __align__(16) __half g_Woh[L_*D_*D_];
__device__ __align__(16) __half g_Wol[L_*D_*D_];
__device__ __align__(16) __half g_W1h[L_*DFF_*D_];
__device__ __align__(16) __half g_W1l[L_*DFF_*D_];
__device__ __align__(16) __half g_W2h[L_*D_*DFF_];
__device__ __align__(16) __half g_W2l[L_*D_*DFF_];
__device__ __align__(16) __half g_Wkvh[2*D_*D_];
__device__ __align__(16) __half g_Wkvl[2*D_*D_];
__device__ __align__(16) __half g_Xoh[B_*N1_*D_];
__device__ __align__(16) __half g_Xol[B_*N1_*D_];

__device__ __forceinline__ void splitf(float v, __half &h, __half &l) {
    h = __float2half_rn(v);
    l = __float2half_rn(v - __half2float(h));
}

__device__ __forceinline__ void cp16(unsigned dst, const void* src, bool p) {
    int sz = p ? 16 : 0;
    asm volatile("cp.async.ca.shared.global [%0], [%1], 16, %2;\n"
                 :: "r"(dst), "l"(src), "r"(sz));
}

#define LDSM4(r0,r1,r2,r3,a) \
    asm volatile("ldmatrix.sync.aligned.m8n8.x4.shared.b16 {%0,%1,%2,%3}, [%4];" \
                 : "=r"(r0),"=r"(r1),"=r"(r2),"=r"(r3) : "r"(a))

#define MMA16816(acc,a0,a1,a2,a3,b0,b1) \
    asm volatile("mma.sync.aligned.m16n8k16.row.col.f32.f16.f16.f32 " \
                 "{%0,%1,%2,%3}, {%4,%5,%6,%7}, {%8,%9}, {%0,%1,%2,%3};" \
                 : "+f"((acc)[0]), "+f"((acc)[1]), "+f"((acc)[2]), "+f"((acc)[3]) \
                 : "r"(a0), "r"(a1), "r"(a2), "r"(a3), "r"(b0), "r"(b1))

// ---------------- split-fp16 GEMM: 3-stage cp.async pipeline ----------------
#define GSTAGES 3
constexpr int gemm_smem(int BM, int BN) { return GSTAGES*2*(BM+BN)*24*2; }

template<int BM, int BN, int WARPS_M, int WARPS_N>
__global__ __launch_bounds__(WARPS_M*WARPS_N*32, 2)
void gemm_hl(const __half* __restrict__ Ah, const __half* __restrict__ Al,
             int lda, long long sA1, long long sA0,
             const __half* __restrict__ Bh, const __half* __restrict__ Bl,
             int ldb, long long sB1, long long sB0,
             float* __restrict__ C, int ldc, long long sC1, long long sC0,
             __half* __restrict__ Ch, __half* __restrict__ Cl,
             int ldch, long long sCh1, long long sCh0,
             const float* __restrict__ addsrc, int ldadd, long long sD1, long long sD0,
             const float* __restrict__ bias,
             int M, int N, int K, int inner, float alpha,
             int relu, int qkv_mode)
{
    constexpr int BK = 16;
    constexpr int LDK = BK + 8;
    constexpr int WM = BM/WARPS_M, WN = BN/WARPS_N;
    constexpr int MT = WM/16, NT = WN/8;

    extern __shared__ __half sm_g[];
    __half* As = sm_g;                          // [S][2][BM][LDK]
    __half* Bs = sm_g + GSTAGES*2*BM*LDK;       // [S][2][BN][LDK]

    int z = blockIdx.z, z1 = z/inner, z0 = z%inner;
    Ah += z1*sA1 + z0*sA0;  Al += z1*sA1 + z0*sA0;
    Bh += z1*sB1 + z0*sB0;  Bl += z1*sB1 + z0*sB0;
    if (C)  C  += z1*sC1  + z0*sC0;
    if (Ch) { Ch += z1*sCh1 + z0*sCh0; Cl += z1*sCh1 + z0*sCh0; }

    int tid = threadIdx.x;
    int warp = tid>>5, lane = tid&31, g = lane>>2, tg = lane&3;
    int wm = (warp % WARPS_M)*WM, wn = (warp / WARPS_M)*WN;
    int row0 = blockIdx.y*BM, col0 = blockIdx.x*BN;

    const unsigned sAb = (unsigned)__cvta_generic_to_shared(As);
    const unsigned sBb = (unsigned)__cvta_generic_to_shared(Bs);

    float acc[MT][NT][4] = {};

    int aRow = (lane&7) + ((lane>>3)&1)*8;
    int aCol = ((lane>>4)&1)*8;
    int bRow = (lane&7) + ((lane>>4)&1)*8;
    int bCol = ((lane>>3)&1)*8;

    auto issue = [&](int kt, int s) {
        if (tid < BM*2) {
            int row = tid>>1, ch = (tid&1)*8;
            bool p = (row0+row) < M;
            long long go = (long long)(row0+row)*lda + kt + ch;
            cp16(sAb + (unsigned)((((s*2+0)*BM + row)*LDK + ch)*2), Ah + go, p);
            cp16(sAb + (unsigned)((((s*2+1)*BM + row)*LDK + ch)*2), Al + go, p);
        }
        if (tid < BN*2) {
            int row = tid>>1, ch = (tid&1)*8;
            bool p = (col0+row) < N;
            long long go = (long long)(col0+row)*ldb + kt + ch;
            cp16(sBb + (unsigned)((((s*2+0)*BN + row)*LDK + ch)*2), Bh + go, p);
            cp16(sBb + (unsigned)((((s*2+1)*BN + row)*LDK + ch)*2), Bl + go, p);
        }
        asm volatile("cp.async.commit_group;");
    };

    auto compute = [&](int s) {
        unsigned ah[MT][4], al[MT][4];
        #pragma unroll
        for (int mt = 0; mt < MT; mt++) {
            int r = wm + mt*16 + aRow;
            LDSM4(ah[mt][0], ah[mt][1], ah[mt][2], ah[mt][3],
                  sAb + (unsigned)((((s*2+0)*BM + r)*LDK + aCol)*2));
            LDSM4(al[mt][0], al[mt][1], al[mt][2], al[mt][3],
                  sAb + (unsigned)((((s*2+1)*BM + r)*LDK + aCol)*2));
        }
        #pragma unroll
        for (int nt2 = 0; nt2 < NT/2; nt2++) {
            int rB = wn + nt2*16 + bRow;
            unsigned bh0,bh1,bh2,bh3, bl0,bl1,bl2,bl3;
            LDSM4(bh0,bh1,bh2,bh3, sBb + (unsigned)((((s*2+0)*BN + rB)*LDK + bCol)*2));
            LDSM4(bl0,bl1,bl2,bl3, sBb + (unsigned)((((s*2+1)*BN + rB)*LDK + bCol)*2));
            #pragma unroll
            for (int mt = 0; mt < MT; mt++) {
                MMA16816(acc[mt][nt2*2], ah[mt][0],ah[mt][1],ah[mt][2],ah[mt][3], bh0,bh1);
                MMA16816(acc[mt][nt2*2], ah[mt][0],ah[mt][1],ah[mt][2],ah[mt][3], bl0,bl1);
                MMA16816(acc[mt][nt2*2], al[mt][0],al[mt][1],al[mt][2],al[mt][3], bh0,bh1);
            }
            #pragma unroll
            for (int mt = 0; mt < MT; mt++) {
                MMA16816(acc[mt][nt2*2+1], ah[mt][0],ah[mt][1],ah[mt][2],ah[mt][3], bh2,bh3);
                MMA16816(acc[mt][nt2*2+1], ah[mt][0],ah[mt][1],ah[mt][2],ah[mt][3], bl2,bl3);
                MMA16816(acc[mt][nt2*2+1], al[mt][0],al[mt][1],al[mt][2],al[mt][3], bh2,bh3);
            }
        }
    };

    const int T = K / BK;
    issue(0, 0);
    if (T > 1) issue(BK, 1);
    for (int i = 0; i < T; i++) {
        if (i + 1 < T) { asm volatile("cp.async.wait_group 1;"); }
        else           { asm volatile("cp.async.wait_group 0;"); }
        __syncthreads();
        if (i + 2 < T) issue((i+2)*BK, (i+2)%GSTAGES);
        compute(i % GSTAGES);
    }

    if (addsrc) addsrc += z1*sD1 + z0*sD0;

    #pragma unroll
    for (int mt = 0; mt < MT; mt++) {
        #pragma unroll
        for (int nt = 0; nt < NT; nt++) {
            int nb = col0 + wn + nt*8 + tg*2;
            #pragma unroll
            for (int h2 = 0; h2 < 2; h2++) {
                int m = row0 + wm + mt*16 + g + h2*8;
                if (m >= M) continue;
                #pragma unroll
                for (int j = 0; j < 2; j++) {
                    int n = nb + j;
                    if (n >= N) continue;
                    float v = alpha * acc[mt][nt][h2*2+j];
                    if (bias)   v += bias[n];
                    if (addsrc) v += addsrc[(long long)m*ldadd + n];
                    if (relu) v = fmaxf(v, 0.f);
                    if (C) C[(long long)m*ldc + n] = v;
                    if (Ch) {
                        __half hh, ll; splitf(v, hh, ll);
                        Ch[(long long)m*ldch + n] = hh;
                        Cl[(long long)m*ldch + n] = ll;
                        if (qkv_mode && n >= 1024) {
                            int b = m / N_, mm = m - b*N_;
                            long long vi = ((long long)b*D_ + (n-1024))*NPAD_ + mm;
                            g_Vth[vi] = hh; g_Vtl[vi] = ll;
                        }
                    }
                }
            }
        }
    }
}

// ---------------- flash attention (double-buffered KV) ----------------
#define LDKQ 72
#define LDVV 136
#define FBUF (2*128*LDKQ + 2*64*LDVV)            // halves per buffer
#define FLASH_SMEM (2*FBUF*2)                    // bytes, 2 buffers

__global__ __launch_bounds__(256,1)
void flash_attn(const float* __restrict__ ef,
                const __half* __restrict__ QKVh, const __half* __restrict__ QKVl,
                const __half* __restrict__ Vth,  const __half* __restrict__ Vtl,
                __half* __restrict__ Oh, __half* __restrict__ Ol)
{
    extern __shared__ __half sm_[];

    const int qb = blockIdx.x;
    const int z  = blockIdx.y;
    const int h  = z / B_, b = z % B_;
    const int row0 = qb*128;
    const int tid = threadIdx.x, warp = tid>>5, lane = tid&31;
    const int g = lane>>2, tg = lane&3;
    const int aRow = (lane&7) + ((lane>>3)&1)*8;
    const int aCol = ((lane>>4)&1)*8;
    const int bRow = (lane&7) + ((lane>>4)&1)*8;
    const int bCol = ((lane>>3)&1)*8;

    const unsigned sBase = (unsigned)__cvta_generic_to_shared(sm_);
    auto sKh = [&](int bf){ return sBase + (unsigned)(bf*FBUF*2); };
    auto sKl = [&](int bf){ return sBase + (unsigned)((bf*FBUF + 128*LDKQ)*2); };
    auto sVh = [&](int bf){ return sBase + (unsigned)((bf*FBUF + 2*128*LDKQ)*2); };
    auto sVl = [&](int bf){ return sBase + (unsigned)((bf*FBUF + 2*128*LDKQ + 64*LDVV)*2); };

    // ---- stage Q tile through buffer-0 K region into registers ----
    #pragma unroll
    for (int i = 0; i < 4; i++) {
        int idx = tid + i*256;
        int r = idx >> 3, ch = (idx & 7)*8;
        int m = row0 + r;
        bool p = m < N_;
        long long go = (long long)(b*N_ + (p ? m : 0))*(3*D_) + h*HD_ + ch;
        cp16(sKh(0) + (unsigned)((r*LDKQ + ch)*2), QKVh + go, p);
        cp16(sKl(0) + (unsigned)((r*LDKQ + ch)*2), QKVl + go, p);
    }
    asm volatile("cp.async.commit_group;");
    asm volatile("cp.async.wait_group 0;");
    __syncthreads();

    unsigned qh[4][4], ql[4][4];
    #pragma unroll
    for (int ks = 0; ks < 4; ks++) {
        LDSM4(qh[ks][0],qh[ks][1],qh[ks][2],qh[ks][3],
              sKh(0) + (unsigned)(((warp*16 + aRow)*LDKQ + ks*16 + aCol)*2));
        LDSM4(ql[ks][0],ql[ks][1],ql[ks][2],ql[ks][3],
              sKl(0) + (unsigned)(((warp*16 + aRow)*LDKQ + ks*16 + aCol)*2));
    }
    __syncthreads();

    auto issue_kv = [&](int kt, int bf) {
        const int kv0 = kt*128;
        #pragma unroll
        for (int i = 0; i < 4; i++) {
            int idx = tid + i*256;
            int r = idx >> 3, ch = (idx & 7)*8;
            int kv = kv0 + r;
            bool p = kv < N_;
            long long go = (long long)(b*N_ + (p ? kv : 0))*(3*D_) + D_ + h*HD_ + ch;
            cp16(sKh(bf) + (unsigned)((r*LDKQ + ch)*2), QKVh + go, p);
            cp16(sKl(bf) + (unsigned)((r*LDKQ + ch)*2), QKVl + go, p);
        }
        #pragma unroll
        for (int i = 0; i < 4; i++) {
            int idx = tid + i*256;
            int r = idx >> 4, ch = (idx & 15)*8;
            long long go = (long long)(b*D_ + h*HD_ + r)*NPAD_ + kv0 + ch;
            cp16(sVh(bf) + (unsigned)((r*LDVV + ch)*2), Vth + go, true);
            cp16(sVl(bf) + (unsigned)((r*LDVV + ch)*2), Vtl + go, true);
        }
        asm volatile("cp.async.commit_group;");
    };

    float oacc[8][4] = {};
    float rmax0 = -1e30f, rmax1 = -1e30f, rsum0 = 0.f, rsum1 = 0.f;
    const int te = b*H_ + h;
    const float ec0 = g_ec0[te], ec1 = g_ec1[te], ec2 = g_ec2[te];
    const float2* e2 = (const float2*)ef + (long long)b*N_*N_;
    const int r0g = row0 + warp*16 + g;
    const int r1g = r0g + 8;
    const long long er0 = (long long)(r0g < N_ ? r0g : N_-1) * N_;
    const long long er1 = (long long)(r1g < N_ ? r1g : N_-1) * N_;

    issue_kv(0, 0);
    issue_kv(1, 1);

    for (int kt = 0; kt < 8; kt++) {
        const int kv0 = kt*128;
        const int bf = kt & 1;
        if (kt < 7) { asm volatile("cp.async.wait_group 1;"); }
        else        { asm volatile("cp.async.wait_group 0;"); }
        __syncthreads();

        // S = Q @ K^T (split-fp16, fp32 acc)
        float s[16][4];
        #pragma unroll
        for (int i = 0; i < 16; i++) { s[i][0]=s[i][1]=s[i][2]=s[i][3]=0.f; }
        #pragma unroll
        for (int ks = 0; ks < 4; ks++) {
            #pragma unroll
            for (int nt2 = 0; nt2 < 8; nt2++) {
                unsigned bh0,bh1,bh2,bh3, bl0,bl1,bl2,bl3;
                LDSM4(bh0,bh1,bh2,bh3, sKh(bf) + (unsigned)(((nt2*16+bRow)*LDKQ + ks*16 + bCol)*2));
                LDSM4(bl0,bl1,bl2,bl3, sKl(bf) + (unsigned)(((nt2*16+bRow)*LDKQ + ks*16 + bCol)*2));
                MMA16816(s[nt2*2],   qh[ks][0],qh[ks][1],qh[ks][2],qh[ks][3], bh0,bh1);
                MMA16816(s[nt2*2],   qh[ks][0],qh[ks][1],qh[ks][2],qh[ks][3], bl0,bl1);
                MMA16816(s[nt2*2],   ql[ks][0],ql[ks][1],ql[ks][2],ql[ks][3], bh0,bh1);
                MMA16816(s[nt2*2+1], qh[ks][0],qh[ks][1],qh[ks][2],qh[ks][3], bh2,bh3);
                MMA16816(s[nt2*2+1], qh[ks][0],qh[ks][1],qh[ks][2],qh[ks][3], bl2,bl3);
                MMA16816(s[nt2*2+1], ql[ks][0],ql[ks][1],ql[ks][2],ql[ks][3], bh2,bh3);
            }
        }

        // edge bias + mask + online softmax
        float tm0 = -1e30f, tm1 = -1e30f;
        #pragma unroll
        for (int nt = 0; nt < 16; nt++) {
            int c = nt*8 + 2*tg;
            int n = kv0 + c;
            bool v0 = (n < N_), v1 = (n+1 < N_);
            long long ei0 = v0 ? n : (N_-1);
            long long ei1 = v1 ? (n+1) : (N_-1);
            float2 f00 = e2[er0 + ei0], f01 = e2[er0 + ei1];
            float2 f10 = e2[er1 + ei0], f11 = e2[er1 + ei1];
            s[nt][0] = v0 ? ALPHA_*s[nt][0] + f00.x*ec0 + f00.y*ec1 + ec2 : -1e30f;
            s[nt][1] = v1 ? ALPHA_*s[nt][1] + f01.x*ec0 + f01.y*ec1 + ec2 : -1e30f;
            s[nt][2] = v0 ? ALPHA_*s[nt][2] + f10.x*ec0 + f10.y*ec1 + ec2 : -1e30f;
            s[nt][3] = v1 ? ALPHA_*s[nt][3] + f11.x*ec0 + f11.y*ec1 + ec2 : -1e30f;
            tm0 = fmaxf(tm0, fmaxf(s[nt][0], s[nt][1]));
            tm1 = fmaxf(tm1, fmaxf(s[nt][2], s[nt][3]));
        }
        tm0 = fmaxf(tm0, __shfl_xor_sync(0xffffffffu, tm0, 1));
        tm0 = fmaxf(tm0, __shfl_xor_sync(0xffffffffu, tm0, 2));
        tm1 = fmaxf(tm1, __shfl_xor_sync(0xffffffffu, tm1, 1));
        tm1 = fmaxf(tm1, __shfl_xor_sync(0xffffffffu, tm1, 2));
        float nm0 = fmaxf(rmax0, tm0), nm1 = fmaxf(rmax1, tm1);
        float sc0 = __expf(rmax0 - nm0), sc1 = __expf(rmax1 - nm1);
        rmax0 = nm0; rmax1 = nm1;
        #pragma unroll
        for (int nt = 0; nt < 8; nt++) {
            oacc[nt][0]*=sc0; oacc[nt][1]*=sc0; oacc[nt][2]*=sc1; oacc[nt][3]*=sc1;
        }
        float ps0 = 0.f, ps1 = 0.f;
        #pragma unroll
        for (int nt = 0; nt < 16; nt++) {
            s[nt][0] = __expf(s[nt][0]-nm0); s[nt][1] = __expf(s[nt][1]-nm0);
            s[nt][2] = __expf(s[nt][2]-nm1); s[nt][3] = __expf(s[nt][3]-nm1);
            ps0 += s[nt][0]+s[nt][1]; ps1 += s[nt][2]+s[nt][3];
        }
        ps0 += __shfl_xor_sync(0xffffffffu, ps0, 1);
        ps0 += __shfl_xor_sync(0xffffffffu, ps0, 2);
        ps1 += __shfl_xor_sync(0xffffffffu, ps1, 1);
        ps1 += __shfl_xor_sync(0xffffffffu, ps1, 2);
        rsum0 = rsum0*sc0 + ps0;
        rsum1 = rsum1*sc1 + ps1;

        // O += P @ V  (P converted in-register to hi/lo A fragments)
        #pragma unroll
        for (int s8 = 0; s8 < 8; s8++) {
            unsigned pa[4], pb[4];
            #pragma unroll
            for (int j = 0; j < 2; j++) {
                float x0 = s[2*s8+j][0], x1 = s[2*s8+j][1];
                float x2 = s[2*s8+j][2], x3 = s[2*s8+j][3];
                __half2 h0 = __floats2half2_rn(x0, x1);
                __half2 h1 = __floats2half2_rn(x2, x3);
                float2 k0 = __half22float2(h0);
                float2 k1 = __half22float2(h1);
                __half2 l0 = __floats2half2_rn(x0-k0.x, x1-k0.y);
                __half2 l1 = __floats2half2_rn(x2-k1.x, x3-k1.y);
                pa[j*2+0] = *(unsigned*)&h0; pa[j*2+1] = *(unsigned*)&h1;
                pb[j*2+0] = *(unsigned*)&l0; pb[j*2+1] = *(unsigned*)&l1;
            }
            #pragma unroll
            for (int nt2 = 0; nt2 < 4; nt2++) {
                unsigned vh0,vh1,vh2,vh3, vl0,vl1,vl2,vl3;
                LDSM4(vh0,vh1,vh2,vh3, sVh(bf) + (unsigned)(((nt2*16+bRow)*LDVV + s8*16 + bCol)*2));
                LDSM4(vl0,vl1,vl2,vl3, sVl(bf) + (unsigned)(((nt2*16+bRow)*LDVV + s8*16 + bCol)*2));
                MMA16816(oacc[nt2*2],   pa[0],pa[1],pa[2],pa[3], vh0,vh1);
                MMA16816(oacc[nt2*2],   pa[0],pa[1],pa[2],pa[3], vl0,vl1);
                MMA16816(oacc[nt2*2],   pb[0],pb[1],pb[2],pb[3], vh0,vh1);
                MMA16816(oacc[nt2*2+1], pa[0],pa[1],pa[2],pa[3], vh2,vh3);
                MMA16816(oacc[nt2*2+1], pa[0],pa[1],pa[2],pa[3], vl2,vl3);
                MMA16816(oacc[nt2*2+1], pb[0],pb[1],pb[2],pb[3], vh2,vh3);
            }
        }
        __syncthreads();
        if (kt + 2 < 8) issue_kv(kt + 2, bf);
    }

    float i0 = 1.f / rsum0, i1 = 1.f / rsum1;
    #pragma unroll
    for (int nt = 0; nt < 8; nt++) {
        int c = h*HD_ + nt*8 + 2*tg;
        if (r0g < N_) {
            float a = oacc[nt][0]*i0, bb = oacc[nt][1]*i0;
            __half2 hh = __floats2half2_rn(a, bb);
            float2 bk = __half22float2(hh);
            __half2 ll = __floats2half2_rn(a-bk.x, bb-bk.y);
            *(__half2*)&Oh[(long long)(b*N_+r0g)*D_ + c] = hh;
            *(__half2*)&Ol[(long long)(b*N_+r0g)*D_ + c] = ll;
        }
        if (r1g < N_) {
            float a = oacc[nt][2]*i1, bb = oacc[nt][3]*i1;
            __half2 hh = __floats2half2_rn(a, bb);
            float2 bk = __half22float2(hh);
            __half2 ll = __floats2half2_rn(a-bk.x, bb-bk.y);
            *(__half2*)&Oh[(long long)(b*N_+r1g)*D_ + c] = hh;
            *(__half2*)&Ol[(long long)(b*N_+r1g)*D_ + c] = ll;
        }
    }
}

// ---------------- InstanceNorm1d: redundant stats, sliced normalize ----------
__global__ void inorm_r(float* __restrict__ X, const float* __restrict__ g,
                        const float* __restrict__ be,
                        __half* __restrict__ Xh, __half* __restrict__ Xl, int Nrows)
{
    int b = blockIdx.y;
    int zz = blockIdx.z;
    int c = blockIdx.x * 32 + threadIdx.x;
    int ty = threadIdx.y;
    long long base = (long long)b * Nrows * D_;
    float* Xb = X + base;
    float s = 0.f, q = 0.f;
    for (int n = ty; n < Nrows; n += 8) {
        float x = Xb[(long long)n * D_ + c];
        s += x; q += x * x;
    }
    __shared__ float sh_s[8][32], sh_q[8][32];
    sh_s[ty][threadIdx.x] = s; sh_q[ty][threadIdx.x] = q;
    __syncthreads();
    __shared__ float sh_m[32], sh_r[32];
    if (ty == 0) {
        float S = 0.f, Q = 0.f;
        #pragma unroll
        for (int i = 0; i < 8; i++) { S += sh_s[i][threadIdx.x]; Q += sh_q[i][threadIdx.x]; }
        float mean = S / (float)Nrows;
        float var  = Q / (float)Nrows - mean*mean;
        sh_m[threadIdx.x] = mean;
        sh_r[threadIdx.x] = rsqrtf(var + EPS_);
    }
    __syncthreads();
    float mean = sh_m[threadIdx.x], r = sh_r[threadIdx.x];
    float gg = g[c], bb = be[c];
    int chunk = (Nrows + 7) / 8;
    int n0 = zz * chunk;
    int n1 = min(n0 + chunk, Nrows);
    for (int n = n0 + ty; n < n1; n += 8) {
        long long idx = (long long)n * D_ + c;
        float v = gg * (Xb[idx] - mean) * r + bb;
        Xb[idx] = v;
        __half hh, ll; splitf(v, hh, ll);
        Xh[base + idx] = hh; Xl[base + idx] = ll;
    }
}

// ---------------- input projections + concat ----------------
__global__ void init_x(const float* __restrict__ wf, const float* __restrict__ tf,
                       const float* __restrict__ Wws, const float* __restrict__ bws,
                       const float* __restrict__ Wwe, const float* __restrict__ bwe,
                       const float* __restrict__ Wt,  const float* __restrict__ bt)
{
    int t = blockIdx.x * blockDim.x + threadIdx.x;
    if (t >= B_*N_*D_) return;
    int d = t & 511;
    int n = (t >> 9) % N_;
    int b = t / (D_*N_);
    float v;
    if (n < NW_) {
        const float* f = wf + (b*NW_ + n)*4;
        v = bws[d];
        #pragma unroll
        for (int k = 0; k < 4; k++) v += f[k] * Wws[k*D_ + d];
    } else if (n < 2*NW_) {
        const float* f = wf + (b*NW_ + (n - NW_))*4;
        v = bwe[d];
        #pragma unroll
        for (int k = 0; k < 4; k++) v += f[k] * Wwe[k*D_ + d];
    } else {
        const float* f = tf + (b*NT_ + (n - 2*NW_))*8;
        v = bt[d];
        #pragma unroll
        for (int k = 0; k < 8; k++) v += f[k] * Wt[k*D_ + d];
    }
    g_X[t] = v;
}

// ---------------- edge bias: per-block partial moments (no atomics) -----------
__global__ __launch_bounds__(256)
void edge_stats(const float* __restrict__ ef)
{
    int b = blockIdx.y;
    int blk = blockIdx.x;            // 0..31
    const float2* p = (const float2*)ef + (long long)b * (N_*N_);
    int stride = gridDim.x * blockDim.x;
    float s0=0,s1=0,s00=0,s11=0,s01=0;
    for (int i = blk*blockDim.x + threadIdx.x; i < N_*N_; i += stride) {
        float2 f = p[i];
        s0 += f.x; s1 += f.y; s00 += f.x*f.x; s11 += f.y*f.y; s01 += f.x*f.y;
    }
    __shared__ double red[256];
    double loc[5] = {(double)s0,(double)s1,(double)s00,(double)s11,(double)s01};
    for (int j = 0; j < 5; j++) {
        red[threadIdx.x] = loc[j];
        __syncthreads();
        for (int s = 128; s > 0; s >>= 1) { if (threadIdx.x < s) red[threadIdx.x] += red[threadIdx.x+s]; __syncthreads(); }
        if (threadIdx.x == 0) g_part[(b*32 + blk)*5 + j] = red[0];
        __syncthreads();
    }
}

__global__ void edge_params(const float* __restrict__ We, const float* __restrict__ be,
                            const float* __restrict__ ge, const float* __restrict__ bee)
{
    int t = threadIdx.x;
    if (t >= B_*H_) return;
    int b = t / H_, h = t % H_;
    double mm[5];
    for (int j = 0; j < 5; j++) {
        double acc = 0.0;
        for (int blk = 0; blk < 32; blk++) acc += g_part[(b*32 + blk)*5 + j];
        mm[j] = acc;
    }
    double cnt = (double)N_ * (double)N_;
    double m0  = mm[0]/cnt, m1 = mm[1]/cnt;
    double v00 = mm[2]/cnt - m0*m0;
    double v11 = mm[3]/cnt - m1*m1;
    double v01 = mm[4]/cnt - m0*m1;
    double w0 = We[0*H_+h], w1 = We[1*H_+h];
    double mean = w0*m0 + w1*m1 + (double)be[h];
    double var  = w0*w0*v00 + 2.0*w0*w1*v01 + w1*w1*v11;
    double grs  = (double)ge[h] / sqrt(var + (double)EPS_);
    g_ec0[t] = (float)(w0*grs);
    g_ec1[t] = (float)(w1*grs);
    g_ec2[t] = (float)(((double)be[h] - mean)*grs + (double)bee[h]);
}

// ---------------- unified weight pack: tiled transpose + split ----------------
__global__ __launch_bounds__(256)
void pack_all(const float* __restrict__ Wq, const float* __restrict__ Wk,
              const float* __restrict__ Wv, const float* __restrict__ Wo,
              const float* __restrict__ W1, const float* __restrict__ W2,
              const float* __restrict__ Kd, const float* __restrict__ Vd)
{
    int t = blockIdx.x;
    int tx = threadIdx.x & 31, ty = threadIdx.x >> 5;

    if (t >= 9728) {          // Section F: zero Vt pad
        int idx = (t - 9728) * 256 + threadIdx.x;     // 0..49151
        int r = idx / (NPAD_ - N_);
        int c = N_ + idx % (NPAD_ - N_);
        __half zz = __float2half(0.f);
        g_Vth[(long long)r*NPAD_ + c] = zz;
        g_Vtl[(long long)r*NPAD_ + c] = zz;
        return;
    }

    const float* src; __half *dh, *dl;
    int C, dstStride; long long srcOff = 0, dstOff = 0;
    int tr, tc;

    if (t < 2304) {           // A: QKV
        int batch = t >> 5, w = t & 31;
        tr = w & 15; tc = w >> 4;
        int l = batch / 24, r24 = batch % 24, sec = r24 >> 3, h = r24 & 7;
        src = (sec == 0) ? Wq : (sec == 1) ? Wk : Wv;
        srcOff = (long long)(l*8 + h) * 32768;
        C = 64; dstStride = 512;
        dh = g_Wqkvh; dl = g_Wqkvl;
        dstOff = (long long)l*786432 + (long long)(sec*512 + h*64)*512;
    } else if (t < 3072) {    // B: Wo
        int t2 = t - 2304;
        int l = t2 >> 8, w = t2 & 255;
        tr = w & 15; tc = w >> 4;
        src = Wo; srcOff = (long long)l*262144;
        C = 512; dstStride = 512;
        dh = g_Woh; dl = g_Wol; dstOff = (long long)l*262144;
    } else if (t < 6144) {    // C: W1 512x2048
        int t2 = t - 3072;
        int l = t2 >> 10, w = t2 & 1023;
        tr = w & 15; tc = w >> 4;
        src = W1; srcOff = (long long)l*1048576;
        C = 2048; dstStride = 512;
        dh = g_W1h; dl = g_W1l; dstOff = (long long)l*1048576;
    } else if (t < 9216) {    // D: W2 2048x512
        int t2 = t - 6144;
        int l = t2 >> 10, w = t2 & 1023;
        tr = w & 63; tc = w >> 6;
        src = W2; srcOff = (long long)l*1048576;
        C = 512; dstStride = 2048;
        dh = g_W2h; dl = g_W2l; dstOff = (long long)l*1048576;
    } else {                  // E: KV
        int t2 = t - 9216;
        int batch = t2 >> 5, w = t2 & 31;
        tr = w & 15; tc = w >> 4;
        int sec = batch >> 3, h = batch & 7;
        src = sec ? Vd : Kd;
        srcOff = (long long)h * 32768;
        C = 64; dstStride = 512;
        dh = g_Wkvh; dl = g_Wkvl;
        dstOff = (long long)(sec*512 + h*64)*512;
    }

    __shared__ float tile[32][33];
    #pragma unroll
    for (int i = 0; i < 4; i++) {
        int r = tr*32 + ty + i*8;
        int c = tc*32 + tx;
        tile[ty + i*8][tx] = src[srcOff + (long long)r*C + c];
    }
    __syncthreads();
    #pragma unroll
    for (int i = 0; i < 4; i++) {
        int n = tc*32 + ty + i*8;
        int k = tr*32 + tx;
        float v = tile[tx][ty + i*8];
        __half hh, ll; splitf(v, hh, ll);
        long long di = dstOff + (long long)n*dstStride + k;
        dh[di] = hh; dl[di] = ll;
    }
}

// ---------------- finish token append into output X (+ hi/lo) ----------------
__global__ void write_xout(const float* __restrict__ fin, float* __restrict__ out)
{
    int t = blockIdx.x * blockDim.x + threadIdx.x;
    if (t >= B_*N1_*D_) return;
    int d = t & 511;
    int n = (t >> 9) % N1_;
    int b = t / (N1_*D_);
    float v = (n < N_) ? g_X[((long long)b*N_ + n)*D_ + d] : fin[d];
    out[t] = v;
    splitf(v, g_Xoh[t], g_Xol[t]);
}

// ---------------- reorder decode K/V to [H][B][N1][HD] ----------------
__global__ void write_kv(float* __restrict__ outK, float* __restrict__ outV)
{
    int t = blockIdx.x * blockDim.x + threadIdx.x;
    if (t >= H_*B_*N1_*HD_) return;
    int e = t & 63;
    int n = (t >> 6) % N1_;
    int rem = t / (HD_*N1_);
    int b = rem & 3;
    int h = rem >> 2;
    long long src = ((long long)(b*N1_ + n))*(2*D_) + h*HD_ + e;
    outK[t] = g_KV[src];
    outV[t] = g_KV[src + D_];
}

// ---------------- host orchestration ----------------
static inline int cdiv(int a, int b) { return (a + b - 1) / b; }

extern "C" void kernel_launch(void* const* d_in, const int* in_sizes, int n_in,
                              void* d_out, int out_size)
{
    const float* wf   = (const float*)d_in[0];
    const float* tf   = (const float*)d_in[1];
    const float* ef   = (const float*)d_in[2];
    const float* Wws  = (const float*)d_in[3];
    const float* bws  = (const float*)d_in[4];
    const float* Wwe  = (const float*)d_in[5];
    const float* bwe  = (const float*)d_in[6];
    const float* Wt   = (const float*)d_in[7];
    const float* bt   = (const float*)d_in[8];
    const float* g_wt = (const float*)d_in[9];
    const float* be_wt= (const float*)d_in[10];
    const float* W_e  = (const float*)d_in[11];
    const float* b_e  = (const float*)d_in[12];
    const float* g_e  = (const float*)d_in[13];
    const float* be_e = (const float*)d_in[14];
    const float* Wq   = (const float*)d_in[15];
    const float* Wk   = (const float*)d_in[16];
    const float* Wv   = (const float*)d_in[17];
    const float* Wo   = (const float*)d_in[18];
    const float* W1   = (const float*)d_in[19];
    const float* b1   = (const float*)d_in[20];
    const float* W2   = (const float*)d_in[21];
    const float* b2   = (const float*)d_in[22];
    const float* g1   = (const float*)d_in[23];
    const float* be1  = (const float*)d_in[24];
    const float* g2   = (const float*)d_in[25];
    const float* be2  = (const float*)d_in[26];
    const float* fin  = (const float*)d_in[27];
    const float* Kd   = (const float*)d_in[28];
    const float* Vd   = (const float*)d_in[29];

    float* out  = (float*)d_out;
    float* outX = out;
    float* outK = out + (size_t)B_*N1_*D_;
    float* outV = outK + (size_t)H_*B_*N1_*HD_;

    float *pX, *pKV;
    __half *pXh,*pXl,*pQh,*pQl,*pVth,*pVtl,*pOhh,*pOll,*pFh,*pFl;
    __half *pWqh,*pWql,*pWoh,*pWol,*pW1h,*pW1l,*pW2h,*pW2l,*pWkh,*pWkl,*pXoh,*pXol;
    cudaGetSymbolAddress((void**)&pX,  g_X);
    cudaGetSymbolAddress((void**)&pKV, g_KV);
    cudaGetSymbolAddress((void**)&pXh, g_Xh);   cudaGetSymbolAddress((void**)&pXl, g_Xl);
    cudaGetSymbolAddress((void**)&pQh, g_QKVh); cudaGetSymbolAddress((void**)&pQl, g_QKVl);
    cudaGetSymbolAddress((void**)&pVth,g_Vth);  cudaGetSymbolAddress((void**)&pVtl,g_Vtl);
    cudaGetSymbolAddress((void**)&pOhh,g_Oh);   cudaGetSymbolAddress((void**)&pOll,g_Ol);
    cudaGetSymbolAddress((void**)&pFh, g_FFh);  cudaGetSymbolAddress((void**)&pFl, g_FFl);
    cudaGetSymbolAddress((void**)&pWqh,g_Wqkvh);cudaGetSymbolAddress((void**)&pWql,g_Wqkvl);
    cudaGetSymbolAddress((void**)&pWoh,g_Woh);  cudaGetSymbolAddress((void**)&pWol,g_Wol);
    cudaGetSymbolAddress((void**)&pW1h,g_W1h);  cudaGetSymbolAddress((void**)&pW1l,g_W1l);
    cudaGetSymbolAddress((void**)&pW2h,g_W2h);  cudaGetSymbolAddress((void**)&pW2l,g_W2l);
    cudaGetSymbolAddress((void**)&pWkh,g_Wkvh); cudaGetSymbolAddress((void**)&pWkl,g_Wkvl);
    cudaGetSymbolAddress((void**)&pXoh,g_Xoh);  cudaGetSymbolAddress((void**)&pXol,g_Xol);

    cudaFuncSetAttribute(flash_attn, cudaFuncAttributeMaxDynamicSharedMemorySize, FLASH_SMEM);
    cudaFuncSetAttribute(gemm_hl<128,128,4,2>, cudaFuncAttributeMaxDynamicSharedMemorySize, gemm_smem(128,128));
    cudaFuncSetAttribute(gemm_hl<64,128,2,4>,  cudaFuncAttributeMaxDynamicSharedMemorySize, gemm_smem(64,128));

    const int Mrows = B_*N_;   // 4000

    // ---- setup, ordered so my launch index 3 == first QKV GEMM (ncu target) ----
    pack_all<<<9920, 256>>>(Wq, Wk, Wv, Wo, W1, W2, Kd, Vd);                   // 0
    init_x<<<cdiv(B_*N_*D_, 256), 256>>>(wf, tf, Wws, bws, Wwe, bwe, Wt, bt);  // 1
    inorm_r<<<dim3(D_/32, B_, 8), dim3(32, 8)>>>(pX, g_wt, be_wt, pXh, pXl, N_); // 2

    for (int l = 0; l < L_; l++) {
        long long wq = (long long)l*3*D_*D_;
        // QKV: hi/lo halves + Vt scatter                                      // 3 (ncu on l=0)
        gemm_hl<128,128,4,2><<<dim3(12, 32, 1), 256, gemm_smem(128,128)>>>(
            pXh, pXl, D_, 0,0,
            pWqh + wq, pWql + wq, D_, 0,0,
            nullptr, 0, 0,0,
            pQh, pQl, 3*D_, 0,0,
            nullptr, 0, 0,0, nullptr,
            Mrows, 3*D_, D_, 1, 1.f, 0, 1);
        if (l == 0) {
            // edge coefficient pipeline (needed before flash only)
            edge_stats<<<dim3(32, B_), 256>>>(ef);
            edge_params<<<1, 32>>>(W_e, b_e, g_e, be_e);
        }
        // fused attention: edge bias + softmax + PV
        flash_attn<<<dim3(8, H_*B_), 256, FLASH_SMEM>>>(
            ef, pQh, pQl, pVth, pVtl, pOhh, pOll);
        // X = X + O @ Wo   (64x128 tiles: 252 CTAs)
        long long wo = (long long)l*D_*D_;
        gemm_hl<64,128,2,4><<<dim3(4, cdiv(Mrows,64), 1), 256, gemm_smem(64,128)>>>(
            pOhh, pOll, D_, 0,0,
            pWoh + wo, pWol + wo, D_, 0,0,
            pX, D_, 0,0,
            nullptr, nullptr, 0, 0,0,
            pX, D_, 0,0, nullptr,
            Mrows, D_, D_, 1, 1.f, 0, 0);
        inorm_r<<<dim3(D_/32, B_, 8), dim3(32, 8)>>>(pX, g1 + l*D_, be1 + l*D_, pXh, pXl, N_);
        // FF = relu(X @ W1 + b1)
        long long w1o = (long long)l*DFF_*D_;
        gemm_hl<128,128,4,2><<<dim3(16, 32, 1), 256, gemm_smem(128,128)>>>(
            pXh, pXl, D_, 0,0,
            pW1h + w1o, pW1l + w1o, D_, 0,0,
            nullptr, 0, 0,0,
            pFh, pFl, DFF_, 0,0,
            nullptr, 0, 0,0, b1 + l*DFF_,
            Mrows, DFF_, D_, 1, 1.f, 1, 0);
        // X = X + FF @ W2 + b2   (64x128 tiles: 252 CTAs)
        long long w2o = (long long)l*D_*DFF_;
        gemm_hl<64,128,2,4><<<dim3(4, cdiv(Mrows,64), 1), 256, gemm_smem(64,128)>>>(
            pFh, pFl, DFF_, 0,0,
            pW2h + w2o, pW2l + w2o, DFF_, 0,0,
            pX, D_, 0,0,
            nullptr, nullptr, 0, 0,0,
            pX, D_, 0,0, b2 + l*D_,
            Mrows, D_, DFF_, 1, 1.f, 0, 0);
        inorm_r<<<dim3(D_/32, B_, 8), dim3(32, 8)>>>(pX, g2 + l*D_, be2 + l*D_, pXh, pXl, N_);
    }

    write_xout<<<cdiv(B_*N1_*D_, 256), 256>>>(fin, outX);
    gemm_hl<128,128,4,2><<<dim3(8, 32, 1), 256, gemm_smem(128,128)>>>(
        pXoh, pXol, D_, 0,0,
        pWkh, pWkl, D_, 0,0,
        pKV, 2*D_, 0,0,
        nullptr, nullptr, 0, 0,0,
        nullptr, 0, 0,0, nullptr,
        B_*N1_, 2*D_, D_, 1, 1.f, 0, 0);
    write_kv<<<cdiv(H_*B_*N1_*HD_, 256), 256>>>(outK, outV);
}

// round 17
// speedup vs baseline: 2.9981x; 1.1291x over previous
#include <cuda_runtime.h>
#include <cuda_fp16.h>
#include <math.h>

// ---------------- problem constants ----------------
#define B_   4
#define NW_  100
#define NT_  800
#define N_   1000
#define N1_  1001
#define D_   512
#define H_   8
#define HD_  64
#define DFF_ 2048
#define L_   3
#define EPS_ 1e-5f
#define ALPHA_ 0.125f   // 1/sqrt(64)
#define NPAD_ 1024      // padded kv length for Vt

// ---------------- device scratch (no allocation allowed) ----------------
__device__ float  g_X   [B_*N_*D_];
__device__ float  g_KV  [B_*N1_*2*D_];
__device__ double g_part[B_*32*5];
__device__ float  g_ec0[32], g_ec1[32], g_ec2[32];

__device__ __align__(16) __half g_Xh [B_*N_*D_];
__device__ __align__(16) __half g_Xl [B_*N_*D_];
__device__ __align__(16) __half g_QKVh[B_*N_*3*D_];
__device__ __align__(16) __half g_QKVl[B_*N_*3*D_];
__device__ __align__(16) __half g_Vth[B_*D_*NPAD_];
__device__ __align__(16) __half g_Vtl[B_*D_*NPAD_];
__device__ __align__(16) __half g_Oh [B_*N_*D_];
__device__ __align__(16) __half g_Ol [B_*N_*D_];
__device__ __align__(16) __half g_FFh[B_*N_*DFF_];
__device__ __align__(16) __half g_FFl[B_*N_*DFF_];
__device__ __align__(16) __half g_Wqkvh[L_*3*D_*D_];
__device__ __align__(16) __half g_Wqkvl[L_*3*D_*D_];
__device__ __align__(16) __half g_Woh[L_*D_*D_];
__device__ __align__(16) __half g_Wol[L_*D_*D_];
__device__ __align__(16) __half g_W1h[L_*DFF_*D_];
__device__ __align__(16) __half g_W1l[L_*DFF_*D_];
__device__ __align__(16) __half g_W2h[L_*D_*DFF_];
__device__ __align__(16) __half g_W2l[L_*D_*DFF_];
__device__ __align__(16) __half g_Wkvh[2*D_*D_];
__device__ __align__(16) __half g_Wkvl[2*D_*D_];
__device__ __align__(16) __half g_Xoh[B_*N1_*D_];
__device__ __align__(16) __half g_Xol[B_*N1_*D_];

__device__ __forceinline__ void splitf(float v, __half &h, __half &l) {
    h = __float2half_rn(v);
    l = __float2half_rn(v - __half2float(h));
}

__device__ __forceinline__ void cp16(unsigned dst, const void* src, bool p) {
    int sz = p ? 16 : 0;
    asm volatile("cp.async.ca.shared.global [%0], [%1], 16, %2;\n"
                 :: "r"(dst), "l"(src), "r"(sz));
}

#define LDSM4(r0,r1,r2,r3,a) \
    asm volatile("ldmatrix.sync.aligned.m8n8.x4.shared.b16 {%0,%1,%2,%3}, [%4];" \
                 : "=r"(r0),"=r"(r1),"=r"(r2),"=r"(r3) : "r"(a))

#define MMA16816(acc,a0,a1,a2,a3,b0,b1) \
    asm volatile("mma.sync.aligned.m16n8k16.row.col.f32.f16.f16.f32 " \
                 "{%0,%1,%2,%3}, {%4,%5,%6,%7}, {%8,%9}, {%0,%1,%2,%3};" \
                 : "+f"((acc)[0]), "+f"((acc)[1]), "+f"((acc)[2]), "+f"((acc)[3]) \
                 : "r"(a0), "r"(a1), "r"(a2), "r"(a3), "r"(b0), "r"(b1))

// ---------------- split-fp16 GEMM: BK=32, 2-stage, 2 CTA/SM ----------------
#define GBK   32
#define GLDK  40
constexpr int gemm_smem(int BM, int BN) { return 2*2*(BM+BN)*GLDK*2; }

template<int BM, int BN, int WARPS_M, int WARPS_N>
__global__ __launch_bounds__(WARPS_M*WARPS_N*32, 2)
void gemm_hl(const __half* __restrict__ Ah, const __half* __restrict__ Al,
             int lda, long long sA1, long long sA0,
             const __half* __restrict__ Bh, const __half* __restrict__ Bl,
             int ldb, long long sB1, long long sB0,
             float* __restrict__ C, int ldc, long long sC1, long long sC0,
             __half* __restrict__ Ch, __half* __restrict__ Cl,
             int ldch, long long sCh1, long long sCh0,
             const float* __restrict__ addsrc, int ldadd, long long sD1, long long sD0,
             const float* __restrict__ bias,
             int M, int N, int K, int inner, float alpha,
             int relu, int qkv_mode)
{
    constexpr int WM = BM/WARPS_M, WN = BN/WARPS_N;
    constexpr int MT = WM/16, NT = WN/8;
    constexpr int THREADS = WARPS_M*WARPS_N*32;
    constexpr int STRIDE = 2*(BM+BN)*GLDK;             // halves per stage
    constexpr int offAh = 0;
    constexpr int offAl = BM*GLDK;
    constexpr int offBh = 2*BM*GLDK;
    constexpr int offBl = (2*BM+BN)*GLDK;
    constexpr int ITER  = (2*(BM+BN)*4)/THREADS;       // cp16 per thread per stage

    extern __shared__ __half sm_g[];

    int z = blockIdx.z, z1 = z/inner, z0 = z%inner;
    Ah += z1*sA1 + z0*sA0;  Al += z1*sA1 + z0*sA0;
    Bh += z1*sB1 + z0*sB0;  Bl += z1*sB1 + z0*sB0;
    if (C)  C  += z1*sC1  + z0*sC0;
    if (Ch) { Ch += z1*sCh1 + z0*sCh0; Cl += z1*sCh1 + z0*sCh0; }

    int tid = threadIdx.x;
    int warp = tid>>5, lane = tid&31, g = lane>>2, tg = lane&3;
    int wm = (warp % WARPS_M)*WM, wn = (warp / WARPS_M)*WN;
    int row0 = blockIdx.y*BM, col0 = blockIdx.x*BN;

    const unsigned sB = (unsigned)__cvta_generic_to_shared(sm_g);

    float acc[MT][NT][4] = {};

    int aRow = (lane&7) + ((lane>>3)&1)*8;
    int aCol = ((lane>>4)&1)*8;
    int bRow = (lane&7) + ((lane>>4)&1)*8;
    int bCol = ((lane>>3)&1)*8;

    auto issue = [&](int kt, int s) {
        int k0 = kt * GBK;
        #pragma unroll
        for (int i = 0; i < ITER; i++) {
            int idx = tid + i*THREADS;
            int ch = (idx & 3) * 8;
            int r  = idx >> 2;
            int off, row; const __half* src; int ld; bool isA;
            if (r < BM)              { off = offAh; row = r;            src = Ah; ld = lda; isA = true; }
            else if (r < 2*BM)       { off = offAl; row = r - BM;       src = Al; ld = lda; isA = true; }
            else if (r < 2*BM + BN)  { off = offBh; row = r - 2*BM;     src = Bh; ld = ldb; isA = false; }
            else                     { off = offBl; row = r - 2*BM - BN; src = Bl; ld = ldb; isA = false; }
            int grow = (isA ? row0 : col0) + row;
            bool p = grow < (isA ? M : N);
            cp16(sB + (unsigned)((s*STRIDE + off + row*GLDK + ch)*2),
                 src + (long long)grow*ld + k0 + ch, p);
        }
        asm volatile("cp.async.commit_group;");
    };

    auto compute = [&](int s) {
        #pragma unroll
        for (int ks2 = 0; ks2 < 2; ks2++) {
            int kc = ks2*16;
            unsigned ah[MT][4], al[MT][4];
            #pragma unroll
            for (int mt = 0; mt < MT; mt++) {
                int r = wm + mt*16 + aRow;
                LDSM4(ah[mt][0], ah[mt][1], ah[mt][2], ah[mt][3],
                      sB + (unsigned)((s*STRIDE + offAh + r*GLDK + kc + aCol)*2));
                LDSM4(al[mt][0], al[mt][1], al[mt][2], al[mt][3],
                      sB + (unsigned)((s*STRIDE + offAl + r*GLDK + kc + aCol)*2));
            }
            #pragma unroll
            for (int nt2 = 0; nt2 < NT/2; nt2++) {
                int rB = wn + nt2*16 + bRow;
                unsigned bh0,bh1,bh2,bh3, bl0,bl1,bl2,bl3;
                LDSM4(bh0,bh1,bh2,bh3, sB + (unsigned)((s*STRIDE + offBh + rB*GLDK + kc + bCol)*2));
                LDSM4(bl0,bl1,bl2,bl3, sB + (unsigned)((s*STRIDE + offBl + rB*GLDK + kc + bCol)*2));
                #pragma unroll
                for (int mt = 0; mt < MT; mt++) {
                    MMA16816(acc[mt][nt2*2], ah[mt][0],ah[mt][1],ah[mt][2],ah[mt][3], bh0,bh1);
                    MMA16816(acc[mt][nt2*2], ah[mt][0],ah[mt][1],ah[mt][2],ah[mt][3], bl0,bl1);
                    MMA16816(acc[mt][nt2*2], al[mt][0],al[mt][1],al[mt][2],al[mt][3], bh0,bh1);
                }
                #pragma unroll
                for (int mt = 0; mt < MT; mt++) {
                    MMA16816(acc[mt][nt2*2+1], ah[mt][0],ah[mt][1],ah[mt][2],ah[mt][3], bh2,bh3);
                    MMA16816(acc[mt][nt2*2+1], ah[mt][0],ah[mt][1],ah[mt][2],ah[mt][3], bl2,bl3);
                    MMA16816(acc[mt][nt2*2+1], al[mt][0],al[mt][1],al[mt][2],al[mt][3], bh2,bh3);
                }
            }
        }
    };

    const int T = K / GBK;
    issue(0, 0);
    if (T > 1) issue(1, 1);
    for (int i = 0; i < T; i++) {
        if (i + 1 < T) { asm volatile("cp.async.wait_group 1;"); }
        else           { asm volatile("cp.async.wait_group 0;"); }
        __syncthreads();
        compute(i & 1);
        if (i + 2 < T) {
            __syncthreads();
            issue(i + 2, i & 1);
        }
    }

    if (addsrc) addsrc += z1*sD1 + z0*sD0;

    #pragma unroll
    for (int mt = 0; mt < MT; mt++) {
        #pragma unroll
        for (int nt = 0; nt < NT; nt++) {
            int nb = col0 + wn + nt*8 + tg*2;
            #pragma unroll
            for (int h2 = 0; h2 < 2; h2++) {
                int m = row0 + wm + mt*16 + g + h2*8;
                if (m >= M) continue;
                #pragma unroll
                for (int j = 0; j < 2; j++) {
                    int n = nb + j;
                    if (n >= N) continue;
                    float v = alpha * acc[mt][nt][h2*2+j];
                    if (bias)   v += bias[n];
                    if (addsrc) v += addsrc[(long long)m*ldadd + n];
                    if (relu) v = fmaxf(v, 0.f);
                    if (C) C[(long long)m*ldc + n] = v;
                    if (Ch) {
                        __half hh, ll; splitf(v, hh, ll);
                        Ch[(long long)m*ldch + n] = hh;
                        Cl[(long long)m*ldch + n] = ll;
                        if (qkv_mode && n >= 1024) {
                            int b = m / N_, mm = m - b*N_;
                            long long vi = ((long long)b*D_ + (n-1024))*NPAD_ + mm;
                            g_Vth[vi] = hh; g_Vtl[vi] = ll;
                        }
                    }
                }
            }
        }
    }
}

// ---------------- flash attention (double-buffered KV) ----------------
#define LDKQ 72
#define LDVV 136
#define FBUF (2*128*LDKQ + 2*64*LDVV)
#define FLASH_SMEM (2*FBUF*2)

__global__ __launch_bounds__(256,1)
void flash_attn(const float* __restrict__ ef,
                const __half* __restrict__ QKVh, const __half* __restrict__ QKVl,
                const __half* __restrict__ Vth,  const __half* __restrict__ Vtl,
                __half* __restrict__ Oh, __half* __restrict__ Ol)
{
    extern __shared__ __half sm_[];

    const int qb = blockIdx.x;
    const int z  = blockIdx.y;
    const int h  = z / B_, b = z % B_;
    const int row0 = qb*128;
    const int tid = threadIdx.x, warp = tid>>5, lane = tid&31;
    const int g = lane>>2, tg = lane&3;
    const int aRow = (lane&7) + ((lane>>3)&1)*8;
    const int aCol = ((lane>>4)&1)*8;
    const int bRow = (lane&7) + ((lane>>4)&1)*8;
    const int bCol = ((lane>>3)&1)*8;

    const unsigned sBase = (unsigned)__cvta_generic_to_shared(sm_);
    auto sKh = [&](int bf){ return sBase + (unsigned)(bf*FBUF*2); };
    auto sKl = [&](int bf){ return sBase + (unsigned)((bf*FBUF + 128*LDKQ)*2); };
    auto sVh = [&](int bf){ return sBase + (unsigned)((bf*FBUF + 2*128*LDKQ)*2); };
    auto sVl = [&](int bf){ return sBase + (unsigned)((bf*FBUF + 2*128*LDKQ + 64*LDVV)*2); };

    #pragma unroll
    for (int i = 0; i < 4; i++) {
        int idx = tid + i*256;
        int r = idx >> 3, ch = (idx & 7)*8;
        int m = row0 + r;
        bool p = m < N_;
        long long go = (long long)(b*N_ + (p ? m : 0))*(3*D_) + h*HD_ + ch;
        cp16(sKh(0) + (unsigned)((r*LDKQ + ch)*2), QKVh + go, p);
        cp16(sKl(0) + (unsigned)((r*LDKQ + ch)*2), QKVl + go, p);
    }
    asm volatile("cp.async.commit_group;");
    asm volatile("cp.async.wait_group 0;");
    __syncthreads();

    unsigned qh[4][4], ql[4][4];
    #pragma unroll
    for (int ks = 0; ks < 4; ks++) {
        LDSM4(qh[ks][0],qh[ks][1],qh[ks][2],qh[ks][3],
              sKh(0) + (unsigned)(((warp*16 + aRow)*LDKQ + ks*16 + aCol)*2));
        LDSM4(ql[ks][0],ql[ks][1],ql[ks][2],ql[ks][3],
              sKl(0) + (unsigned)(((warp*16 + aRow)*LDKQ + ks*16 + aCol)*2));
    }
    __syncthreads();

    auto issue_kv = [&](int kt, int bf) {
        const int kv0 = kt*128;
        #pragma unroll
        for (int i = 0; i < 4; i++) {
            int idx = tid + i*256;
            int r = idx >> 3, ch = (idx & 7)*8;
            int kv = kv0 + r;
            bool p = kv < N_;
            long long go = (long long)(b*N_ + (p ? kv : 0))*(3*D_) + D_ + h*HD_ + ch;
            cp16(sKh(bf) + (unsigned)((r*LDKQ + ch)*2), QKVh + go, p);
            cp16(sKl(bf) + (unsigned)((r*LDKQ + ch)*2), QKVl + go, p);
        }
        #pragma unroll
        for (int i = 0; i < 4; i++) {
            int idx = tid + i*256;
            int r = idx >> 4, ch = (idx & 15)*8;
            long long go = (long long)(b*D_ + h*HD_ + r)*NPAD_ + kv0 + ch;
            cp16(sVh(bf) + (unsigned)((r*LDVV + ch)*2), Vth + go, true);
            cp16(sVl(bf) + (unsigned)((r*LDVV + ch)*2), Vtl + go, true);
        }
        asm volatile("cp.async.commit_group;");
    };

    float oacc[8][4] = {};
    float rmax0 = -1e30f, rmax1 = -1e30f, rsum0 = 0.f, rsum1 = 0.f;
    const int te = b*H_ + h;
    const float ec0 = g_ec0[te], ec1 = g_ec1[te], ec2 = g_ec2[te];
    const float2* e2 = (const float2*)ef + (long long)b*N_*N_;
    const int r0g = row0 + warp*16 + g;
    const int r1g = r0g + 8;
    const long long er0 = (long long)(r0g < N_ ? r0g : N_-1) * N_;
    const long long er1 = (long long)(r1g < N_ ? r1g : N_-1) * N_;

    issue_kv(0, 0);
    issue_kv(1, 1);

    for (int kt = 0; kt < 8; kt++) {
        const int kv0 = kt*128;
        const int bf = kt & 1;
        if (kt < 7) { asm volatile("cp.async.wait_group 1;"); }
        else        { asm volatile("cp.async.wait_group 0;"); }
        __syncthreads();

        float s[16][4];
        #pragma unroll
        for (int i = 0; i < 16; i++) { s[i][0]=s[i][1]=s[i][2]=s[i][3]=0.f; }
        #pragma unroll
        for (int ks = 0; ks < 4; ks++) {
            #pragma unroll
            for (int nt2 = 0; nt2 < 8; nt2++) {
                unsigned bh0,bh1,bh2,bh3, bl0,bl1,bl2,bl3;
                LDSM4(bh0,bh1,bh2,bh3, sKh(bf) + (unsigned)(((nt2*16+bRow)*LDKQ + ks*16 + bCol)*2));
                LDSM4(bl0,bl1,bl2,bl3, sKl(bf) + (unsigned)(((nt2*16+bRow)*LDKQ + ks*16 + bCol)*2));
                MMA16816(s[nt2*2],   qh[ks][0],qh[ks][1],qh[ks][2],qh[ks][3], bh0,bh1);
                MMA16816(s[nt2*2],   qh[ks][0],qh[ks][1],qh[ks][2],qh[ks][3], bl0,bl1);
                MMA16816(s[nt2*2],   ql[ks][0],ql[ks][1],ql[ks][2],ql[ks][3], bh0,bh1);
                MMA16816(s[nt2*2+1], qh[ks][0],qh[ks][1],qh[ks][2],qh[ks][3], bh2,bh3);
                MMA16816(s[nt2*2+1], qh[ks][0],qh[ks][1],qh[ks][2],qh[ks][3], bl2,bl3);
                MMA16816(s[nt2*2+1], ql[ks][0],ql[ks][1],ql[ks][2],ql[ks][3], bh2,bh3);
            }
        }

        float tm0 = -1e30f, tm1 = -1e30f;
        #pragma unroll
        for (int nt = 0; nt < 16; nt++) {
            int c = nt*8 + 2*tg;
            int n = kv0 + c;
            bool v0 = (n < N_), v1 = (n+1 < N_);
            long long ei0 = v0 ? n : (N_-1);
            long long ei1 = v1 ? (n+1) : (N_-1);
            float2 f00 = e2[er0 + ei0], f01 = e2[er0 + ei1];
            float2 f10 = e2[er1 + ei0], f11 = e2[er1 + ei1];
            s[nt][0] = v0 ? ALPHA_*s[nt][0] + f00.x*ec0 + f00.y*ec1 + ec2 : -1e30f;
            s[nt][1] = v1 ? ALPHA_*s[nt][1] + f01.x*ec0 + f01.y*ec1 + ec2 : -1e30f;
            s[nt][2] = v0 ? ALPHA_*s[nt][2] + f10.x*ec0 + f10.y*ec1 + ec2 : -1e30f;
            s[nt][3] = v1 ? ALPHA_*s[nt][3] + f11.x*ec0 + f11.y*ec1 + ec2 : -1e30f;
            tm0 = fmaxf(tm0, fmaxf(s[nt][0], s[nt][1]));
            tm1 = fmaxf(tm1, fmaxf(s[nt][2], s[nt][3]));
        }
        tm0 = fmaxf(tm0, __shfl_xor_sync(0xffffffffu, tm0, 1));
        tm0 = fmaxf(tm0, __shfl_xor_sync(0xffffffffu, tm0, 2));
        tm1 = fmaxf(tm1, __shfl_xor_sync(0xffffffffu, tm1, 1));
        tm1 = fmaxf(tm1, __shfl_xor_sync(0xffffffffu, tm1, 2));
        float nm0 = fmaxf(rmax0, tm0), nm1 = fmaxf(rmax1, tm1);
        float sc0 = __expf(rmax0 - nm0), sc1 = __expf(rmax1 - nm1);
        rmax0 = nm0; rmax1 = nm1;
        #pragma unroll
        for (int nt = 0; nt < 8; nt++) {
            oacc[nt][0]*=sc0; oacc[nt][1]*=sc0; oacc[nt][2]*=sc1; oacc[nt][3]*=sc1;
        }
        float ps0 = 0.f, ps1 = 0.f;
        #pragma unroll
        for (int nt = 0; nt < 16; nt++) {
            s[nt][0] = __expf(s[nt][0]-nm0); s[nt][1] = __expf(s[nt][1]-nm0);
            s[nt][2] = __expf(s[nt][2]-nm1); s[nt][3] = __expf(s[nt][3]-nm1);
            ps0 += s[nt][0]+s[nt][1]; ps1 += s[nt][2]+s[nt][3];
        }
        ps0 += __shfl_xor_sync(0xffffffffu, ps0, 1);
        ps0 += __shfl_xor_sync(0xffffffffu, ps0, 2);
        ps1 += __shfl_xor_sync(0xffffffffu, ps1, 1);
        ps1 += __shfl_xor_sync(0xffffffffu, ps1, 2);
        rsum0 = rsum0*sc0 + ps0;
        rsum1 = rsum1*sc1 + ps1;

        #pragma unroll
        for (int s8 = 0; s8 < 8; s8++) {
            unsigned pa[4], pb[4];
            #pragma unroll
            for (int j = 0; j < 2; j++) {
                float x0 = s[2*s8+j][0], x1 = s[2*s8+j][1];
                float x2 = s[2*s8+j][2], x3 = s[2*s8+j][3];
                __half2 h0 = __floats2half2_rn(x0, x1);
                __half2 h1 = __floats2half2_rn(x2, x3);
                float2 k0 = __half22float2(h0);
                float2 k1 = __half22float2(h1);
                __half2 l0 = __floats2half2_rn(x0-k0.x, x1-k0.y);
                __half2 l1 = __floats2half2_rn(x2-k1.x, x3-k1.y);
                pa[j*2+0] = *(unsigned*)&h0; pa[j*2+1] = *(unsigned*)&h1;
                pb[j*2+0] = *(unsigned*)&l0; pb[j*2+1] = *(unsigned*)&l1;
            }
            #pragma unroll
            for (int nt2 = 0; nt2 < 4; nt2++) {
                unsigned vh0,vh1,vh2,vh3, vl0,vl1,vl2,vl3;
                LDSM4(vh0,vh1,vh2,vh3, sVh(bf) + (unsigned)(((nt2*16+bRow)*LDVV + s8*16 + bCol)*2));
                LDSM4(vl0,vl1,vl2,vl3, sVl(bf) + (unsigned)(((nt2*16+bRow)*LDVV + s8*16 + bCol)*2));
                MMA16816(oacc[nt2*2],   pa[0],pa[1],pa[2],pa[3], vh0,vh1);
                MMA16816(oacc[nt2*2],   pa[0],pa[1],pa[2],pa[3], vl0,vl1);
                MMA16816(oacc[nt2*2],   pb[0],pb[1],pb[2],pb[3], vh0,vh1);
                MMA16816(oacc[nt2*2+1], pa[0],pa[1],pa[2],pa[3], vh2,vh3);
                MMA16816(oacc[nt2*2+1], pa[0],pa[1],pa[2],pa[3], vl2,vl3);
                MMA16816(oacc[nt2*2+1], pb[0],pb[1],pb[2],pb[3], vh2,vh3);
            }
        }
        __syncthreads();
        if (kt + 2 < 8) issue_kv(kt + 2, bf);
    }

    float i0 = 1.f / rsum0, i1 = 1.f / rsum1;
    #pragma unroll
    for (int nt = 0; nt < 8; nt++) {
        int c = h*HD_ + nt*8 + 2*tg;
        if (r0g < N_) {
            float a = oacc[nt][0]*i0, bb = oacc[nt][1]*i0;
            __half2 hh = __floats2half2_rn(a, bb);
            float2 bk = __half22float2(hh);
            __half2 ll = __floats2half2_rn(a-bk.x, bb-bk.y);
            *(__half2*)&Oh[(long long)(b*N_+r0g)*D_ + c] = hh;
            *(__half2*)&Ol[(long long)(b*N_+r0g)*D_ + c] = ll;
        }
        if (r1g < N_) {
            float a = oacc[nt][2]*i1, bb = oacc[nt][3]*i1;
            __half2 hh = __floats2half2_rn(a, bb);
            float2 bk = __half22float2(hh);
            __half2 ll = __floats2half2_rn(a-bk.x, bb-bk.y);
            *(__half2*)&Oh[(long long)(b*N_+r1g)*D_ + c] = hh;
            *(__half2*)&Ol[(long long)(b*N_+r1g)*D_ + c] = ll;
        }
    }
}

// ---------------- InstanceNorm1d: redundant stats, sliced normalize ----------
__global__ void inorm_r(float* __restrict__ X, const float* __restrict__ g,
                        const float* __restrict__ be,
                        __half* __restrict__ Xh, __half* __restrict__ Xl, int Nrows)
{
    int b = blockIdx.y;
    int zz = blockIdx.z;
    int c = blockIdx.x * 32 + threadIdx.x;
    int ty = threadIdx.y;
    long long base = (long long)b * Nrows * D_;
    float* Xb = X + base;
    float s = 0.f, q = 0.f;
    for (int n = ty; n < Nrows; n += 8) {
        float x = Xb[(long long)n * D_ + c];
        s += x; q += x * x;
    }
    __shared__ float sh_s[8][32], sh_q[8][32];
    sh_s[ty][threadIdx.x] = s; sh_q[ty][threadIdx.x] = q;
    __syncthreads();
    __shared__ float sh_m[32], sh_r[32];
    if (ty == 0) {
        float S = 0.f, Q = 0.f;
        #pragma unroll
        for (int i = 0; i < 8; i++) { S += sh_s[i][threadIdx.x]; Q += sh_q[i][threadIdx.x]; }
        float mean = S / (float)Nrows;
        float var  = Q / (float)Nrows - mean*mean;
        sh_m[threadIdx.x] = mean;
        sh_r[threadIdx.x] = rsqrtf(var + EPS_);
    }
    __syncthreads();
    float mean = sh_m[threadIdx.x], r = sh_r[threadIdx.x];
    float gg = g[c], bb = be[c];
    int chunk = (Nrows + 7) / 8;
    int n0 = zz * chunk;
    int n1 = min(n0 + chunk, Nrows);
    for (int n = n0 + ty; n < n1; n += 8) {
        long long idx = (long long)n * D_ + c;
        float v = gg * (Xb[idx] - mean) * r + bb;
        Xb[idx] = v;
        __half hh, ll; splitf(v, hh, ll);
        Xh[base + idx] = hh; Xl[base + idx] = ll;
    }
}

// ---------------- input projections + concat ----------------
__global__ void init_x(const float* __restrict__ wf, const float* __restrict__ tf,
                       const float* __restrict__ Wws, const float* __restrict__ bws,
                       const float* __restrict__ Wwe, const float* __restrict__ bwe,
                       const float* __restrict__ Wt,  const float* __restrict__ bt)
{
    int t = blockIdx.x * blockDim.x + threadIdx.x;
    if (t >= B_*N_*D_) return;
    int d = t & 511;
    int n = (t >> 9) % N_;
    int b = t / (D_*N_);
    float v;
    if (n < NW_) {
        const float* f = wf + (b*NW_ + n)*4;
        v = bws[d];
        #pragma unroll
        for (int k = 0; k < 4; k++) v += f[k] * Wws[k*D_ + d];
    } else if (n < 2*NW_) {
        const float* f = wf + (b*NW_ + (n - NW_))*4;
        v = bwe[d];
        #pragma unroll
        for (int k = 0; k < 4; k++) v += f[k] * Wwe[k*D_ + d];
    } else {
        const float* f = tf + (b*NT_ + (n - 2*NW_))*8;
        v = bt[d];
        #pragma unroll
        for (int k = 0; k < 8; k++) v += f[k] * Wt[k*D_ + d];
    }
    g_X[t] = v;
}

// ---------------- edge bias: per-block partial moments -----------
__global__ __launch_bounds__(256)
void edge_stats(const float* __restrict__ ef)
{
    int b = blockIdx.y;
    int blk = blockIdx.x;
    const float2* p = (const float2*)ef + (long long)b * (N_*N_);
    int stride = gridDim.x * blockDim.x;
    float s0=0,s1=0,s00=0,s11=0,s01=0;
    for (int i = blk*blockDim.x + threadIdx.x; i < N_*N_; i += stride) {
        float2 f = p[i];
        s0 += f.x; s1 += f.y; s00 += f.x*f.x; s11 += f.y*f.y; s01 += f.x*f.y;
    }
    __shared__ double red[256];
    double loc[5] = {(double)s0,(double)s1,(double)s00,(double)s11,(double)s01};
    for (int j = 0; j < 5; j++) {
        red[threadIdx.x] = loc[j];
        __syncthreads();
        for (int s = 128; s > 0; s >>= 1) { if (threadIdx.x < s) red[threadIdx.x] += red[threadIdx.x+s]; __syncthreads(); }
        if (threadIdx.x == 0) g_part[(b*32 + blk)*5 + j] = red[0];
        __syncthreads();
    }
}

__global__ void edge_params(const float* __restrict__ We, const float* __restrict__ be,
                            const float* __restrict__ ge, const float* __restrict__ bee)
{
    int t = threadIdx.x;
    if (t >= B_*H_) return;
    int b = t / H_, h = t % H_;
    double mm[5];
    for (int j = 0; j < 5; j++) {
        double acc = 0.0;
        for (int blk = 0; blk < 32; blk++) acc += g_part[(b*32 + blk)*5 + j];
        mm[j] = acc;
    }
    double cnt = (double)N_ * (double)N_;
    double m0  = mm[0]/cnt, m1 = mm[1]/cnt;
    double v00 = mm[2]/cnt - m0*m0;
    double v11 = mm[3]/cnt - m1*m1;
    double v01 = mm[4]/cnt - m0*m1;
    double w0 = We[0*H_+h], w1 = We[1*H_+h];
    double mean = w0*m0 + w1*m1 + (double)be[h];
    double var  = w0*w0*v00 + 2.0*w0*w1*v01 + w1*w1*v11;
    double grs  = (double)ge[h] / sqrt(var + (double)EPS_);
    g_ec0[t] = (float)(w0*grs);
    g_ec1[t] = (float)(w1*grs);
    g_ec2[t] = (float)(((double)be[h] - mean)*grs + (double)bee[h]);
}

// ---------------- unified weight pack: tiled transpose + split ----------------
__global__ __launch_bounds__(256)
void pack_all(const float* __restrict__ Wq, const float* __restrict__ Wk,
              const float* __restrict__ Wv, const float* __restrict__ Wo,
              const float* __restrict__ W1, const float* __restrict__ W2,
              const float* __restrict__ Kd, const float* __restrict__ Vd)
{
    int t = blockIdx.x;
    int tx = threadIdx.x & 31, ty = threadIdx.x >> 5;

    if (t >= 9728) {
        int idx = (t - 9728) * 256 + threadIdx.x;
        int r = idx / (NPAD_ - N_);
        int c = N_ + idx % (NPAD_ - N_);
        __half zz = __float2half(0.f);
        g_Vth[(long long)r*NPAD_ + c] = zz;
        g_Vtl[(long long)r*NPAD_ + c] = zz;
        return;
    }

    const float* src; __half *dh, *dl;
    int C, dstStride; long long srcOff = 0, dstOff = 0;
    int tr, tc;

    if (t < 2304) {
        int batch = t >> 5, w = t & 31;
        tr = w & 15; tc = w >> 4;
        int l = batch / 24, r24 = batch % 24, sec = r24 >> 3, h = r24 & 7;
        src = (sec == 0) ? Wq : (sec == 1) ? Wk : Wv;
        srcOff = (long long)(l*8 + h) * 32768;
        C = 64; dstStride = 512;
        dh = g_Wqkvh; dl = g_Wqkvl;
        dstOff = (long long)l*786432 + (long long)(sec*512 + h*64)*512;
    } else if (t < 3072) {
        int t2 = t - 2304;
        int l = t2 >> 8, w = t2 & 255;
        tr = w & 15; tc = w >> 4;
        src = Wo; srcOff = (long long)l*262144;
        C = 512; dstStride = 512;
        dh = g_Woh; dl = g_Wol; dstOff = (long long)l*262144;
    } else if (t < 6144) {
        int t2 = t - 3072;
        int l = t2 >> 10, w = t2 & 1023;
        tr = w & 15; tc = w >> 4;
        src = W1; srcOff = (long long)l*1048576;
        C = 2048; dstStride = 512;
        dh = g_W1h; dl = g_W1l; dstOff = (long long)l*1048576;
    } else if (t < 9216) {
        int t2 = t - 6144;
        int l = t2 >> 10, w = t2 & 1023;
        tr = w & 63; tc = w >> 6;
        src = W2; srcOff = (long long)l*1048576;
        C = 512; dstStride = 2048;
        dh = g_W2h; dl = g_W2l; dstOff = (long long)l*1048576;
    } else {
        int t2 = t - 9216;
        int batch = t2 >> 5, w = t2 & 31;
        tr = w & 15; tc = w >> 4;
        int sec = batch >> 3, h = batch & 7;
        src = sec ? Vd : Kd;
        srcOff = (long long)h * 32768;
        C = 64; dstStride = 512;
        dh = g_Wkvh; dl = g_Wkvl;
        dstOff = (long long)(sec*512 + h*64)*512;
    }

    __shared__ float tile[32][33];
    #pragma unroll
    for (int i = 0; i < 4; i++) {
        int r = tr*32 + ty + i*8;
        int c = tc*32 + tx;
        tile[ty + i*8][tx] = src[srcOff + (long long)r*C + c];
    }
    __syncthreads();
    #pragma unroll
    for (int i = 0; i < 4; i++) {
        int n = tc*32 + ty + i*8;
        int k = tr*32 + tx;
        float v = tile[tx][ty + i*8];
        __half hh, ll; splitf(v, hh, ll);
        long long di = dstOff + (long long)n*dstStride + k;
        dh[di] = hh; dl[di] = ll;
    }
}

// ---------------- finish token append into output X (+ hi/lo) ----------------
__global__ void write_xout(const float* __restrict__ fin, float* __restrict__ out)
{
    int t = blockIdx.x * blockDim.x + threadIdx.x;
    if (t >= B_*N1_*D_) return;
    int d = t & 511;
    int n = (t >> 9) % N1_;
    int b = t / (N1_*D_);
    float v = (n < N_) ? g_X[((long long)b*N_ + n)*D_ + d] : fin[d];
    out[t] = v;
    splitf(v, g_Xoh[t], g_Xol[t]);
}

// ---------------- reorder decode K/V to [H][B][N1][HD] ----------------
__global__ void write_kv(float* __restrict__ outK, float* __restrict__ outV)
{
    int t = blockIdx.x * blockDim.x + threadIdx.x;
    if (t >= H_*B_*N1_*HD_) return;
    int e = t & 63;
    int n = (t >> 6) % N1_;
    int rem = t / (HD_*N1_);
    int b = rem & 3;
    int h = rem >> 2;
    long long src = ((long long)(b*N1_ + n))*(2*D_) + h*HD_ + e;
    outK[t] = g_KV[src];
    outV[t] = g_KV[src + D_];
}

// ---------------- host orchestration ----------------
static inline int cdiv(int a, int b) { return (a + b - 1) / b; }

extern "C" void kernel_launch(void* const* d_in, const int* in_sizes, int n_in,
                              void* d_out, int out_size)
{
    const float* wf   = (const float*)d_in[0];
    const float* tf   = (const float*)d_in[1];
    const float* ef   = (const float*)d_in[2];
    const float* Wws  = (const float*)d_in[3];
    const float* bws  = (const float*)d_in[4];
    const float* Wwe  = (const float*)d_in[5];
    const float* bwe  = (const float*)d_in[6];
    const float* Wt   = (const float*)d_in[7];
    const float* bt   = (const float*)d_in[8];
    const float* g_wt = (const float*)d_in[9];
    const float* be_wt= (const float*)d_in[10];
    const float* W_e  = (const float*)d_in[11];
    const float* b_e  = (const float*)d_in[12];
    const float* g_e  = (const float*)d_in[13];
    const float* be_e = (const float*)d_in[14];
    const float* Wq   = (const float*)d_in[15];
    const float* Wk   = (const float*)d_in[16];
    const float* Wv   = (const float*)d_in[17];
    const float* Wo   = (const float*)d_in[18];
    const float* W1   = (const float*)d_in[19];
    const float* b1   = (const float*)d_in[20];
    const float* W2   = (const float*)d_in[21];
    const float* b2   = (const float*)d_in[22];
    const float* g1   = (const float*)d_in[23];
    const float* be1  = (const float*)d_in[24];
    const float* g2   = (const float*)d_in[25];
    const float* be2  = (const float*)d_in[26];
    const float* fin  = (const float*)d_in[27];
    const float* Kd   = (const float*)d_in[28];
    const float* Vd   = (const float*)d_in[29];

    float* out  = (float*)d_out;
    float* outX = out;
    float* outK = out + (size_t)B_*N1_*D_;
    float* outV = outK + (size_t)H_*B_*N1_*HD_;

    float *pX, *pKV;
    __half *pXh,*pXl,*pQh,*pQl,*pVth,*pVtl,*pOhh,*pOll,*pFh,*pFl;
    __half *pWqh,*pWql,*pWoh,*pWol,*pW1h,*pW1l,*pW2h,*pW2l,*pWkh,*pWkl,*pXoh,*pXol;
    cudaGetSymbolAddress((void**)&pX,  g_X);
    cudaGetSymbolAddress((void**)&pKV, g_KV);
    cudaGetSymbolAddress((void**)&pXh, g_Xh);   cudaGetSymbolAddress((void**)&pXl, g_Xl);
    cudaGetSymbolAddress((void**)&pQh, g_QKVh); cudaGetSymbolAddress((void**)&pQl, g_QKVl);
    cudaGetSymbolAddress((void**)&pVth,g_Vth);  cudaGetSymbolAddress((void**)&pVtl,g_Vtl);
    cudaGetSymbolAddress((void**)&pOhh,g_Oh);   cudaGetSymbolAddress((void**)&pOll,g_Ol);
    cudaGetSymbolAddress((void**)&pFh, g_FFh);  cudaGetSymbolAddress((void**)&pFl, g_FFl);
    cudaGetSymbolAddress((void**)&pWqh,g_Wqkvh);cudaGetSymbolAddress((void**)&pWql,g_Wqkvl);
    cudaGetSymbolAddress((void**)&pWoh,g_Woh);  cudaGetSymbolAddress((void**)&pWol,g_Wol);
    cudaGetSymbolAddress((void**)&pW1h,g_W1h);  cudaGetSymbolAddress((void**)&pW1l,g_W1l);
    cudaGetSymbolAddress((void**)&pW2h,g_W2h);  cudaGetSymbolAddress((void**)&pW2l,g_W2l);
    cudaGetSymbolAddress((void**)&pWkh,g_Wkvh); cudaGetSymbolAddress((void**)&pWkl,g_Wkvl);
    cudaGetSymbolAddress((void**)&pXoh,g_Xoh);  cudaGetSymbolAddress((void**)&pXol,g_Xol);

    cudaFuncSetAttribute(flash_attn, cudaFuncAttributeMaxDynamicSharedMemorySize, FLASH_SMEM);
    cudaFuncSetAttribute(gemm_hl<128,128,4,2>, cudaFuncAttributeMaxDynamicSharedMemorySize, gemm_smem(128,128));
    cudaFuncSetAttribute(gemm_hl<64,128,2,4>,  cudaFuncAttributeMaxDynamicSharedMemorySize, gemm_smem(64,128));

    const int Mrows = B_*N_;   // 4000

    // ---- setup (launch index 3 == first QKV GEMM => ncu target) ----
    pack_all<<<9920, 256>>>(Wq, Wk, Wv, Wo, W1, W2, Kd, Vd);                     // 0
    init_x<<<cdiv(B_*N_*D_, 256), 256>>>(wf, tf, Wws, bws, Wwe, bwe, Wt, bt);    // 1
    inorm_r<<<dim3(D_/32, B_, 8), dim3(32, 8)>>>(pX, g_wt, be_wt, pXh, pXl, N_); // 2

    for (int l = 0; l < L_; l++) {
        long long wq = (long long)l*3*D_*D_;
        // QKV: hi/lo halves + Vt scatter                                        // 3 (ncu)
        gemm_hl<128,128,4,2><<<dim3(12, 32, 1), 256, gemm_smem(128,128)>>>(
            pXh, pXl, D_, 0,0,
            pWqh + wq, pWql + wq, D_, 0,0,
            nullptr, 0, 0,0,
            pQh, pQl, 3*D_, 0,0,
            nullptr, 0, 0,0, nullptr,
            Mrows, 3*D_, D_, 1, 1.f, 0, 1);
        if (l == 0) {
            edge_stats<<<dim3(32, B_), 256>>>(ef);
            edge_params<<<1, 32>>>(W_e, b_e, g_e, be_e);
        }
        // fused attention
        flash_attn<<<dim3(8, H_*B_), 256, FLASH_SMEM>>>(
            ef, pQh, pQl, pVth, pVtl, pOhh, pOll);
        // X = X + O @ Wo
        long long wo = (long long)l*D_*D_;
        gemm_hl<64,128,2,4><<<dim3(4, cdiv(Mrows,64), 1), 256, gemm_smem(64,128)>>>(
            pOhh, pOll, D_, 0,0,
            pWoh + wo, pWol + wo, D_, 0,0,
            pX, D_, 0,0,
            nullptr, nullptr, 0, 0,0,
            pX, D_, 0,0, nullptr,
            Mrows, D_, D_, 1, 1.f, 0, 0);
        inorm_r<<<dim3(D_/32, B_, 8), dim3(32, 8)>>>(pX, g1 + l*D_, be1 + l*D_, pXh, pXl, N_);
        // FF = relu(X @ W1 + b1)
        long long w1o = (long long)l*DFF_*D_;
        gemm_hl<128,128,4,2><<<dim3(16, 32, 1), 256, gemm_smem(128,128)>>>(
            pXh, pXl, D_, 0,0,
            pW1h + w1o, pW1l + w1o, D_, 0,0,
            nullptr, 0, 0,0,
            pFh, pFl, DFF_, 0,0,
            nullptr, 0, 0,0, b1 + l*DFF_,
            Mrows, DFF_, D_, 1, 1.f, 1, 0);
        // X = X + FF @ W2 + b2
        long long w2o = (long long)l*D_*DFF_;
        gemm_hl<64,128,2,4><<<dim3(4, cdiv(Mrows,64), 1), 256, gemm_smem(64,128)>>>(
            pFh, pFl, DFF_, 0,0,
            pW2h + w2o, pW2l + w2o, DFF_, 0,0,
            pX, D_, 0,0,
            nullptr, nullptr, 0, 0,0,
            pX, D_, 0,0, b2 + l*D_,
            Mrows, D_, DFF_, 1, 1.f, 0, 0);
        inorm_r<<<dim3(D_/32, B_, 8), dim3(32, 8)>>>(pX, g2 + l*D_, be2 + l*D_, pXh, pXl, N_);
    }

    write_xout<<<cdiv(B_*N1_*D_, 256), 256>>>(fin, outX);
    gemm_hl<128,128,4,2><<<dim3(8, 32, 1), 256, gemm_smem(128,128)>>>(
        pXoh, pXol, D_, 0,0,
        pWkh, pWkl, D_, 0,0,
        pKV, 2*D_, 0,0,
        nullptr, nullptr, 0, 0,0,
        nullptr, 0, 0,0, nullptr,
        B_*N1_, 2*D_, D_, 1, 1.f, 0, 0);
    write_kv<<<cdiv(H_*B_*N1_*HD_, 256), 256>>>(outK, outV);
}